// round 13
// baseline (speedup 1.0000x reference)
#include <cuda_runtime.h>
#include <cuda_bf16.h>
#include <cstdint>

#define BB    8
#define NN    1024
#define RR    8192
#define DIN   32
#define NF    128
#define DOUT  3
#define PSTEPS 3
#define MREL  (BB * RR)   // 65536
#define MPART (BB * NN)   // 8192

// ---------------- scratch (device globals) ----------------------------------
__device__ float    g_relbase[MREL * NF]; // 32 MB fp32
__device__ uint32_t g_ptmpP[MPART * NF];
__device__ uint32_t g_peffP[MPART * NF];
__device__ float    g_peffect[MPART * NF];
__device__ float    g_pbase[MPART * NF];
__device__ float    g_eagg[MPART * NF];
__device__ float    g_pair[2 * MPART * NF]; // Sr/Ss, later P1/P2
__device__ int      g_recv[MREL];
__device__ int      g_send[MREL];
__device__ int      g_cnt[MPART];
__device__ int      g_off[MPART + 1];
__device__ int      g_pos[MPART];
__device__ int      g_list[MREL];
// packed weights: [Kpad/2][128] u32 (bf16x2 of k,k+1 per col n), hi & lo planes
#define WT_U32 79872
__device__ uint32_t g_wh[WT_U32];
__device__ uint32_t g_wl[WT_U32];
#define WO_PE0  0       // Kpad 32
#define WO_PE1  2048    // 128
#define WO_RE1  10240   // 128
#define WO_RE2  18432   // 128
#define WO_RPT  26624   // 128 (rp_w rows 0-127)
#define WO_RPM  34816   // 128 (rows 128-255)
#define WO_RPB  43008   // 128 (rows 256-383)
#define WO_PP   51200   // 256 (top: k2 0-63, bot: +8192)
#define WO_PR0  67584   // 128
#define WO_REWR 75776   // 32 (re_w0 rows 0-31)
#define WO_REWS 77824   // 32 (re_w0 rows 32-63)

// ---------------- helpers ----------------------------------------------------
__device__ __forceinline__ uint32_t packbf(float vlo, float vhi) {
    uint32_t r;
    asm("cvt.rn.bf16x2.f32 %0, %1, %2;" : "=r"(r) : "f"(vhi), "f"(vlo));
    return r;
}
__device__ __forceinline__ void mma16816(float* d, const uint32_t* a, uint32_t b0, uint32_t b1) {
    asm volatile("mma.sync.aligned.m16n8k16.row.col.f32.bf16.bf16.f32 "
                 "{%0,%1,%2,%3}, {%4,%5,%6,%7}, {%8,%9}, {%0,%1,%2,%3};"
                 : "+f"(d[0]), "+f"(d[1]), "+f"(d[2]), "+f"(d[3])
                 : "r"(a[0]), "r"(a[1]), "r"(a[2]), "r"(a[3]), "r"(b0), "r"(b1));
}

// ---------------- index extraction + inline CSR count (high-MLP) -------------
__device__ __forceinline__ void proc_quad(uint4 v, long long idx,
                                          int* __restrict__ dst,
                                          int* __restrict__ cnt, bool do_cnt)
{
    if (v.x | v.y | v.z | v.w) {
        long long e = idx * 4;
        int b = (int)(e >> 23);
        int n = (int)((e >> 13) & (NN - 1));
        int r = (int)(e & (RR - 1));
        int* o = dst + b * RR + r;
        int nz = 0;
        if (v.x) { o[0] = n; ++nz; }
        if (v.y) { o[1] = n; ++nz; }
        if (v.z) { o[2] = n; ++nz; }
        if (v.w) { o[3] = n; ++nz; }
        if (do_cnt) atomicAdd(&cnt[(b << 10) + n], nz);
    }
}

__global__ void extract_idx_kernel(const uint4* __restrict__ Rr,
                                   const uint4* __restrict__ Rs,
                                   int* __restrict__ recv, int* __restrict__ send,
                                   int* __restrict__ cnt)
{
    const long long total  = (long long)BB * NN * RR / 4;          // 16M uint4
    const long long stride = (long long)gridDim.x * blockDim.x * 4;
    const int bd = blockDim.x;
    for (long long base = (long long)blockIdx.x * bd * 4 + threadIdx.x;
         base < total; base += stride) {
        uint4 a0 = __ldcs(Rr + base);
        uint4 a1 = __ldcs(Rr + base + bd);
        uint4 a2 = __ldcs(Rr + base + 2 * bd);
        uint4 a3 = __ldcs(Rr + base + 3 * bd);
        uint4 b0 = __ldcs(Rs + base);
        uint4 b1 = __ldcs(Rs + base + bd);
        uint4 b2 = __ldcs(Rs + base + 2 * bd);
        uint4 b3 = __ldcs(Rs + base + 3 * bd);
        proc_quad(a0, base,          recv, cnt, true);
        proc_quad(a1, base + bd,     recv, cnt, true);
        proc_quad(a2, base + 2 * bd, recv, cnt, true);
        proc_quad(a3, base + 3 * bd, recv, cnt, true);
        proc_quad(b0, base,          send, nullptr, false);
        proc_quad(b1, base + bd,     send, nullptr, false);
        proc_quad(b2, base + 2 * bd, send, nullptr, false);
        proc_quad(b3, base + 3 * bd, send, nullptr, false);
    }
}

// ---------------- CSR scan + fill --------------------------------------------
__global__ void csr_scan_kernel(const int* __restrict__ cnt,
                                int* __restrict__ off, int* __restrict__ pos) {
    __shared__ int part[1024];
    const int tid = threadIdx.x;
    int local[8];
    int s = 0;
#pragma unroll
    for (int j = 0; j < 8; ++j) { local[j] = s; s += cnt[tid * 8 + j]; }
    part[tid] = s;
    __syncthreads();
    for (int d = 1; d < 1024; d <<= 1) {
        int v = part[tid];
        if (tid >= d) v += part[tid - d];
        __syncthreads();
        part[tid] = v;
        __syncthreads();
    }
    int base = (tid == 0) ? 0 : part[tid - 1];
#pragma unroll
    for (int j = 0; j < 8; ++j) {
        int o = base + local[j];
        off[tid * 8 + j] = o;
        pos[tid * 8 + j] = o;
    }
    if (tid == 1023) off[MPART] = part[1023];
}
__global__ void csr_fill_kernel(const int* __restrict__ recv,
                                int* __restrict__ pos, int* __restrict__ list) {
    int r = blockIdx.x * blockDim.x + threadIdx.x;
    int p = ((r >> 13) << 10) + recv[r];
    int idx = atomicAdd(&pos[p], 1);
    list[idx] = r;
}

// ---------------- weights: transpose + split + pack (+ cnt zero) ------------
__global__ void split_all_kernel(const float* __restrict__ pe_w0, const float* __restrict__ pe_w1,
                                 const float* __restrict__ re_w0, const float* __restrict__ re_w1,
                                 const float* __restrict__ re_w2, const float* __restrict__ rp_w,
                                 const float* __restrict__ pp_w, const float* __restrict__ pr_w0,
                                 uint32_t* __restrict__ hi, uint32_t* __restrict__ lo,
                                 int* __restrict__ cnt)
{
    int idx = blockIdx.x * blockDim.x + threadIdx.x;
    if (idx >= WT_U32) {
        int z = idx - WT_U32;
        if (z < MPART) cnt[z] = 0;
        return;
    }
    const float* w; int K, local;
    if      (idx < 2048)  { w = pe_w0;              K = 32;  local = idx; }
    else if (idx < 10240) { w = pe_w1;              K = 128; local = idx - 2048; }
    else if (idx < 18432) { w = re_w1;              K = 128; local = idx - 10240; }
    else if (idx < 26624) { w = re_w2;              K = 128; local = idx - 18432; }
    else if (idx < 34816) { w = rp_w;               K = 128; local = idx - 26624; }
    else if (idx < 43008) { w = rp_w + 128 * 128;   K = 128; local = idx - 34816; }
    else if (idx < 51200) { w = rp_w + 256 * 128;   K = 128; local = idx - 43008; }
    else if (idx < 67584) { w = pp_w;               K = 256; local = idx - 51200; }
    else if (idx < 75776) { w = pr_w0;              K = 128; local = idx - 67584; }
    else if (idx < 77824) { w = re_w0;              K = 32;  local = idx - 75776; }
    else                  { w = re_w0 + 32 * 128;   K = 32;  local = idx - 77824; }
    int k2 = local >> 7, n = local & 127;
    int k0 = 2 * k2;
    float v0 = (k0 < K)     ? w[(size_t)k0 * 128 + n]       : 0.f;
    float v1 = (k0 + 1 < K) ? w[(size_t)(k0 + 1) * 128 + n] : 0.f;
    uint32_t h = packbf(v0, v1);
    float h0 = __uint_as_float(h << 16);
    float h1 = __uint_as_float(h & 0xFFFF0000u);
    hi[idx] = h;
    lo[idx] = packbf(v0 - h0, v1 - h1);
}

// -------- CSR gather-reduce aggregation (atomic-free) -----------------------
template<bool FIRST>
__global__ __launch_bounds__(256, 8)
void agg_kernel(const float* __restrict__ relbase,
                const float* __restrict__ P1, const float* __restrict__ P2,
                const int* __restrict__ send,
                const int* __restrict__ off, const int* __restrict__ list,
                float* __restrict__ eagg)
{
    const int p = blockIdx.x * 2 + (threadIdx.x >> 7);
    const int c = threadIdx.x & 127;
    const int beg = off[p], end = off[p + 1];
    float p1c = FIRST ? 0.f : P1[(size_t)p * NF + c];
    float acc = 0.f;
    for (int i = beg; i < end; ++i) {
        int r = list[i];
        float v = relbase[(size_t)r * NF + c] + p1c;
        if (!FIRST) {
            int gs = ((r >> 13) << 10) + send[r];
            v += P2[(size_t)gs * NF + c];
        }
        acc += fmaxf(v, 0.f);
    }
    eagg[(size_t)p * NF + c] = acc;
}

// ================== chained multi-layer GEMM machinery (interleaved planes) ==
// A: 128 rows x 68 uint2 (pair = (hi,lo) bf16x2), row stride 544B.
// W: per stage 16 k2-rows x 132 uint2, row stride 1056B; double-buffered.
#define CH_WA   0
#define CH_B0   512
#define CH_BA   1024
#define CH_BB   1536
#define CH_BC   2048
#define CH_A    2560                         // 128*544 = 69632 bytes
#define CH_W(s) (CH_A + 69632 + (s) * 16896) // 16*1056 per stage
#define CH_TOTAL (CH_A + 69632 + 2 * 16896)  // 105984

__device__ __forceinline__ void ch_fill_w(char* smem, int s, int kt,
    const uint32_t* __restrict__ Whp, const uint32_t* __restrict__ Wlp, int tid)
{
    const int k2 = tid >> 4;
    const int nn = (tid & 15) * 8;
    const size_t gi = (size_t)(kt * 16 + k2) * 128 + nn;
    uint4 h0 = *(const uint4*)(Whp + gi);
    uint4 h1 = *(const uint4*)(Whp + gi + 4);
    uint4 l0 = *(const uint4*)(Wlp + gi);
    uint4 l1 = *(const uint4*)(Wlp + gi + 4);
    uint4* wp = (uint4*)((uint2*)(smem + CH_W(s)) + k2 * 132 + nn);
    wp[0] = make_uint4(h0.x, l0.x, h0.y, l0.y);
    wp[1] = make_uint4(h0.z, l0.z, h0.w, l0.w);
    wp[2] = make_uint4(h1.x, l1.x, h1.y, l1.y);
    wp[3] = make_uint4(h1.z, l1.z, h1.w, l1.w);
}

__device__ __forceinline__ void ch_compute(char* smem, int kt, int s,
    int wm, int wn, int lane, float (&acc)[4][4][4])
{
    const uint2* A2 = (const uint2*)(smem + CH_A);
    const uint2* W2 = (const uint2*)(smem + CH_W(s));
#pragma unroll
    for (int step = 0; step < 2; ++step) {
        uint32_t ah[4][4], al[4][4];
#pragma unroll
        for (int f = 0; f < 4; ++f) {
            int r = wm * 64 + f * 16 + (lane >> 2);
            int i0 = r * 68 + kt * 16 + (lane & 3) + step * 8;
            uint2 p0 = A2[i0];
            uint2 p1 = A2[i0 + 544];   // row +8 = +8*68 pairs
            uint2 p2 = A2[i0 + 4];
            uint2 p3 = A2[i0 + 548];
            ah[f][0] = p0.x; ah[f][1] = p1.x; ah[f][2] = p2.x; ah[f][3] = p3.x;
            al[f][0] = p0.y; al[f][1] = p1.y; al[f][2] = p2.y; al[f][3] = p3.y;
        }
#pragma unroll
        for (int nf = 0; nf < 4; ++nf) {
            int bi = (step * 8 + (lane & 3)) * 132 + wn * 32 + nf * 8 + (lane >> 2);
            uint2 q0 = W2[bi];
            uint2 q1 = W2[bi + 528];   // row +4 = +4*132 pairs
#pragma unroll
            for (int f = 0; f < 4; ++f) {
                mma16816(acc[f][nf], ah[f], q0.x, q1.x);
                mma16816(acc[f][nf], ah[f], q0.y, q1.y);
                mma16816(acc[f][nf], al[f], q0.x, q1.x);
            }
        }
    }
}

__device__ __forceinline__ void ch_gemm_layer(char* smem,
    const uint32_t* __restrict__ Whp, const uint32_t* __restrict__ Wlp, int nchunk,
    int wm, int wn, int lane, int tid, float (&acc)[4][4][4])
{
#pragma unroll
    for (int f = 0; f < 4; ++f)
#pragma unroll
        for (int nf = 0; nf < 4; ++nf)
#pragma unroll
            for (int j = 0; j < 4; ++j) acc[f][nf][j] = 0.f;
    ch_fill_w(smem, 0, 0, Whp, Wlp, tid);
    __syncthreads();
    for (int kt = 0; kt < nchunk; ++kt) {
        int s = kt & 1;
        if (kt + 1 < nchunk) ch_fill_w(smem, s ^ 1, kt + 1, Whp, Wlp, tid);
        ch_compute(smem, kt, s, wm, wn, lane, acc);
        __syncthreads();
    }
}

__device__ __forceinline__ void ch_epi_planes(char* smem, const float* bias_s,
    int wm, int wn, int lane, float (&acc)[4][4][4])
{
    uint2* A2 = (uint2*)(smem + CH_A);
#pragma unroll
    for (int f = 0; f < 4; ++f) {
        int r0 = wm * 64 + f * 16 + (lane >> 2);
        int r1 = r0 + 8;
#pragma unroll
        for (int nf = 0; nf < 4; ++nf) {
            int c = wn * 32 + nf * 8 + (lane & 3) * 2;
            int c2 = c >> 1;
            float a0 = fmaxf(acc[f][nf][0] + bias_s[c], 0.f);
            float a1 = fmaxf(acc[f][nf][1] + bias_s[c + 1], 0.f);
            float a2 = fmaxf(acc[f][nf][2] + bias_s[c], 0.f);
            float a3 = fmaxf(acc[f][nf][3] + bias_s[c + 1], 0.f);
            uint32_t h0 = packbf(a0, a1), h1 = packbf(a2, a3);
            uint32_t l0 = packbf(a0 - __uint_as_float(h0 << 16), a1 - __uint_as_float(h0 & 0xFFFF0000u));
            uint32_t l1 = packbf(a2 - __uint_as_float(h1 << 16), a3 - __uint_as_float(h1 & 0xFFFF0000u));
            A2[r0 * 68 + c2] = make_uint2(h0, l0);
            A2[r1 * 68 + c2] = make_uint2(h1, l1);
        }
    }
}

__device__ __forceinline__ void ch_write_f32(float* dst, int row0, const float* bias_s,
    int wm, int wn, int lane, float (&acc)[4][4][4])
{
#pragma unroll
    for (int f = 0; f < 4; ++f) {
        int r0 = wm * 64 + f * 16 + (lane >> 2), r1 = r0 + 8;
#pragma unroll
        for (int nf = 0; nf < 4; ++nf) {
            int c = wn * 32 + nf * 8 + (lane & 3) * 2;
            float b0 = bias_s ? bias_s[c] : 0.f;
            float b1 = bias_s ? bias_s[c + 1] : 0.f;
            *(float2*)(dst + (size_t)(row0 + r0) * 128 + c) =
                make_float2(acc[f][nf][0] + b0, acc[f][nf][1] + b1);
            *(float2*)(dst + (size_t)(row0 + r1) * 128 + c) =
                make_float2(acc[f][nf][2] + b0, acc[f][nf][3] + b1);
        }
    }
}

// ---- fused relation chain: gather-combine -> re1 -> re2 -> relbase ----------
__global__ __launch_bounds__(256, 2)
void relchain_kernel(const float* __restrict__ Sr, const float* __restrict__ Ss,
                     const float* __restrict__ Ra,
                     const float* __restrict__ wa, const float* __restrict__ b0,
                     const float* __restrict__ b1, const float* __restrict__ b2,
                     const float* __restrict__ brp,
                     const int* __restrict__ recv, const int* __restrict__ send,
                     const uint32_t* __restrict__ wh, const uint32_t* __restrict__ wl,
                     float* __restrict__ relbase)
{
    extern __shared__ char smem[];
    const int tid = threadIdx.x, lane = tid & 31, wid = tid >> 5;
    const int wm = wid & 1, wn = wid >> 1;
    const int row0 = blockIdx.x * 128;
    float* wa_s = (float*)(smem + CH_WA);
    float* b0_s = (float*)(smem + CH_B0);
    float* bA_s = (float*)(smem + CH_BA);
    float* bB_s = (float*)(smem + CH_BB);
    float* bC_s = (float*)(smem + CH_BC);
    if (tid < 128) {
        wa_s[tid] = wa[tid]; b0_s[tid] = b0[tid];
        bA_s[tid] = b1[tid]; bB_s[tid] = b2[tid]; bC_s[tid] = brp[tid];
    }
    const int row = tid >> 1, half = tid & 1, grow = row0 + row, bb = grow >> 13;
    const float ra = Ra[grow];
    const int rv = (bb << 10) + recv[grow];
    const int sd = (bb << 10) + send[grow];
    const float4* pr = (const float4*)(Sr + (size_t)rv * 128 + half * 64);
    const float4* ps = (const float4*)(Ss + (size_t)sd * 128 + half * 64);
    __syncthreads();
    {
        uint4* AP = (uint4*)((uint2*)(smem + CH_A) + row * 68 + half * 32);
#pragma unroll
        for (int j = 0; j < 16; ++j) {
            float4 u = pr[j], v = ps[j];
            int c = half * 64 + j * 4;
            float a0 = fmaxf(u.x + v.x + ra * wa_s[c]     + b0_s[c],     0.f);
            float a1 = fmaxf(u.y + v.y + ra * wa_s[c + 1] + b0_s[c + 1], 0.f);
            float a2 = fmaxf(u.z + v.z + ra * wa_s[c + 2] + b0_s[c + 2], 0.f);
            float a3 = fmaxf(u.w + v.w + ra * wa_s[c + 3] + b0_s[c + 3], 0.f);
            uint32_t h0 = packbf(a0, a1), h1 = packbf(a2, a3);
            uint32_t l0 = packbf(a0 - __uint_as_float(h0 << 16), a1 - __uint_as_float(h0 & 0xFFFF0000u));
            uint32_t l1 = packbf(a2 - __uint_as_float(h1 << 16), a3 - __uint_as_float(h1 & 0xFFFF0000u));
            AP[j] = make_uint4(h0, l0, h1, l1);
        }
    }
    float acc[4][4][4];
    ch_gemm_layer(smem, wh + WO_RE1, wl + WO_RE1, 4, wm, wn, lane, tid, acc);
    ch_epi_planes(smem, bA_s, wm, wn, lane, acc);
    ch_gemm_layer(smem, wh + WO_RE2, wl + WO_RE2, 4, wm, wn, lane, tid, acc);
    ch_epi_planes(smem, bB_s, wm, wn, lane, acc);
    ch_gemm_layer(smem, wh + WO_RPT, wl + WO_RPT, 4, wm, wn, lane, tid, acc);
    ch_write_f32(relbase, row0, bC_s, wm, wn, lane, acc);
}

// ---- fused particle prep: Sr, Ss, pe0 -> pe1 -> pbase -----------------------
__global__ __launch_bounds__(256, 2)
void partall_kernel(const float* __restrict__ state,
                    const float* __restrict__ pe_b0, const float* __restrict__ pe_b1,
                    const float* __restrict__ pp_b,
                    const uint32_t* __restrict__ wh, const uint32_t* __restrict__ wl,
                    float* __restrict__ Sr, float* __restrict__ Ss,
                    float* __restrict__ pbase)
{
    extern __shared__ char smem[];
    const int tid = threadIdx.x, lane = tid & 31, wid = tid >> 5;
    const int wm = wid & 1, wn = wid >> 1;
    const int row0 = blockIdx.x * 128;
    float* bA_s = (float*)(smem + CH_BA);
    float* bB_s = (float*)(smem + CH_BB);
    float* bC_s = (float*)(smem + CH_BC);
    if (tid < 128) { bA_s[tid] = pe_b0[tid]; bB_s[tid] = pe_b1[tid]; bC_s[tid] = pp_b[tid]; }
    {
        const int row = tid >> 1, half = tid & 1, grow = row0 + row;
        const float4* q = (const float4*)(state + (size_t)grow * 32 + half * 16);
        float x[16];
#pragma unroll
        for (int j = 0; j < 4; ++j) {
            float4 u = q[j];
            x[4 * j] = u.x; x[4 * j + 1] = u.y; x[4 * j + 2] = u.z; x[4 * j + 3] = u.w;
        }
        uint4* AP = (uint4*)((uint2*)(smem + CH_A) + row * 68 + half * 8);
#pragma unroll
        for (int j = 0; j < 4; ++j) {
            uint32_t h0 = packbf(x[4 * j],     x[4 * j + 1]);
            uint32_t h1 = packbf(x[4 * j + 2], x[4 * j + 3]);
            uint32_t l0 = packbf(x[4 * j]     - __uint_as_float(h0 << 16),
                                 x[4 * j + 1] - __uint_as_float(h0 & 0xFFFF0000u));
            uint32_t l1 = packbf(x[4 * j + 2] - __uint_as_float(h1 << 16),
                                 x[4 * j + 3] - __uint_as_float(h1 & 0xFFFF0000u));
            AP[j] = make_uint4(h0, l0, h1, l1);
        }
    }
    float acc[4][4][4];
    ch_gemm_layer(smem, wh + WO_REWR, wl + WO_REWR, 1, wm, wn, lane, tid, acc);
    ch_write_f32(Sr, row0, nullptr, wm, wn, lane, acc);
    ch_gemm_layer(smem, wh + WO_REWS, wl + WO_REWS, 1, wm, wn, lane, tid, acc);
    ch_write_f32(Ss, row0, nullptr, wm, wn, lane, acc);
    ch_gemm_layer(smem, wh + WO_PE0, wl + WO_PE0, 1, wm, wn, lane, tid, acc);
    ch_epi_planes(smem, bA_s, wm, wn, lane, acc);
    ch_gemm_layer(smem, wh + WO_PE1, wl + WO_PE1, 4, wm, wn, lane, tid, acc);
    ch_epi_planes(smem, bB_s, wm, wn, lane, acc);
    ch_gemm_layer(smem, wh + WO_PP, wl + WO_PP, 4, wm, wn, lane, tid, acc);
    ch_write_f32(pbase, row0, bC_s, wm, wn, lane, acc);
}

// ---------------- generic fused mma.sync GEMM (R12-validated, untouched) -----
enum { A_F32 = 0, A_BF = 1 };
enum { E_RELU_F32 = 0, E_BASE = 2, E_RESID = 3, E_RESID0 = 4 };

#define SM_BIAS 0
#define SM_A    1536
#define AHI_OFF(s) (SM_A + (s) * 10240)
#define ALO_OFF(s) (SM_A + 20480 + (s) * 10240)
#define SM_W    (SM_A + 40960)
#define WHI_OFF(s) (SM_W + (s) * 8704)
#define WLO_OFF(s) (SM_W + 17408 + (s) * 8704)
#define SMEM_TOTAL_B (SM_W + 34816)   // 77312 bytes

template<int MODE_A>
__device__ __forceinline__ void fill_tile(
    char* smem, int s, int kt,
    const void* __restrict__ Av,
    const uint32_t* __restrict__ Whp, const uint32_t* __restrict__ Wlp,
    int row0, int K, int tid)
{
    const int row   = tid >> 1;
    const int half  = tid & 1;
    const int kbase = kt * 32 + half * 16;
    const int grow  = row0 + row;

    uint4 hA0, hA1, lA0, lA1;

    if (MODE_A == A_BF) {
        const uint32_t* Xp = (const uint32_t*)Av + (size_t)grow * 128;
        int k2 = kbase >> 1;
        hA0 = *(const uint4*)(Xp + k2);
        hA1 = *(const uint4*)(Xp + k2 + 4);
        lA0 = *(const uint4*)(Xp + 64 + k2);
        lA1 = *(const uint4*)(Xp + 64 + k2 + 4);
    } else {
        float x[16];
        if (kbase < K) {
            const float4* q = (const float4*)((const float*)Av + (size_t)grow * K + kbase);
#pragma unroll
            for (int j = 0; j < 4; ++j) {
                float4 u = q[j];
                x[4 * j] = u.x; x[4 * j + 1] = u.y; x[4 * j + 2] = u.z; x[4 * j + 3] = u.w;
            }
        } else {
#pragma unroll
            for (int j = 0; j < 16; ++j) x[j] = 0.f;
        }
        uint32_t hi[8], lo[8];
#pragma unroll
        for (int j = 0; j < 8; ++j) {
            uint32_t h = packbf(x[2 * j], x[2 * j + 1]);
            hi[j] = h;
            float h0 = __uint_as_float(h << 16);
            float h1 = __uint_as_float(h & 0xFFFF0000u);
            lo[j] = packbf(x[2 * j] - h0, x[2 * j + 1] - h1);
        }
        hA0 = make_uint4(hi[0], hi[1], hi[2], hi[3]);
        hA1 = make_uint4(hi[4], hi[5], hi[6], hi[7]);
        lA0 = make_uint4(lo[0], lo[1], lo[2], lo[3]);
        lA1 = make_uint4(lo[4], lo[5], lo[6], lo[7]);
    }
    {
        uint4* dh = (uint4*)(smem + AHI_OFF(s) + row * 80 + half * 32);
        dh[0] = hA0; dh[1] = hA1;
        uint4* dl = (uint4*)(smem + ALO_OFF(s) + row * 80 + half * 32);
        dl[0] = lA0; dl[1] = lA1;
    }
    {
        const int k2 = tid >> 4;
        const int nn = (tid & 15) * 8;
        const size_t gi = (size_t)(kt * 16 + k2) * 128 + nn;
        uint4 h0 = *(const uint4*)(Whp + gi);
        uint4 h1 = *(const uint4*)(Whp + gi + 4);
        uint4 l0 = *(const uint4*)(Wlp + gi);
        uint4 l1 = *(const uint4*)(Wlp + gi + 4);
        char* wb = smem + WHI_OFF(s) + k2 * 544 + nn * 4;
        ((uint4*)wb)[0] = h0; ((uint4*)wb)[1] = h1;
        char* lb = smem + WLO_OFF(s) + k2 * 544 + nn * 4;
        ((uint4*)lb)[0] = l0; ((uint4*)lb)[1] = l1;
    }
}

template<int MODE_A, int MODE_EPI>
__global__ __launch_bounds__(256, 2)
void mma_gemm(const void* __restrict__ Av,
              const uint32_t* __restrict__ Whp, const uint32_t* __restrict__ Wlp,
              const float* __restrict__ bias, void* __restrict__ Cv,
              const float* __restrict__ base,
              uint32_t* __restrict__ C2,
              int K, int nchunk, int wstride, long long cstrideB)
{
    extern __shared__ char smem[];
    const int tid  = threadIdx.x;
    const int wid  = tid >> 5;
    const int lane = tid & 31;
    const int row0 = blockIdx.x * 128;
    const int wm = wid & 1;
    const int wn = wid >> 1;

    Whp += (size_t)blockIdx.y * wstride;
    Wlp += (size_t)blockIdx.y * wstride;
    char* Cb = (char*)Cv + (size_t)blockIdx.y * cstrideB;

    float* bias_s = (float*)(smem + SM_BIAS);
    if (tid < 128) bias_s[tid] = bias ? bias[tid] : 0.f;
    __syncthreads();

    float acc[4][4][4];
#pragma unroll
    for (int f = 0; f < 4; ++f)
#pragma unroll
        for (int nf = 0; nf < 4; ++nf)
#pragma unroll
            for (int j = 0; j < 4; ++j) acc[f][nf][j] = 0.f;

    fill_tile<MODE_A>(smem, 0, 0, Av, Whp, Wlp, row0, K, tid);
    __syncthreads();

    for (int kt = 0; kt < nchunk; ++kt) {
        const int s = kt & 1;
        if (kt + 1 < nchunk)
            fill_tile<MODE_A>(smem, s ^ 1, kt + 1, Av, Whp, Wlp, row0, K, tid);

        const uint32_t* AH = (const uint32_t*)(smem + AHI_OFF(s));
        const uint32_t* AL = (const uint32_t*)(smem + ALO_OFF(s));
        const uint32_t* WH = (const uint32_t*)(smem + WHI_OFF(s));
        const uint32_t* WL = (const uint32_t*)(smem + WLO_OFF(s));

#pragma unroll
        for (int step = 0; step < 2; ++step) {
            uint32_t ah[4][4], al[4][4];
#pragma unroll
            for (int f = 0; f < 4; ++f) {
                int r = wm * 64 + f * 16 + (lane >> 2);
                int i0 = r * 20 + (lane & 3) + step * 8;
                ah[f][0] = AH[i0];       ah[f][1] = AH[i0 + 160];
                ah[f][2] = AH[i0 + 4];   ah[f][3] = AH[i0 + 164];
                al[f][0] = AL[i0];       al[f][1] = AL[i0 + 160];
                al[f][2] = AL[i0 + 4];   al[f][3] = AL[i0 + 164];
            }
#pragma unroll
            for (int nf = 0; nf < 4; ++nf) {
                int bi = (step * 8 + (lane & 3)) * 136 + wn * 32 + nf * 8 + (lane >> 2);
                uint32_t bh0 = WH[bi], bh1 = WH[bi + 544];
                uint32_t bl0 = WL[bi], bl1 = WL[bi + 544];
#pragma unroll
                for (int f = 0; f < 4; ++f) {
                    mma16816(acc[f][nf], ah[f], bh0, bh1);
                    mma16816(acc[f][nf], ah[f], bl0, bl1);
                    mma16816(acc[f][nf], al[f], bh0, bh1);
                }
            }
        }
        __syncthreads();
    }

    float bc0[4], bc1[4];
#pragma unroll
    for (int nf = 0; nf < 4; ++nf) {
        int c = wn * 32 + nf * 8 + (lane & 3) * 2;
        bc0[nf] = bias_s[c];
        bc1[nf] = bias_s[c + 1];
    }
#pragma unroll
    for (int f = 0; f < 4; ++f) {
        int rl0 = wm * 64 + f * 16 + (lane >> 2);
        int rl1 = rl0 + 8;
        int r0 = row0 + rl0;
        int r1 = row0 + rl1;
#pragma unroll
        for (int nf = 0; nf < 4; ++nf) {
            int c = wn * 32 + nf * 8 + (lane & 3) * 2;
            float v0 = acc[f][nf][0] + bc0[nf];
            float v1 = acc[f][nf][1] + bc1[nf];
            float v2 = acc[f][nf][2] + bc0[nf];
            float v3 = acc[f][nf][3] + bc1[nf];
            if (MODE_EPI == E_RELU_F32) {
                float* CF = (float*)Cb;
                *(float2*)(&CF[(size_t)r0 * NF + c]) = make_float2(fmaxf(v0, 0.f), fmaxf(v1, 0.f));
                *(float2*)(&CF[(size_t)r1 * NF + c]) = make_float2(fmaxf(v2, 0.f), fmaxf(v3, 0.f));
            } else if (MODE_EPI == E_BASE) {
                float* CF = (float*)Cb;
                *(float2*)(&CF[(size_t)r0 * NF + c]) = make_float2(v0, v1);
                *(float2*)(&CF[(size_t)r1 * NF + c]) = make_float2(v2, v3);
            } else { // E_RESID / E_RESID0
                float* CF = (float*)Cb;
                float2 b0 = *(const float2*)(&base[(size_t)r0 * NF + c]);
                float2 b1 = *(const float2*)(&base[(size_t)r1 * NF + c]);
                float2 p0 = make_float2(0.f, 0.f), p1 = make_float2(0.f, 0.f);
                if (MODE_EPI == E_RESID) {
                    p0 = *(const float2*)(&CF[(size_t)r0 * NF + c]);
                    p1 = *(const float2*)(&CF[(size_t)r1 * NF + c]);
                }
                float a0 = fmaxf(v0 + b0.x + p0.x, 0.f);
                float a1 = fmaxf(v1 + b0.y + p0.y, 0.f);
                float a2 = fmaxf(v2 + b1.x + p1.x, 0.f);
                float a3 = fmaxf(v3 + b1.y + p1.y, 0.f);
                *(float2*)(&CF[(size_t)r0 * NF + c]) = make_float2(a0, a1);
                *(float2*)(&CF[(size_t)r1 * NF + c]) = make_float2(a2, a3);
                uint32_t h0 = packbf(a0, a1);
                uint32_t h1 = packbf(a2, a3);
                C2[(size_t)r0 * 128 + (c >> 1)] = h0;
                C2[(size_t)r1 * 128 + (c >> 1)] = h1;
                C2[(size_t)r0 * 128 + 64 + (c >> 1)] =
                    packbf(a0 - __uint_as_float(h0 << 16), a1 - __uint_as_float(h0 & 0xFFFF0000u));
                C2[(size_t)r1 * 128 + 64 + (c >> 1)] =
                    packbf(a2 - __uint_as_float(h1 << 16), a3 - __uint_as_float(h1 & 0xFFFF0000u));
            }
        }
    }
}

// ---------------- final predictor layer --------------------------------------
__global__ void pred_final_kernel(const float* __restrict__ X, const float* __restrict__ W,
                                  const float* __restrict__ bias, float* __restrict__ out)
{
    __shared__ float Ws[NF * DOUT];
    __shared__ float bs[DOUT];
    int tid = threadIdx.x;
    for (int i = tid; i < NF * DOUT; i += blockDim.x) Ws[i] = W[i];
    if (tid < DOUT) bs[tid] = bias[tid];
    __syncthreads();
    int p = blockIdx.x * blockDim.x + tid;
    float a0 = bs[0], a1 = bs[1], a2 = bs[2];
    const float4* xp = (const float4*)(X + (size_t)p * NF);
#pragma unroll
    for (int k4 = 0; k4 < NF / 4; ++k4) {
        float4 x = xp[k4];
        int k = k4 * 4;
        a0 += x.x * Ws[k * 3 + 0] + x.y * Ws[(k + 1) * 3 + 0] +
              x.z * Ws[(k + 2) * 3 + 0] + x.w * Ws[(k + 3) * 3 + 0];
        a1 += x.x * Ws[k * 3 + 1] + x.y * Ws[(k + 1) * 3 + 1] +
              x.z * Ws[(k + 2) * 3 + 1] + x.w * Ws[(k + 3) * 3 + 1];
        a2 += x.x * Ws[k * 3 + 2] + x.y * Ws[(k + 1) * 3 + 2] +
              x.z * Ws[(k + 2) * 3 + 2] + x.w * Ws[(k + 3) * 3 + 2];
    }
    out[p * 3 + 0] = a0;
    out[p * 3 + 1] = a1;
    out[p * 3 + 2] = a2;
}

// ---------------- host orchestration ----------------------------------------
extern "C" void kernel_launch(void* const* d_in, const int* in_sizes, int n_in,
                              void* d_out, int out_size)
{
    const float* state = (const float*)d_in[0];
    const float* Rr    = (const float*)d_in[1];
    const float* Rs    = (const float*)d_in[2];
    const float* Ra    = (const float*)d_in[3];
    const float* pe_w0 = (const float*)d_in[5],  *pe_b0 = (const float*)d_in[6];
    const float* pe_w1 = (const float*)d_in[7],  *pe_b1 = (const float*)d_in[8];
    const float* re_w0 = (const float*)d_in[9],  *re_b0 = (const float*)d_in[10];
    const float* re_w1 = (const float*)d_in[11], *re_b1 = (const float*)d_in[12];
    const float* re_w2 = (const float*)d_in[13], *re_b2 = (const float*)d_in[14];
    const float* rp_w  = (const float*)d_in[15], *rp_b  = (const float*)d_in[16];
    const float* pp_w  = (const float*)d_in[17], *pp_b  = (const float*)d_in[18];
    const float* pr_w0 = (const float*)d_in[19], *pr_b0 = (const float*)d_in[20];
    const float* pr_w1 = (const float*)d_in[21], *pr_b1 = (const float*)d_in[22];
    float* out = (float*)d_out;

    uint32_t *ptmpP, *peffP, *wh, *wl;
    float *relbase, *peffect, *pbase, *eagg, *pair;
    int *recv, *send, *cnt, *off, *pos, *list;
    cudaGetSymbolAddress((void**)&relbase, g_relbase);
    cudaGetSymbolAddress((void**)&ptmpP,   g_ptmpP);
    cudaGetSymbolAddress((void**)&peffP,   g_peffP);
    cudaGetSymbolAddress((void**)&peffect, g_peffect);
    cudaGetSymbolAddress((void**)&pbase,   g_pbase);
    cudaGetSymbolAddress((void**)&eagg,    g_eagg);
    cudaGetSymbolAddress((void**)&pair,    g_pair);
    cudaGetSymbolAddress((void**)&recv,    g_recv);
    cudaGetSymbolAddress((void**)&send,    g_send);
    cudaGetSymbolAddress((void**)&cnt,     g_cnt);
    cudaGetSymbolAddress((void**)&off,     g_off);
    cudaGetSymbolAddress((void**)&pos,     g_pos);
    cudaGetSymbolAddress((void**)&list,    g_list);
    cudaGetSymbolAddress((void**)&wh,      g_wh);
    cudaGetSymbolAddress((void**)&wl,      g_wl);

    cudaFuncSetAttribute(mma_gemm<A_BF,  E_BASE>,    cudaFuncAttributeMaxDynamicSharedMemorySize, SMEM_TOTAL_B);
    cudaFuncSetAttribute(mma_gemm<A_F32, E_RESID>,   cudaFuncAttributeMaxDynamicSharedMemorySize, SMEM_TOTAL_B);
    cudaFuncSetAttribute(mma_gemm<A_F32, E_RESID0>,  cudaFuncAttributeMaxDynamicSharedMemorySize, SMEM_TOTAL_B);
    cudaFuncSetAttribute(mma_gemm<A_BF,  E_RELU_F32>,cudaFuncAttributeMaxDynamicSharedMemorySize, SMEM_TOTAL_B);
    cudaFuncSetAttribute(relchain_kernel,  cudaFuncAttributeMaxDynamicSharedMemorySize, CH_TOTAL);
    cudaFuncSetAttribute(partall_kernel,   cudaFuncAttributeMaxDynamicSharedMemorySize, CH_TOTAL);

    float* P1 = pair;
    float* P2 = pair + (size_t)MPART * NF;
    const int WO_PPBOT = WO_PP + 8192;

    // 1) weights + cnt zero
    split_all_kernel<<<(WT_U32 + MPART + 255) / 256, 256>>>(
        pe_w0, pe_w1, re_w0, re_w1, re_w2, rp_w, pp_w, pr_w0, wh, wl, cnt);
    // 2) one-hot -> indices + CSR count (high-MLP scan)
    extract_idx_kernel<<<2048, 256>>>((const uint4*)Rr, (const uint4*)Rs, recv, send, cnt);
    // 3) CSR scan + fill
    csr_scan_kernel<<<1, 1024>>>(cnt, off, pos);
    csr_fill_kernel<<<MREL / 256, 256>>>(recv, pos, list);
    // 4) particle prep: Sr, Ss, pencode chain -> pbase
    partall_kernel<<<MPART / 128, 256, CH_TOTAL>>>(state, pe_b0, pe_b1, pp_b, wh, wl,
                                                   P1, P2, pbase);
    // 5) relation chain -> relbase
    relchain_kernel<<<MREL / 128, 256, CH_TOTAL>>>(
        P1, P2, Ra, re_w0 + 64 * 128, re_b0, re_b1, re_b2, rp_b, recv, send, wh, wl, relbase);
    // 6) propagation (first step uses E_RESID0 — no stale peffect read)
    agg_kernel<true><<<MPART / 2, 256>>>(relbase, nullptr, nullptr, send, off, list, eagg);
    mma_gemm<A_F32, E_RESID0><<<MPART / 128, 256, SMEM_TOTAL_B>>>(
        eagg, wh + WO_PPBOT, wl + WO_PPBOT, nullptr, peffect, pbase, peffP, 128, 4, 0, 0);
    for (int s = 1; s < PSTEPS; ++s) {
        dim3 g(MPART / 128, 2);
        mma_gemm<A_BF, E_BASE><<<g, 256, SMEM_TOTAL_B>>>(
            peffP, wh + WO_RPM, wl + WO_RPM, nullptr, pair, nullptr, nullptr,
            128, 4, 8192, (long long)MPART * NF * 4);
        agg_kernel<false><<<MPART / 2, 256>>>(relbase, P1, P2, send, off, list, eagg);
        mma_gemm<A_F32, E_RESID><<<MPART / 128, 256, SMEM_TOTAL_B>>>(
            eagg, wh + WO_PPBOT, wl + WO_PPBOT, nullptr, peffect, pbase, peffP, 128, 4, 0, 0);
    }
    // 7) predictor
    mma_gemm<A_BF, E_RELU_F32><<<MPART / 128, 256, SMEM_TOTAL_B>>>(
        peffP, wh + WO_PR0, wl + WO_PR0, pr_b0, ptmpP, nullptr, nullptr, 128, 4, 0, 0);
    pred_final_kernel<<<MPART / 256, 256>>>((const float*)ptmpP, pr_w1, pr_b1, out);
}

// round 14
// speedup vs baseline: 1.0706x; 1.0706x over previous
#include <cuda_runtime.h>
#include <cuda_bf16.h>
#include <cstdint>

#define BB    8
#define NN    1024
#define RR    8192
#define DIN   32
#define NF    128
#define DOUT  3
#define PSTEPS 3
#define MREL  (BB * RR)   // 65536
#define MPART (BB * NN)   // 8192

// ---------------- scratch (device globals) ----------------------------------
__device__ float    g_relbase[MREL * NF]; // 32 MB fp32
__device__ uint32_t g_ptmpP[MPART * NF];
__device__ uint32_t g_peffP[MPART * NF];
__device__ float    g_peffect[MPART * NF];
__device__ float    g_pbase[MPART * NF];
__device__ float    g_eagg[MPART * NF];
__device__ float    g_pair[2 * MPART * NF]; // Sr/Ss, later P1/P2
__device__ int      g_recv[MREL];
__device__ int      g_send[MREL];
__device__ int      g_cnt[MPART];
__device__ int      g_off[MPART + 1];
__device__ int      g_pos[MPART];
__device__ int      g_list[MREL];
// packed weights: [Kpad/2][128] u32 (bf16x2 of k,k+1 per col n), hi & lo planes
#define WT_U32 79872
__device__ uint32_t g_wh[WT_U32];
__device__ uint32_t g_wl[WT_U32];
#define WO_PE0  0       // Kpad 32
#define WO_PE1  2048    // 128
#define WO_RE1  10240   // 128
#define WO_RE2  18432   // 128
#define WO_RPT  26624   // 128 (rp_w rows 0-127)
#define WO_RPM  34816   // 128 (rows 128-255)
#define WO_RPB  43008   // 128 (rows 256-383)
#define WO_PP   51200   // 256 (top: k2 0-63, bot: +8192)
#define WO_PR0  67584   // 128
#define WO_REWR 75776   // 32 (re_w0 rows 0-31)
#define WO_REWS 77824   // 32 (re_w0 rows 32-63)

// ---------------- helpers ----------------------------------------------------
__device__ __forceinline__ uint32_t packbf(float vlo, float vhi) {
    uint32_t r;
    asm("cvt.rn.bf16x2.f32 %0, %1, %2;" : "=r"(r) : "f"(vhi), "f"(vlo));
    return r;
}
__device__ __forceinline__ void mma16816(float* d, const uint32_t* a, uint32_t b0, uint32_t b1) {
    asm volatile("mma.sync.aligned.m16n8k16.row.col.f32.bf16.bf16.f32 "
                 "{%0,%1,%2,%3}, {%4,%5,%6,%7}, {%8,%9}, {%0,%1,%2,%3};"
                 : "+f"(d[0]), "+f"(d[1]), "+f"(d[2]), "+f"(d[3])
                 : "r"(a[0]), "r"(a[1]), "r"(a[2]), "r"(a[3]), "r"(b0), "r"(b1));
}

// ---------------- index extraction + inline CSR count (high-MLP) -------------
__device__ __forceinline__ void proc_quad(uint4 v, long long idx,
                                          int* __restrict__ dst,
                                          int* __restrict__ cnt, bool do_cnt)
{
    if (v.x | v.y | v.z | v.w) {
        long long e = idx * 4;
        int b = (int)(e >> 23);
        int n = (int)((e >> 13) & (NN - 1));
        int r = (int)(e & (RR - 1));
        int* o = dst + b * RR + r;
        int nz = 0;
        if (v.x) { o[0] = n; ++nz; }
        if (v.y) { o[1] = n; ++nz; }
        if (v.z) { o[2] = n; ++nz; }
        if (v.w) { o[3] = n; ++nz; }
        if (do_cnt) atomicAdd(&cnt[(b << 10) + n], nz);
    }
}

__global__ void extract_idx_kernel(const uint4* __restrict__ Rr,
                                   const uint4* __restrict__ Rs,
                                   int* __restrict__ recv, int* __restrict__ send,
                                   int* __restrict__ cnt)
{
    const long long total  = (long long)BB * NN * RR / 4;          // 16M uint4
    const long long stride = (long long)gridDim.x * blockDim.x * 4;
    const int bd = blockDim.x;
    for (long long base = (long long)blockIdx.x * bd * 4 + threadIdx.x;
         base < total; base += stride) {
        uint4 a0 = __ldcs(Rr + base);
        uint4 a1 = __ldcs(Rr + base + bd);
        uint4 a2 = __ldcs(Rr + base + 2 * bd);
        uint4 a3 = __ldcs(Rr + base + 3 * bd);
        uint4 b0 = __ldcs(Rs + base);
        uint4 b1 = __ldcs(Rs + base + bd);
        uint4 b2 = __ldcs(Rs + base + 2 * bd);
        uint4 b3 = __ldcs(Rs + base + 3 * bd);
        proc_quad(a0, base,          recv, cnt, true);
        proc_quad(a1, base + bd,     recv, cnt, true);
        proc_quad(a2, base + 2 * bd, recv, cnt, true);
        proc_quad(a3, base + 3 * bd, recv, cnt, true);
        proc_quad(b0, base,          send, nullptr, false);
        proc_quad(b1, base + bd,     send, nullptr, false);
        proc_quad(b2, base + 2 * bd, send, nullptr, false);
        proc_quad(b3, base + 3 * bd, send, nullptr, false);
    }
}

// ---------------- CSR scan + fill --------------------------------------------
__global__ void csr_scan_kernel(const int* __restrict__ cnt,
                                int* __restrict__ off, int* __restrict__ pos) {
    __shared__ int part[1024];
    const int tid = threadIdx.x;
    int local[8];
    int s = 0;
#pragma unroll
    for (int j = 0; j < 8; ++j) { local[j] = s; s += cnt[tid * 8 + j]; }
    part[tid] = s;
    __syncthreads();
    for (int d = 1; d < 1024; d <<= 1) {
        int v = part[tid];
        if (tid >= d) v += part[tid - d];
        __syncthreads();
        part[tid] = v;
        __syncthreads();
    }
    int base = (tid == 0) ? 0 : part[tid - 1];
#pragma unroll
    for (int j = 0; j < 8; ++j) {
        int o = base + local[j];
        off[tid * 8 + j] = o;
        pos[tid * 8 + j] = o;
    }
    if (tid == 1023) off[MPART] = part[1023];
}
__global__ void csr_fill_kernel(const int* __restrict__ recv,
                                int* __restrict__ pos, int* __restrict__ list) {
    int r = blockIdx.x * blockDim.x + threadIdx.x;
    int p = ((r >> 13) << 10) + recv[r];
    int idx = atomicAdd(&pos[p], 1);
    list[idx] = r;
}

// ---------------- weights: transpose + split + pack (+ cnt zero) ------------
__global__ void split_all_kernel(const float* __restrict__ pe_w0, const float* __restrict__ pe_w1,
                                 const float* __restrict__ re_w0, const float* __restrict__ re_w1,
                                 const float* __restrict__ re_w2, const float* __restrict__ rp_w,
                                 const float* __restrict__ pp_w, const float* __restrict__ pr_w0,
                                 uint32_t* __restrict__ hi, uint32_t* __restrict__ lo,
                                 int* __restrict__ cnt)
{
    int idx = blockIdx.x * blockDim.x + threadIdx.x;
    if (idx >= WT_U32) {
        int z = idx - WT_U32;
        if (z < MPART) cnt[z] = 0;
        return;
    }
    const float* w; int K, local;
    if      (idx < 2048)  { w = pe_w0;              K = 32;  local = idx; }
    else if (idx < 10240) { w = pe_w1;              K = 128; local = idx - 2048; }
    else if (idx < 18432) { w = re_w1;              K = 128; local = idx - 10240; }
    else if (idx < 26624) { w = re_w2;              K = 128; local = idx - 18432; }
    else if (idx < 34816) { w = rp_w;               K = 128; local = idx - 26624; }
    else if (idx < 43008) { w = rp_w + 128 * 128;   K = 128; local = idx - 34816; }
    else if (idx < 51200) { w = rp_w + 256 * 128;   K = 128; local = idx - 43008; }
    else if (idx < 67584) { w = pp_w;               K = 256; local = idx - 51200; }
    else if (idx < 75776) { w = pr_w0;              K = 128; local = idx - 67584; }
    else if (idx < 77824) { w = re_w0;              K = 32;  local = idx - 75776; }
    else                  { w = re_w0 + 32 * 128;   K = 32;  local = idx - 77824; }
    int k2 = local >> 7, n = local & 127;
    int k0 = 2 * k2;
    float v0 = (k0 < K)     ? w[(size_t)k0 * 128 + n]       : 0.f;
    float v1 = (k0 + 1 < K) ? w[(size_t)(k0 + 1) * 128 + n] : 0.f;
    uint32_t h = packbf(v0, v1);
    float h0 = __uint_as_float(h << 16);
    float h1 = __uint_as_float(h & 0xFFFF0000u);
    hi[idx] = h;
    lo[idx] = packbf(v0 - h0, v1 - h1);
}

// -------- CSR gather-reduce aggregation (atomic-free) -----------------------
template<bool FIRST>
__global__ __launch_bounds__(256, 8)
void agg_kernel(const float* __restrict__ relbase,
                const float* __restrict__ P1, const float* __restrict__ P2,
                const int* __restrict__ send,
                const int* __restrict__ off, const int* __restrict__ list,
                float* __restrict__ eagg)
{
    const int p = blockIdx.x * 2 + (threadIdx.x >> 7);
    const int c = threadIdx.x & 127;
    const int beg = off[p], end = off[p + 1];
    float p1c = FIRST ? 0.f : P1[(size_t)p * NF + c];
    float acc = 0.f;
    for (int i = beg; i < end; ++i) {
        int r = list[i];
        float v = relbase[(size_t)r * NF + c] + p1c;
        if (!FIRST) {
            int gs = ((r >> 13) << 10) + send[r];
            v += P2[(size_t)gs * NF + c];
        }
        acc += fmaxf(v, 0.f);
    }
    eagg[(size_t)p * NF + c] = acc;
}

// ================== chained multi-layer GEMM machinery =======================
// A: R12-validated split planes (hi/lo u32, row stride 68 u32 = 80B-class,
//    conflict-free). W: interleaved (hi,lo) uint2, 16 k2-rows x 132 pairs,
//    row stride 1056B (verified conflict-free for 64-bit phases).
#define CH_WA   0
#define CH_B0   512
#define CH_BA   1024
#define CH_BB   1536
#define CH_BC   2048
#define CH_AHI  2560                        // 128 rows x 68 u32
#define CH_ALO  (CH_AHI + 34816)            // 37376
#define CH_WBASE (CH_ALO + 34816)           // 72192
#define CH_W(s) (CH_WBASE + (s) * 16896)    // 16*132*8 per stage
#define CH_TOTAL (CH_WBASE + 2 * 16896)     // 105984

__device__ __forceinline__ void ch_fill_w(char* smem, int s, int kt,
    const uint32_t* __restrict__ Whp, const uint32_t* __restrict__ Wlp, int tid)
{
    const int k2 = tid >> 4;
    const int nn = (tid & 15) * 8;
    const size_t gi = (size_t)(kt * 16 + k2) * 128 + nn;
    uint4 h0 = *(const uint4*)(Whp + gi);
    uint4 h1 = *(const uint4*)(Whp + gi + 4);
    uint4 l0 = *(const uint4*)(Wlp + gi);
    uint4 l1 = *(const uint4*)(Wlp + gi + 4);
    uint4* wp = (uint4*)((uint2*)(smem + CH_W(s)) + k2 * 132 + nn);
    wp[0] = make_uint4(h0.x, l0.x, h0.y, l0.y);
    wp[1] = make_uint4(h0.z, l0.z, h0.w, l0.w);
    wp[2] = make_uint4(h1.x, l1.x, h1.y, l1.y);
    wp[3] = make_uint4(h1.z, l1.z, h1.w, l1.w);
}

__device__ __forceinline__ void ch_compute(char* smem, int kt, int s,
    int wm, int wn, int lane, float (&acc)[4][4][4])
{
    const uint32_t* AH = (const uint32_t*)(smem + CH_AHI);
    const uint32_t* AL = (const uint32_t*)(smem + CH_ALO);
    const uint2* W2 = (const uint2*)(smem + CH_W(s));
#pragma unroll
    for (int step = 0; step < 2; ++step) {
        uint32_t ah[4][4], al[4][4];
#pragma unroll
        for (int f = 0; f < 4; ++f) {
            int r = wm * 64 + f * 16 + (lane >> 2);
            int i0 = r * 68 + kt * 16 + (lane & 3) + step * 8;
            ah[f][0] = AH[i0];       ah[f][1] = AH[i0 + 544];
            ah[f][2] = AH[i0 + 4];   ah[f][3] = AH[i0 + 548];
            al[f][0] = AL[i0];       al[f][1] = AL[i0 + 544];
            al[f][2] = AL[i0 + 4];   al[f][3] = AL[i0 + 548];
        }
#pragma unroll
        for (int nf = 0; nf < 4; ++nf) {
            int bi = (step * 8 + (lane & 3)) * 132 + wn * 32 + nf * 8 + (lane >> 2);
            uint2 q0 = W2[bi];
            uint2 q1 = W2[bi + 528];   // +4 k2-rows
#pragma unroll
            for (int f = 0; f < 4; ++f) {
                mma16816(acc[f][nf], ah[f], q0.x, q1.x);
                mma16816(acc[f][nf], ah[f], q0.y, q1.y);
                mma16816(acc[f][nf], al[f], q0.x, q1.x);
            }
        }
    }
}

__device__ __forceinline__ void ch_gemm_layer(char* smem,
    const uint32_t* __restrict__ Whp, const uint32_t* __restrict__ Wlp, int nchunk,
    int wm, int wn, int lane, int tid, float (&acc)[4][4][4])
{
#pragma unroll
    for (int f = 0; f < 4; ++f)
#pragma unroll
        for (int nf = 0; nf < 4; ++nf)
#pragma unroll
            for (int j = 0; j < 4; ++j) acc[f][nf][j] = 0.f;
    ch_fill_w(smem, 0, 0, Whp, Wlp, tid);
    __syncthreads();
    for (int kt = 0; kt < nchunk; ++kt) {
        int s = kt & 1;
        if (kt + 1 < nchunk) ch_fill_w(smem, s ^ 1, kt + 1, Whp, Wlp, tid);
        ch_compute(smem, kt, s, wm, wn, lane, acc);
        __syncthreads();
    }
}

__device__ __forceinline__ void ch_epi_planes(char* smem, const float* bias_s,
    int wm, int wn, int lane, float (&acc)[4][4][4])
{
    uint32_t* AH = (uint32_t*)(smem + CH_AHI);
    uint32_t* AL = (uint32_t*)(smem + CH_ALO);
#pragma unroll
    for (int f = 0; f < 4; ++f) {
        int r0 = wm * 64 + f * 16 + (lane >> 2);
        int r1 = r0 + 8;
#pragma unroll
        for (int nf = 0; nf < 4; ++nf) {
            int c = wn * 32 + nf * 8 + (lane & 3) * 2;
            int c2 = c >> 1;
            float a0 = fmaxf(acc[f][nf][0] + bias_s[c], 0.f);
            float a1 = fmaxf(acc[f][nf][1] + bias_s[c + 1], 0.f);
            float a2 = fmaxf(acc[f][nf][2] + bias_s[c], 0.f);
            float a3 = fmaxf(acc[f][nf][3] + bias_s[c + 1], 0.f);
            uint32_t h0 = packbf(a0, a1), h1 = packbf(a2, a3);
            AH[r0 * 68 + c2] = h0;
            AH[r1 * 68 + c2] = h1;
            AL[r0 * 68 + c2] = packbf(a0 - __uint_as_float(h0 << 16), a1 - __uint_as_float(h0 & 0xFFFF0000u));
            AL[r1 * 68 + c2] = packbf(a2 - __uint_as_float(h1 << 16), a3 - __uint_as_float(h1 & 0xFFFF0000u));
        }
    }
}

__device__ __forceinline__ void ch_write_f32(float* dst, int row0, const float* bias_s,
    int wm, int wn, int lane, float (&acc)[4][4][4])
{
#pragma unroll
    for (int f = 0; f < 4; ++f) {
        int r0 = wm * 64 + f * 16 + (lane >> 2), r1 = r0 + 8;
#pragma unroll
        for (int nf = 0; nf < 4; ++nf) {
            int c = wn * 32 + nf * 8 + (lane & 3) * 2;
            float b0 = bias_s ? bias_s[c] : 0.f;
            float b1 = bias_s ? bias_s[c + 1] : 0.f;
            *(float2*)(dst + (size_t)(row0 + r0) * 128 + c) =
                make_float2(acc[f][nf][0] + b0, acc[f][nf][1] + b1);
            *(float2*)(dst + (size_t)(row0 + r1) * 128 + c) =
                make_float2(acc[f][nf][2] + b0, acc[f][nf][3] + b1);
        }
    }
}

// ---- fused relation chain: gather-combine -> re1 -> re2 -> relbase ----------
__global__ __launch_bounds__(256, 2)
void relchain_kernel(const float* __restrict__ Sr, const float* __restrict__ Ss,
                     const float* __restrict__ Ra,
                     const float* __restrict__ wa, const float* __restrict__ b0,
                     const float* __restrict__ b1, const float* __restrict__ b2,
                     const float* __restrict__ brp,
                     const int* __restrict__ recv, const int* __restrict__ send,
                     const uint32_t* __restrict__ wh, const uint32_t* __restrict__ wl,
                     float* __restrict__ relbase)
{
    extern __shared__ char smem[];
    const int tid = threadIdx.x, lane = tid & 31, wid = tid >> 5;
    const int wm = wid & 1, wn = wid >> 1;
    const int row0 = blockIdx.x * 128;
    float* wa_s = (float*)(smem + CH_WA);
    float* b0_s = (float*)(smem + CH_B0);
    float* bA_s = (float*)(smem + CH_BA);
    float* bB_s = (float*)(smem + CH_BB);
    float* bC_s = (float*)(smem + CH_BC);
    if (tid < 128) {
        wa_s[tid] = wa[tid]; b0_s[tid] = b0[tid];
        bA_s[tid] = b1[tid]; bB_s[tid] = b2[tid]; bC_s[tid] = brp[tid];
    }
    const int row = tid >> 1, half = tid & 1, grow = row0 + row, bb = grow >> 13;
    const float ra = Ra[grow];
    const int rv = (bb << 10) + recv[grow];
    const int sd = (bb << 10) + send[grow];
    const float4* pr = (const float4*)(Sr + (size_t)rv * 128 + half * 64);
    const float4* ps = (const float4*)(Ss + (size_t)sd * 128 + half * 64);
    __syncthreads();
    {
        uint32_t* AH = (uint32_t*)(smem + CH_AHI) + row * 68 + half * 32;
        uint32_t* AL = (uint32_t*)(smem + CH_ALO) + row * 68 + half * 32;
#pragma unroll
        for (int j = 0; j < 16; ++j) {
            float4 u = pr[j], v = ps[j];
            int c = half * 64 + j * 4;
            float a0 = fmaxf(u.x + v.x + ra * wa_s[c]     + b0_s[c],     0.f);
            float a1 = fmaxf(u.y + v.y + ra * wa_s[c + 1] + b0_s[c + 1], 0.f);
            float a2 = fmaxf(u.z + v.z + ra * wa_s[c + 2] + b0_s[c + 2], 0.f);
            float a3 = fmaxf(u.w + v.w + ra * wa_s[c + 3] + b0_s[c + 3], 0.f);
            uint32_t h0 = packbf(a0, a1), h1 = packbf(a2, a3);
            AH[2 * j] = h0; AH[2 * j + 1] = h1;
            AL[2 * j] = packbf(a0 - __uint_as_float(h0 << 16), a1 - __uint_as_float(h0 & 0xFFFF0000u));
            AL[2 * j + 1] = packbf(a2 - __uint_as_float(h1 << 16), a3 - __uint_as_float(h1 & 0xFFFF0000u));
        }
    }
    float acc[4][4][4];
    ch_gemm_layer(smem, wh + WO_RE1, wl + WO_RE1, 4, wm, wn, lane, tid, acc);
    ch_epi_planes(smem, bA_s, wm, wn, lane, acc);
    ch_gemm_layer(smem, wh + WO_RE2, wl + WO_RE2, 4, wm, wn, lane, tid, acc);
    ch_epi_planes(smem, bB_s, wm, wn, lane, acc);
    ch_gemm_layer(smem, wh + WO_RPT, wl + WO_RPT, 4, wm, wn, lane, tid, acc);
    ch_write_f32(relbase, row0, bC_s, wm, wn, lane, acc);
}

// ---- fused particle prep: Sr, Ss, pe0 -> pe1 -> pbase -----------------------
__global__ __launch_bounds__(256, 2)
void partall_kernel(const float* __restrict__ state,
                    const float* __restrict__ pe_b0, const float* __restrict__ pe_b1,
                    const float* __restrict__ pp_b,
                    const uint32_t* __restrict__ wh, const uint32_t* __restrict__ wl,
                    float* __restrict__ Sr, float* __restrict__ Ss,
                    float* __restrict__ pbase)
{
    extern __shared__ char smem[];
    const int tid = threadIdx.x, lane = tid & 31, wid = tid >> 5;
    const int wm = wid & 1, wn = wid >> 1;
    const int row0 = blockIdx.x * 128;
    float* bA_s = (float*)(smem + CH_BA);
    float* bB_s = (float*)(smem + CH_BB);
    float* bC_s = (float*)(smem + CH_BC);
    if (tid < 128) { bA_s[tid] = pe_b0[tid]; bB_s[tid] = pe_b1[tid]; bC_s[tid] = pp_b[tid]; }
    {
        const int row = tid >> 1, half = tid & 1, grow = row0 + row;
        const float4* q = (const float4*)(state + (size_t)grow * 32 + half * 16);
        float x[16];
#pragma unroll
        for (int j = 0; j < 4; ++j) {
            float4 u = q[j];
            x[4 * j] = u.x; x[4 * j + 1] = u.y; x[4 * j + 2] = u.z; x[4 * j + 3] = u.w;
        }
        uint32_t* AH = (uint32_t*)(smem + CH_AHI) + row * 68 + half * 8;
        uint32_t* AL = (uint32_t*)(smem + CH_ALO) + row * 68 + half * 8;
#pragma unroll
        for (int j = 0; j < 8; ++j) {
            uint32_t h = packbf(x[2 * j], x[2 * j + 1]);
            AH[j] = h;
            AL[j] = packbf(x[2 * j] - __uint_as_float(h << 16),
                           x[2 * j + 1] - __uint_as_float(h & 0xFFFF0000u));
        }
    }
    float acc[4][4][4];
    ch_gemm_layer(smem, wh + WO_REWR, wl + WO_REWR, 1, wm, wn, lane, tid, acc);
    ch_write_f32(Sr, row0, nullptr, wm, wn, lane, acc);
    ch_gemm_layer(smem, wh + WO_REWS, wl + WO_REWS, 1, wm, wn, lane, tid, acc);
    ch_write_f32(Ss, row0, nullptr, wm, wn, lane, acc);
    ch_gemm_layer(smem, wh + WO_PE0, wl + WO_PE0, 1, wm, wn, lane, tid, acc);
    ch_epi_planes(smem, bA_s, wm, wn, lane, acc);
    ch_gemm_layer(smem, wh + WO_PE1, wl + WO_PE1, 4, wm, wn, lane, tid, acc);
    ch_epi_planes(smem, bB_s, wm, wn, lane, acc);
    ch_gemm_layer(smem, wh + WO_PP, wl + WO_PP, 4, wm, wn, lane, tid, acc);
    ch_write_f32(pbase, row0, bC_s, wm, wn, lane, acc);
}

// ---------------- generic fused mma.sync GEMM (R12-validated, untouched) -----
enum { A_F32 = 0, A_BF = 1 };
enum { E_RELU_F32 = 0, E_BASE = 2, E_RESID = 3, E_RESID0 = 4 };

#define SM_BIAS 0
#define SM_A    1536
#define AHI_OFF(s) (SM_A + (s) * 10240)
#define ALO_OFF(s) (SM_A + 20480 + (s) * 10240)
#define SM_W    (SM_A + 40960)
#define WHI_OFF(s) (SM_W + (s) * 8704)
#define WLO_OFF(s) (SM_W + 17408 + (s) * 8704)
#define SMEM_TOTAL_B (SM_W + 34816)   // 77312 bytes

template<int MODE_A>
__device__ __forceinline__ void fill_tile(
    char* smem, int s, int kt,
    const void* __restrict__ Av,
    const uint32_t* __restrict__ Whp, const uint32_t* __restrict__ Wlp,
    int row0, int K, int tid)
{
    const int row   = tid >> 1;
    const int half  = tid & 1;
    const int kbase = kt * 32 + half * 16;
    const int grow  = row0 + row;

    uint4 hA0, hA1, lA0, lA1;

    if (MODE_A == A_BF) {
        const uint32_t* Xp = (const uint32_t*)Av + (size_t)grow * 128;
        int k2 = kbase >> 1;
        hA0 = *(const uint4*)(Xp + k2);
        hA1 = *(const uint4*)(Xp + k2 + 4);
        lA0 = *(const uint4*)(Xp + 64 + k2);
        lA1 = *(const uint4*)(Xp + 64 + k2 + 4);
    } else {
        float x[16];
        if (kbase < K) {
            const float4* q = (const float4*)((const float*)Av + (size_t)grow * K + kbase);
#pragma unroll
            for (int j = 0; j < 4; ++j) {
                float4 u = q[j];
                x[4 * j] = u.x; x[4 * j + 1] = u.y; x[4 * j + 2] = u.z; x[4 * j + 3] = u.w;
            }
        } else {
#pragma unroll
            for (int j = 0; j < 16; ++j) x[j] = 0.f;
        }
        uint32_t hi[8], lo[8];
#pragma unroll
        for (int j = 0; j < 8; ++j) {
            uint32_t h = packbf(x[2 * j], x[2 * j + 1]);
            hi[j] = h;
            float h0 = __uint_as_float(h << 16);
            float h1 = __uint_as_float(h & 0xFFFF0000u);
            lo[j] = packbf(x[2 * j] - h0, x[2 * j + 1] - h1);
        }
        hA0 = make_uint4(hi[0], hi[1], hi[2], hi[3]);
        hA1 = make_uint4(hi[4], hi[5], hi[6], hi[7]);
        lA0 = make_uint4(lo[0], lo[1], lo[2], lo[3]);
        lA1 = make_uint4(lo[4], lo[5], lo[6], lo[7]);
    }
    {
        uint4* dh = (uint4*)(smem + AHI_OFF(s) + row * 80 + half * 32);
        dh[0] = hA0; dh[1] = hA1;
        uint4* dl = (uint4*)(smem + ALO_OFF(s) + row * 80 + half * 32);
        dl[0] = lA0; dl[1] = lA1;
    }
    {
        const int k2 = tid >> 4;
        const int nn = (tid & 15) * 8;
        const size_t gi = (size_t)(kt * 16 + k2) * 128 + nn;
        uint4 h0 = *(const uint4*)(Whp + gi);
        uint4 h1 = *(const uint4*)(Whp + gi + 4);
        uint4 l0 = *(const uint4*)(Wlp + gi);
        uint4 l1 = *(const uint4*)(Wlp + gi + 4);
        char* wb = smem + WHI_OFF(s) + k2 * 544 + nn * 4;
        ((uint4*)wb)[0] = h0; ((uint4*)wb)[1] = h1;
        char* lb = smem + WLO_OFF(s) + k2 * 544 + nn * 4;
        ((uint4*)lb)[0] = l0; ((uint4*)lb)[1] = l1;
    }
}

template<int MODE_A, int MODE_EPI>
__global__ __launch_bounds__(256, 2)
void mma_gemm(const void* __restrict__ Av,
              const uint32_t* __restrict__ Whp, const uint32_t* __restrict__ Wlp,
              const float* __restrict__ bias, void* __restrict__ Cv,
              const float* __restrict__ base,
              uint32_t* __restrict__ C2,
              int K, int nchunk, int wstride, long long cstrideB)
{
    extern __shared__ char smem[];
    const int tid  = threadIdx.x;
    const int wid  = tid >> 5;
    const int lane = tid & 31;
    const int row0 = blockIdx.x * 128;
    const int wm = wid & 1;
    const int wn = wid >> 1;

    Whp += (size_t)blockIdx.y * wstride;
    Wlp += (size_t)blockIdx.y * wstride;
    char* Cb = (char*)Cv + (size_t)blockIdx.y * cstrideB;

    float* bias_s = (float*)(smem + SM_BIAS);
    if (tid < 128) bias_s[tid] = bias ? bias[tid] : 0.f;
    __syncthreads();

    float acc[4][4][4];
#pragma unroll
    for (int f = 0; f < 4; ++f)
#pragma unroll
        for (int nf = 0; nf < 4; ++nf)
#pragma unroll
            for (int j = 0; j < 4; ++j) acc[f][nf][j] = 0.f;

    fill_tile<MODE_A>(smem, 0, 0, Av, Whp, Wlp, row0, K, tid);
    __syncthreads();

    for (int kt = 0; kt < nchunk; ++kt) {
        const int s = kt & 1;
        if (kt + 1 < nchunk)
            fill_tile<MODE_A>(smem, s ^ 1, kt + 1, Av, Whp, Wlp, row0, K, tid);

        const uint32_t* AH = (const uint32_t*)(smem + AHI_OFF(s));
        const uint32_t* AL = (const uint32_t*)(smem + ALO_OFF(s));
        const uint32_t* WH = (const uint32_t*)(smem + WHI_OFF(s));
        const uint32_t* WL = (const uint32_t*)(smem + WLO_OFF(s));

#pragma unroll
        for (int step = 0; step < 2; ++step) {
            uint32_t ah[4][4], al[4][4];
#pragma unroll
            for (int f = 0; f < 4; ++f) {
                int r = wm * 64 + f * 16 + (lane >> 2);
                int i0 = r * 20 + (lane & 3) + step * 8;
                ah[f][0] = AH[i0];       ah[f][1] = AH[i0 + 160];
                ah[f][2] = AH[i0 + 4];   ah[f][3] = AH[i0 + 164];
                al[f][0] = AL[i0];       al[f][1] = AL[i0 + 160];
                al[f][2] = AL[i0 + 4];   al[f][3] = AL[i0 + 164];
            }
#pragma unroll
            for (int nf = 0; nf < 4; ++nf) {
                int bi = (step * 8 + (lane & 3)) * 136 + wn * 32 + nf * 8 + (lane >> 2);
                uint32_t bh0 = WH[bi], bh1 = WH[bi + 544];
                uint32_t bl0 = WL[bi], bl1 = WL[bi + 544];
#pragma unroll
                for (int f = 0; f < 4; ++f) {
                    mma16816(acc[f][nf], ah[f], bh0, bh1);
                    mma16816(acc[f][nf], ah[f], bl0, bl1);
                    mma16816(acc[f][nf], al[f], bh0, bh1);
                }
            }
        }
        __syncthreads();
    }

    float bc0[4], bc1[4];
#pragma unroll
    for (int nf = 0; nf < 4; ++nf) {
        int c = wn * 32 + nf * 8 + (lane & 3) * 2;
        bc0[nf] = bias_s[c];
        bc1[nf] = bias_s[c + 1];
    }
#pragma unroll
    for (int f = 0; f < 4; ++f) {
        int rl0 = wm * 64 + f * 16 + (lane >> 2);
        int rl1 = rl0 + 8;
        int r0 = row0 + rl0;
        int r1 = row0 + rl1;
#pragma unroll
        for (int nf = 0; nf < 4; ++nf) {
            int c = wn * 32 + nf * 8 + (lane & 3) * 2;
            float v0 = acc[f][nf][0] + bc0[nf];
            float v1 = acc[f][nf][1] + bc1[nf];
            float v2 = acc[f][nf][2] + bc0[nf];
            float v3 = acc[f][nf][3] + bc1[nf];
            if (MODE_EPI == E_RELU_F32) {
                float* CF = (float*)Cb;
                *(float2*)(&CF[(size_t)r0 * NF + c]) = make_float2(fmaxf(v0, 0.f), fmaxf(v1, 0.f));
                *(float2*)(&CF[(size_t)r1 * NF + c]) = make_float2(fmaxf(v2, 0.f), fmaxf(v3, 0.f));
            } else if (MODE_EPI == E_BASE) {
                float* CF = (float*)Cb;
                *(float2*)(&CF[(size_t)r0 * NF + c]) = make_float2(v0, v1);
                *(float2*)(&CF[(size_t)r1 * NF + c]) = make_float2(v2, v3);
            } else { // E_RESID / E_RESID0
                float* CF = (float*)Cb;
                float2 b0 = *(const float2*)(&base[(size_t)r0 * NF + c]);
                float2 b1 = *(const float2*)(&base[(size_t)r1 * NF + c]);
                float2 p0 = make_float2(0.f, 0.f), p1 = make_float2(0.f, 0.f);
                if (MODE_EPI == E_RESID) {
                    p0 = *(const float2*)(&CF[(size_t)r0 * NF + c]);
                    p1 = *(const float2*)(&CF[(size_t)r1 * NF + c]);
                }
                float a0 = fmaxf(v0 + b0.x + p0.x, 0.f);
                float a1 = fmaxf(v1 + b0.y + p0.y, 0.f);
                float a2 = fmaxf(v2 + b1.x + p1.x, 0.f);
                float a3 = fmaxf(v3 + b1.y + p1.y, 0.f);
                *(float2*)(&CF[(size_t)r0 * NF + c]) = make_float2(a0, a1);
                *(float2*)(&CF[(size_t)r1 * NF + c]) = make_float2(a2, a3);
                uint32_t h0 = packbf(a0, a1);
                uint32_t h1 = packbf(a2, a3);
                C2[(size_t)r0 * 128 + (c >> 1)] = h0;
                C2[(size_t)r1 * 128 + (c >> 1)] = h1;
                C2[(size_t)r0 * 128 + 64 + (c >> 1)] =
                    packbf(a0 - __uint_as_float(h0 << 16), a1 - __uint_as_float(h0 & 0xFFFF0000u));
                C2[(size_t)r1 * 128 + 64 + (c >> 1)] =
                    packbf(a2 - __uint_as_float(h1 << 16), a3 - __uint_as_float(h1 & 0xFFFF0000u));
            }
        }
    }
}

// ---------------- final predictor layer --------------------------------------
__global__ void pred_final_kernel(const float* __restrict__ X, const float* __restrict__ W,
                                  const float* __restrict__ bias, float* __restrict__ out)
{
    __shared__ float Ws[NF * DOUT];
    __shared__ float bs[DOUT];
    int tid = threadIdx.x;
    for (int i = tid; i < NF * DOUT; i += blockDim.x) Ws[i] = W[i];
    if (tid < DOUT) bs[tid] = bias[tid];
    __syncthreads();
    int p = blockIdx.x * blockDim.x + tid;
    float a0 = bs[0], a1 = bs[1], a2 = bs[2];
    const float4* xp = (const float4*)(X + (size_t)p * NF);
#pragma unroll
    for (int k4 = 0; k4 < NF / 4; ++k4) {
        float4 x = xp[k4];
        int k = k4 * 4;
        a0 += x.x * Ws[k * 3 + 0] + x.y * Ws[(k + 1) * 3 + 0] +
              x.z * Ws[(k + 2) * 3 + 0] + x.w * Ws[(k + 3) * 3 + 0];
        a1 += x.x * Ws[k * 3 + 1] + x.y * Ws[(k + 1) * 3 + 1] +
              x.z * Ws[(k + 2) * 3 + 1] + x.w * Ws[(k + 3) * 3 + 1];
        a2 += x.x * Ws[k * 3 + 2] + x.y * Ws[(k + 1) * 3 + 2] +
              x.z * Ws[(k + 2) * 3 + 2] + x.w * Ws[(k + 3) * 3 + 2];
    }
    out[p * 3 + 0] = a0;
    out[p * 3 + 1] = a1;
    out[p * 3 + 2] = a2;
}

// ---------------- host orchestration ----------------------------------------
extern "C" void kernel_launch(void* const* d_in, const int* in_sizes, int n_in,
                              void* d_out, int out_size)
{
    const float* state = (const float*)d_in[0];
    const float* Rr    = (const float*)d_in[1];
    const float* Rs    = (const float*)d_in[2];
    const float* Ra    = (const float*)d_in[3];
    const float* pe_w0 = (const float*)d_in[5],  *pe_b0 = (const float*)d_in[6];
    const float* pe_w1 = (const float*)d_in[7],  *pe_b1 = (const float*)d_in[8];
    const float* re_w0 = (const float*)d_in[9],  *re_b0 = (const float*)d_in[10];
    const float* re_w1 = (const float*)d_in[11], *re_b1 = (const float*)d_in[12];
    const float* re_w2 = (const float*)d_in[13], *re_b2 = (const float*)d_in[14];
    const float* rp_w  = (const float*)d_in[15], *rp_b  = (const float*)d_in[16];
    const float* pp_w  = (const float*)d_in[17], *pp_b  = (const float*)d_in[18];
    const float* pr_w0 = (const float*)d_in[19], *pr_b0 = (const float*)d_in[20];
    const float* pr_w1 = (const float*)d_in[21], *pr_b1 = (const float*)d_in[22];
    float* out = (float*)d_out;

    uint32_t *ptmpP, *peffP, *wh, *wl;
    float *relbase, *peffect, *pbase, *eagg, *pair;
    int *recv, *send, *cnt, *off, *pos, *list;
    cudaGetSymbolAddress((void**)&relbase, g_relbase);
    cudaGetSymbolAddress((void**)&ptmpP,   g_ptmpP);
    cudaGetSymbolAddress((void**)&peffP,   g_peffP);
    cudaGetSymbolAddress((void**)&peffect, g_peffect);
    cudaGetSymbolAddress((void**)&pbase,   g_pbase);
    cudaGetSymbolAddress((void**)&eagg,    g_eagg);
    cudaGetSymbolAddress((void**)&pair,    g_pair);
    cudaGetSymbolAddress((void**)&recv,    g_recv);
    cudaGetSymbolAddress((void**)&send,    g_send);
    cudaGetSymbolAddress((void**)&cnt,     g_cnt);
    cudaGetSymbolAddress((void**)&off,     g_off);
    cudaGetSymbolAddress((void**)&pos,     g_pos);
    cudaGetSymbolAddress((void**)&list,    g_list);
    cudaGetSymbolAddress((void**)&wh,      g_wh);
    cudaGetSymbolAddress((void**)&wl,      g_wl);

    cudaFuncSetAttribute(mma_gemm<A_BF,  E_BASE>,    cudaFuncAttributeMaxDynamicSharedMemorySize, SMEM_TOTAL_B);
    cudaFuncSetAttribute(mma_gemm<A_F32, E_RESID>,   cudaFuncAttributeMaxDynamicSharedMemorySize, SMEM_TOTAL_B);
    cudaFuncSetAttribute(mma_gemm<A_F32, E_RESID0>,  cudaFuncAttributeMaxDynamicSharedMemorySize, SMEM_TOTAL_B);
    cudaFuncSetAttribute(mma_gemm<A_BF,  E_RELU_F32>,cudaFuncAttributeMaxDynamicSharedMemorySize, SMEM_TOTAL_B);
    cudaFuncSetAttribute(relchain_kernel,  cudaFuncAttributeMaxDynamicSharedMemorySize, CH_TOTAL);
    cudaFuncSetAttribute(partall_kernel,   cudaFuncAttributeMaxDynamicSharedMemorySize, CH_TOTAL);

    float* P1 = pair;
    float* P2 = pair + (size_t)MPART * NF;
    const int WO_PPBOT = WO_PP + 8192;

    // 1) weights + cnt zero
    split_all_kernel<<<(WT_U32 + MPART + 255) / 256, 256>>>(
        pe_w0, pe_w1, re_w0, re_w1, re_w2, rp_w, pp_w, pr_w0, wh, wl, cnt);
    // 2) one-hot -> indices + CSR count (high-MLP scan)
    extract_idx_kernel<<<2048, 256>>>((const uint4*)Rr, (const uint4*)Rs, recv, send, cnt);
    // 3) CSR scan + fill
    csr_scan_kernel<<<1, 1024>>>(cnt, off, pos);
    csr_fill_kernel<<<MREL / 256, 256>>>(recv, pos, list);
    // 4) particle prep: Sr, Ss, pencode chain -> pbase
    partall_kernel<<<MPART / 128, 256, CH_TOTAL>>>(state, pe_b0, pe_b1, pp_b, wh, wl,
                                                   P1, P2, pbase);
    // 5) relation chain -> relbase
    relchain_kernel<<<MREL / 128, 256, CH_TOTAL>>>(
        P1, P2, Ra, re_w0 + 64 * 128, re_b0, re_b1, re_b2, rp_b, recv, send, wh, wl, relbase);
    // 6) propagation (first step uses E_RESID0 — no stale peffect read)
    agg_kernel<true><<<MPART / 2, 256>>>(relbase, nullptr, nullptr, send, off, list, eagg);
    mma_gemm<A_F32, E_RESID0><<<MPART / 128, 256, SMEM_TOTAL_B>>>(
        eagg, wh + WO_PPBOT, wl + WO_PPBOT, nullptr, peffect, pbase, peffP, 128, 4, 0, 0);
    for (int s = 1; s < PSTEPS; ++s) {
        dim3 g(MPART / 128, 2);
        mma_gemm<A_BF, E_BASE><<<g, 256, SMEM_TOTAL_B>>>(
            peffP, wh + WO_RPM, wl + WO_RPM, nullptr, pair, nullptr, nullptr,
            128, 4, 8192, (long long)MPART * NF * 4);
        agg_kernel<false><<<MPART / 2, 256>>>(relbase, P1, P2, send, off, list, eagg);
        mma_gemm<A_F32, E_RESID><<<MPART / 128, 256, SMEM_TOTAL_B>>>(
            eagg, wh + WO_PPBOT, wl + WO_PPBOT, nullptr, peffect, pbase, peffP, 128, 4, 0, 0);
    }
    // 7) predictor
    mma_gemm<A_BF, E_RELU_F32><<<MPART / 128, 256, SMEM_TOTAL_B>>>(
        peffP, wh + WO_PR0, wl + WO_PR0, pr_b0, ptmpP, nullptr, nullptr, 128, 4, 0, 0);
    pred_final_kernel<<<MPART / 256, 256>>>((const float*)ptmpP, pr_w1, pr_b1, out);
}

// round 15
// speedup vs baseline: 1.1152x; 1.0417x over previous
#include <cuda_runtime.h>
#include <cuda_bf16.h>
#include <cstdint>

#define BB    8
#define NN    1024
#define RR    8192
#define DIN   32
#define NF    128
#define DOUT  3
#define PSTEPS 3
#define MREL  (BB * RR)   // 65536
#define MPART (BB * NN)   // 8192

// ---------------- scratch (device globals) ----------------------------------
__device__ float    g_relbase[MREL * NF]; // 32 MB fp32
__device__ uint32_t g_ptmpP[MPART * NF];
__device__ uint32_t g_peffP[MPART * NF];
__device__ float    g_peffect[MPART * NF];
__device__ float    g_pbase[MPART * NF];
__device__ float    g_eagg[MPART * NF];
__device__ float    g_pair[2 * MPART * NF]; // Sr/Ss, later P1/P2
__device__ int      g_recv[MREL];
__device__ int      g_send[MREL];
__device__ int      g_cnt[MPART];
__device__ int      g_off[MPART + 1];
__device__ int      g_pos[MPART];
__device__ int      g_list[MREL];
// packed weights: [Kpad/2][128] u32 (bf16x2 of k,k+1 per col n), hi & lo planes
#define WT_U32 79872
__device__ uint32_t g_wh[WT_U32];
__device__ uint32_t g_wl[WT_U32];
#define WO_PE0  0       // Kpad 32
#define WO_PE1  2048    // 128
#define WO_RE1  10240   // 128
#define WO_RE2  18432   // 128
#define WO_RPT  26624   // 128 (rp_w rows 0-127)
#define WO_RPM  34816   // 128 (rows 128-255)
#define WO_RPB  43008   // 128 (rows 256-383)
#define WO_PP   51200   // 256 (top: k2 0-63, bot: +8192)
#define WO_PR0  67584   // 128
#define WO_REWR 75776   // 32 (re_w0 rows 0-31)
#define WO_REWS 77824   // 32 (re_w0 rows 32-63)

// ---------------- helpers ----------------------------------------------------
__device__ __forceinline__ uint32_t packbf(float vlo, float vhi) {
    uint32_t r;
    asm("cvt.rn.bf16x2.f32 %0, %1, %2;" : "=r"(r) : "f"(vhi), "f"(vlo));
    return r;
}
__device__ __forceinline__ void mma16816(float* d, const uint32_t* a, uint32_t b0, uint32_t b1) {
    asm volatile("mma.sync.aligned.m16n8k16.row.col.f32.bf16.bf16.f32 "
                 "{%0,%1,%2,%3}, {%4,%5,%6,%7}, {%8,%9}, {%0,%1,%2,%3};"
                 : "+f"(d[0]), "+f"(d[1]), "+f"(d[2]), "+f"(d[3])
                 : "r"(a[0]), "r"(a[1]), "r"(a[2]), "r"(a[3]), "r"(b0), "r"(b1));
}

// ---------------- index extraction + inline CSR count (high-MLP) -------------
__device__ __forceinline__ void proc_quad(uint4 v, long long idx,
                                          int* __restrict__ dst,
                                          int* __restrict__ cnt, bool do_cnt)
{
    if (v.x | v.y | v.z | v.w) {
        long long e = idx * 4;
        int b = (int)(e >> 23);
        int n = (int)((e >> 13) & (NN - 1));
        int r = (int)(e & (RR - 1));
        int* o = dst + b * RR + r;
        int nz = 0;
        if (v.x) { o[0] = n; ++nz; }
        if (v.y) { o[1] = n; ++nz; }
        if (v.z) { o[2] = n; ++nz; }
        if (v.w) { o[3] = n; ++nz; }
        if (do_cnt) atomicAdd(&cnt[(b << 10) + n], nz);
    }
}

__global__ void extract_idx_kernel(const uint4* __restrict__ Rr,
                                   const uint4* __restrict__ Rs,
                                   int* __restrict__ recv, int* __restrict__ send,
                                   int* __restrict__ cnt)
{
    const long long total  = (long long)BB * NN * RR / 4;          // 16M uint4
    const long long stride = (long long)gridDim.x * blockDim.x * 4;
    const int bd = blockDim.x;
    for (long long base = (long long)blockIdx.x * bd * 4 + threadIdx.x;
         base < total; base += stride) {
        uint4 a0 = __ldcs(Rr + base);
        uint4 a1 = __ldcs(Rr + base + bd);
        uint4 a2 = __ldcs(Rr + base + 2 * bd);
        uint4 a3 = __ldcs(Rr + base + 3 * bd);
        uint4 b0 = __ldcs(Rs + base);
        uint4 b1 = __ldcs(Rs + base + bd);
        uint4 b2 = __ldcs(Rs + base + 2 * bd);
        uint4 b3 = __ldcs(Rs + base + 3 * bd);
        proc_quad(a0, base,          recv, cnt, true);
        proc_quad(a1, base + bd,     recv, cnt, true);
        proc_quad(a2, base + 2 * bd, recv, cnt, true);
        proc_quad(a3, base + 3 * bd, recv, cnt, true);
        proc_quad(b0, base,          send, nullptr, false);
        proc_quad(b1, base + bd,     send, nullptr, false);
        proc_quad(b2, base + 2 * bd, send, nullptr, false);
        proc_quad(b3, base + 3 * bd, send, nullptr, false);
    }
}

// ---------------- CSR scan + fill --------------------------------------------
__global__ void csr_scan_kernel(const int* __restrict__ cnt,
                                int* __restrict__ off, int* __restrict__ pos) {
    __shared__ int part[1024];
    const int tid = threadIdx.x;
    int local[8];
    int s = 0;
#pragma unroll
    for (int j = 0; j < 8; ++j) { local[j] = s; s += cnt[tid * 8 + j]; }
    part[tid] = s;
    __syncthreads();
    for (int d = 1; d < 1024; d <<= 1) {
        int v = part[tid];
        if (tid >= d) v += part[tid - d];
        __syncthreads();
        part[tid] = v;
        __syncthreads();
    }
    int base = (tid == 0) ? 0 : part[tid - 1];
#pragma unroll
    for (int j = 0; j < 8; ++j) {
        int o = base + local[j];
        off[tid * 8 + j] = o;
        pos[tid * 8 + j] = o;
    }
    if (tid == 1023) off[MPART] = part[1023];
}
__global__ void csr_fill_kernel(const int* __restrict__ recv,
                                int* __restrict__ pos, int* __restrict__ list) {
    int r = blockIdx.x * blockDim.x + threadIdx.x;
    int p = ((r >> 13) << 10) + recv[r];
    int idx = atomicAdd(&pos[p], 1);
    list[idx] = r;
}

// ---------------- weights: transpose + split + pack (+ cnt zero) ------------
__global__ void split_all_kernel(const float* __restrict__ pe_w0, const float* __restrict__ pe_w1,
                                 const float* __restrict__ re_w0, const float* __restrict__ re_w1,
                                 const float* __restrict__ re_w2, const float* __restrict__ rp_w,
                                 const float* __restrict__ pp_w, const float* __restrict__ pr_w0,
                                 uint32_t* __restrict__ hi, uint32_t* __restrict__ lo,
                                 int* __restrict__ cnt)
{
    int idx = blockIdx.x * blockDim.x + threadIdx.x;
    if (idx >= WT_U32) {
        int z = idx - WT_U32;
        if (z < MPART) cnt[z] = 0;
        return;
    }
    const float* w; int K, local;
    if      (idx < 2048)  { w = pe_w0;              K = 32;  local = idx; }
    else if (idx < 10240) { w = pe_w1;              K = 128; local = idx - 2048; }
    else if (idx < 18432) { w = re_w1;              K = 128; local = idx - 10240; }
    else if (idx < 26624) { w = re_w2;              K = 128; local = idx - 18432; }
    else if (idx < 34816) { w = rp_w;               K = 128; local = idx - 26624; }
    else if (idx < 43008) { w = rp_w + 128 * 128;   K = 128; local = idx - 34816; }
    else if (idx < 51200) { w = rp_w + 256 * 128;   K = 128; local = idx - 43008; }
    else if (idx < 67584) { w = pp_w;               K = 256; local = idx - 51200; }
    else if (idx < 75776) { w = pr_w0;              K = 128; local = idx - 67584; }
    else if (idx < 77824) { w = re_w0;              K = 32;  local = idx - 75776; }
    else                  { w = re_w0 + 32 * 128;   K = 32;  local = idx - 77824; }
    int k2 = local >> 7, n = local & 127;
    int k0 = 2 * k2;
    float v0 = (k0 < K)     ? w[(size_t)k0 * 128 + n]       : 0.f;
    float v1 = (k0 + 1 < K) ? w[(size_t)(k0 + 1) * 128 + n] : 0.f;
    uint32_t h = packbf(v0, v1);
    float h0 = __uint_as_float(h << 16);
    float h1 = __uint_as_float(h & 0xFFFF0000u);
    hi[idx] = h;
    lo[idx] = packbf(v0 - h0, v1 - h1);
}

// -------- CSR gather-reduce aggregation (atomic-free, 2-way unrolled) --------
template<bool FIRST>
__global__ __launch_bounds__(256, 8)
void agg_kernel(const float* __restrict__ relbase,
                const float* __restrict__ P1, const float* __restrict__ P2,
                const int* __restrict__ send,
                const int* __restrict__ off, const int* __restrict__ list,
                float* __restrict__ eagg)
{
    const int p = blockIdx.x * 2 + (threadIdx.x >> 7);
    const int c = threadIdx.x & 127;
    const int beg = off[p], end = off[p + 1];
    float p1c = FIRST ? 0.f : P1[(size_t)p * NF + c];
    float acc = 0.f;
    int i = beg;
    for (; i + 2 <= end; i += 2) {
        int r0 = list[i];
        int r1 = list[i + 1];
        float v0 = relbase[(size_t)r0 * NF + c];
        float v1 = relbase[(size_t)r1 * NF + c];
        if (!FIRST) {
            int gs0 = ((r0 >> 13) << 10) + send[r0];
            int gs1 = ((r1 >> 13) << 10) + send[r1];
            v0 += P2[(size_t)gs0 * NF + c];
            v1 += P2[(size_t)gs1 * NF + c];
        }
        acc += fmaxf(v0 + p1c, 0.f);
        acc += fmaxf(v1 + p1c, 0.f);
    }
    if (i < end) {
        int r = list[i];
        float v = relbase[(size_t)r * NF + c] + p1c;
        if (!FIRST) {
            int gs = ((r >> 13) << 10) + send[r];
            v += P2[(size_t)gs * NF + c];
        }
        acc += fmaxf(v, 0.f);
    }
    eagg[(size_t)p * NF + c] = acc;
}

// ================== chained multi-layer GEMM machinery (R12-validated) =======
#define CH_WA   0
#define CH_B0   512
#define CH_BA   1024
#define CH_BB   1536
#define CH_BC   2048
#define CH_AHI  2560                        // chained A hi plane: 128 rows x 68 u32
#define CH_ALO  (CH_AHI + 34816)            // 37376
#define CH_WBASE (CH_ALO + 34816)           // 72192
#define CH_WHI(s) (CH_WBASE + (s) * 8704)
#define CH_WLO(s) (CH_WBASE + 17408 + (s) * 8704)
#define CH_TOTAL (CH_WBASE + 34816)         // 107008

__device__ __forceinline__ void ch_fill_w(char* smem, int s, int kt,
    const uint32_t* __restrict__ Whp, const uint32_t* __restrict__ Wlp, int tid)
{
    const int k2 = tid >> 4;
    const int nn = (tid & 15) * 8;
    const size_t gi = (size_t)(kt * 16 + k2) * 128 + nn;
    uint4 h0 = *(const uint4*)(Whp + gi);
    uint4 h1 = *(const uint4*)(Whp + gi + 4);
    uint4 l0 = *(const uint4*)(Wlp + gi);
    uint4 l1 = *(const uint4*)(Wlp + gi + 4);
    char* wb = smem + CH_WHI(s) + k2 * 544 + nn * 4;
    ((uint4*)wb)[0] = h0; ((uint4*)wb)[1] = h1;
    char* lb = smem + CH_WLO(s) + k2 * 544 + nn * 4;
    ((uint4*)lb)[0] = l0; ((uint4*)lb)[1] = l1;
}

__device__ __forceinline__ void ch_compute(char* smem, int kt, int s,
    int wm, int wn, int lane, float (&acc)[4][4][4])
{
    const uint32_t* AH = (const uint32_t*)(smem + CH_AHI);
    const uint32_t* AL = (const uint32_t*)(smem + CH_ALO);
    const uint32_t* WH = (const uint32_t*)(smem + CH_WHI(s));
    const uint32_t* WL = (const uint32_t*)(smem + CH_WLO(s));
#pragma unroll
    for (int step = 0; step < 2; ++step) {
        uint32_t ah[4][4], al[4][4];
#pragma unroll
        for (int f = 0; f < 4; ++f) {
            int r = wm * 64 + f * 16 + (lane >> 2);
            int i0 = r * 68 + kt * 16 + (lane & 3) + step * 8;
            ah[f][0] = AH[i0];       ah[f][1] = AH[i0 + 544];
            ah[f][2] = AH[i0 + 4];   ah[f][3] = AH[i0 + 548];
            al[f][0] = AL[i0];       al[f][1] = AL[i0 + 544];
            al[f][2] = AL[i0 + 4];   al[f][3] = AL[i0 + 548];
        }
#pragma unroll
        for (int nf = 0; nf < 4; ++nf) {
            int bi = (step * 8 + (lane & 3)) * 136 + wn * 32 + nf * 8 + (lane >> 2);
            uint32_t bh0 = WH[bi], bh1 = WH[bi + 544];
            uint32_t bl0 = WL[bi], bl1 = WL[bi + 544];
#pragma unroll
            for (int f = 0; f < 4; ++f) {
                mma16816(acc[f][nf], ah[f], bh0, bh1);
                mma16816(acc[f][nf], ah[f], bl0, bl1);
                mma16816(acc[f][nf], al[f], bh0, bh1);
            }
        }
    }
}

__device__ __forceinline__ void ch_gemm_layer(char* smem,
    const uint32_t* __restrict__ Whp, const uint32_t* __restrict__ Wlp, int nchunk,
    int wm, int wn, int lane, int tid, float (&acc)[4][4][4])
{
#pragma unroll
    for (int f = 0; f < 4; ++f)
#pragma unroll
        for (int nf = 0; nf < 4; ++nf)
#pragma unroll
            for (int j = 0; j < 4; ++j) acc[f][nf][j] = 0.f;
    ch_fill_w(smem, 0, 0, Whp, Wlp, tid);
    __syncthreads();
    for (int kt = 0; kt < nchunk; ++kt) {
        int s = kt & 1;
        if (kt + 1 < nchunk) ch_fill_w(smem, s ^ 1, kt + 1, Whp, Wlp, tid);
        ch_compute(smem, kt, s, wm, wn, lane, acc);
        __syncthreads();
    }
}

__device__ __forceinline__ void ch_epi_planes(char* smem, const float* bias_s,
    int wm, int wn, int lane, float (&acc)[4][4][4])
{
    uint32_t* AH = (uint32_t*)(smem + CH_AHI);
    uint32_t* AL = (uint32_t*)(smem + CH_ALO);
#pragma unroll
    for (int f = 0; f < 4; ++f) {
        int r0 = wm * 64 + f * 16 + (lane >> 2);
        int r1 = r0 + 8;
#pragma unroll
        for (int nf = 0; nf < 4; ++nf) {
            int c = wn * 32 + nf * 8 + (lane & 3) * 2;
            int c2 = c >> 1;
            float a0 = fmaxf(acc[f][nf][0] + bias_s[c], 0.f);
            float a1 = fmaxf(acc[f][nf][1] + bias_s[c + 1], 0.f);
            float a2 = fmaxf(acc[f][nf][2] + bias_s[c], 0.f);
            float a3 = fmaxf(acc[f][nf][3] + bias_s[c + 1], 0.f);
            uint32_t h0 = packbf(a0, a1), h1 = packbf(a2, a3);
            AH[r0 * 68 + c2] = h0;
            AH[r1 * 68 + c2] = h1;
            AL[r0 * 68 + c2] = packbf(a0 - __uint_as_float(h0 << 16), a1 - __uint_as_float(h0 & 0xFFFF0000u));
            AL[r1 * 68 + c2] = packbf(a2 - __uint_as_float(h1 << 16), a3 - __uint_as_float(h1 & 0xFFFF0000u));
        }
    }
}

__device__ __forceinline__ void ch_write_f32(float* dst, int row0, const float* bias_s,
    int wm, int wn, int lane, float (&acc)[4][4][4])
{
#pragma unroll
    for (int f = 0; f < 4; ++f) {
        int r0 = wm * 64 + f * 16 + (lane >> 2), r1 = r0 + 8;
#pragma unroll
        for (int nf = 0; nf < 4; ++nf) {
            int c = wn * 32 + nf * 8 + (lane & 3) * 2;
            float b0 = bias_s ? bias_s[c] : 0.f;
            float b1 = bias_s ? bias_s[c + 1] : 0.f;
            *(float2*)(dst + (size_t)(row0 + r0) * 128 + c) =
                make_float2(acc[f][nf][0] + b0, acc[f][nf][1] + b1);
            *(float2*)(dst + (size_t)(row0 + r1) * 128 + c) =
                make_float2(acc[f][nf][2] + b0, acc[f][nf][3] + b1);
        }
    }
}

// ---- fused relation chain: gather-combine -> re1 -> re2 -> relbase ----------
__global__ __launch_bounds__(256, 2)
void relchain_kernel(const float* __restrict__ Sr, const float* __restrict__ Ss,
                     const float* __restrict__ Ra,
                     const float* __restrict__ wa, const float* __restrict__ b0,
                     const float* __restrict__ b1, const float* __restrict__ b2,
                     const float* __restrict__ brp,
                     const int* __restrict__ recv, const int* __restrict__ send,
                     const uint32_t* __restrict__ wh, const uint32_t* __restrict__ wl,
                     float* __restrict__ relbase)
{
    extern __shared__ char smem[];
    const int tid = threadIdx.x, lane = tid & 31, wid = tid >> 5;
    const int wm = wid & 1, wn = wid >> 1;
    const int row0 = blockIdx.x * 128;
    float* wa_s = (float*)(smem + CH_WA);
    float* b0_s = (float*)(smem + CH_B0);
    float* bA_s = (float*)(smem + CH_BA);
    float* bB_s = (float*)(smem + CH_BB);
    float* bC_s = (float*)(smem + CH_BC);
    if (tid < 128) {
        wa_s[tid] = wa[tid]; b0_s[tid] = b0[tid];
        bA_s[tid] = b1[tid]; bB_s[tid] = b2[tid]; bC_s[tid] = brp[tid];
    }
    const int row = tid >> 1, half = tid & 1, grow = row0 + row, bb = grow >> 13;
    const float ra = Ra[grow];
    const int rv = (bb << 10) + recv[grow];
    const int sd = (bb << 10) + send[grow];
    const float4* pr = (const float4*)(Sr + (size_t)rv * 128 + half * 64);
    const float4* ps = (const float4*)(Ss + (size_t)sd * 128 + half * 64);
    __syncthreads();
    {
        uint32_t* AH = (uint32_t*)(smem + CH_AHI) + row * 68 + half * 32;
        uint32_t* AL = (uint32_t*)(smem + CH_ALO) + row * 68 + half * 32;
#pragma unroll
        for (int j = 0; j < 16; ++j) {
            float4 u = pr[j], v = ps[j];
            int c = half * 64 + j * 4;
            float a0 = fmaxf(u.x + v.x + ra * wa_s[c]     + b0_s[c],     0.f);
            float a1 = fmaxf(u.y + v.y + ra * wa_s[c + 1] + b0_s[c + 1], 0.f);
            float a2 = fmaxf(u.z + v.z + ra * wa_s[c + 2] + b0_s[c + 2], 0.f);
            float a3 = fmaxf(u.w + v.w + ra * wa_s[c + 3] + b0_s[c + 3], 0.f);
            uint32_t h0 = packbf(a0, a1), h1 = packbf(a2, a3);
            AH[2 * j] = h0; AH[2 * j + 1] = h1;
            AL[2 * j] = packbf(a0 - __uint_as_float(h0 << 16), a1 - __uint_as_float(h0 & 0xFFFF0000u));
            AL[2 * j + 1] = packbf(a2 - __uint_as_float(h1 << 16), a3 - __uint_as_float(h1 & 0xFFFF0000u));
        }
    }
    float acc[4][4][4];
    ch_gemm_layer(smem, wh + WO_RE1, wl + WO_RE1, 4, wm, wn, lane, tid, acc);
    ch_epi_planes(smem, bA_s, wm, wn, lane, acc);
    ch_gemm_layer(smem, wh + WO_RE2, wl + WO_RE2, 4, wm, wn, lane, tid, acc);
    ch_epi_planes(smem, bB_s, wm, wn, lane, acc);
    ch_gemm_layer(smem, wh + WO_RPT, wl + WO_RPT, 4, wm, wn, lane, tid, acc);
    ch_write_f32(relbase, row0, bC_s, wm, wn, lane, acc);
}

// ---- fused particle prep: Sr, Ss, pe0 -> pe1 -> pbase -----------------------
__global__ __launch_bounds__(256, 2)
void partall_kernel(const float* __restrict__ state,
                    const float* __restrict__ pe_b0, const float* __restrict__ pe_b1,
                    const float* __restrict__ pp_b,
                    const uint32_t* __restrict__ wh, const uint32_t* __restrict__ wl,
                    float* __restrict__ Sr, float* __restrict__ Ss,
                    float* __restrict__ pbase)
{
    extern __shared__ char smem[];
    const int tid = threadIdx.x, lane = tid & 31, wid = tid >> 5;
    const int wm = wid & 1, wn = wid >> 1;
    const int row0 = blockIdx.x * 128;
    float* bA_s = (float*)(smem + CH_BA);
    float* bB_s = (float*)(smem + CH_BB);
    float* bC_s = (float*)(smem + CH_BC);
    if (tid < 128) { bA_s[tid] = pe_b0[tid]; bB_s[tid] = pe_b1[tid]; bC_s[tid] = pp_b[tid]; }
    {
        const int row = tid >> 1, half = tid & 1, grow = row0 + row;
        const float4* q = (const float4*)(state + (size_t)grow * 32 + half * 16);
        float x[16];
#pragma unroll
        for (int j = 0; j < 4; ++j) {
            float4 u = q[j];
            x[4 * j] = u.x; x[4 * j + 1] = u.y; x[4 * j + 2] = u.z; x[4 * j + 3] = u.w;
        }
        uint32_t* AH = (uint32_t*)(smem + CH_AHI) + row * 68 + half * 8;
        uint32_t* AL = (uint32_t*)(smem + CH_ALO) + row * 68 + half * 8;
#pragma unroll
        for (int j = 0; j < 8; ++j) {
            uint32_t h = packbf(x[2 * j], x[2 * j + 1]);
            AH[j] = h;
            AL[j] = packbf(x[2 * j] - __uint_as_float(h << 16),
                           x[2 * j + 1] - __uint_as_float(h & 0xFFFF0000u));
        }
    }
    float acc[4][4][4];
    ch_gemm_layer(smem, wh + WO_REWR, wl + WO_REWR, 1, wm, wn, lane, tid, acc);
    ch_write_f32(Sr, row0, nullptr, wm, wn, lane, acc);
    ch_gemm_layer(smem, wh + WO_REWS, wl + WO_REWS, 1, wm, wn, lane, tid, acc);
    ch_write_f32(Ss, row0, nullptr, wm, wn, lane, acc);
    ch_gemm_layer(smem, wh + WO_PE0, wl + WO_PE0, 1, wm, wn, lane, tid, acc);
    ch_epi_planes(smem, bA_s, wm, wn, lane, acc);
    ch_gemm_layer(smem, wh + WO_PE1, wl + WO_PE1, 4, wm, wn, lane, tid, acc);
    ch_epi_planes(smem, bB_s, wm, wn, lane, acc);
    ch_gemm_layer(smem, wh + WO_PP, wl + WO_PP, 4, wm, wn, lane, tid, acc);
    ch_write_f32(pbase, row0, bC_s, wm, wn, lane, acc);
}

// ---------------- generic fused mma.sync GEMM (R12-validated) ----------------
enum { A_F32 = 0, A_BF = 1 };
enum { E_RELU_F32 = 0, E_BASE = 2, E_RESID = 3, E_RESID0 = 4 };

#define SM_BIAS 0
#define SM_A    1536
#define AHI_OFF(s) (SM_A + (s) * 10240)
#define ALO_OFF(s) (SM_A + 20480 + (s) * 10240)
#define SM_W    (SM_A + 40960)
#define WHI_OFF(s) (SM_W + (s) * 8704)
#define WLO_OFF(s) (SM_W + 17408 + (s) * 8704)
#define SMEM_TOTAL_B (SM_W + 34816)   // 77312 bytes

template<int MODE_A>
__device__ __forceinline__ void fill_tile(
    char* smem, int s, int kt,
    const void* __restrict__ Av,
    const uint32_t* __restrict__ Whp, const uint32_t* __restrict__ Wlp,
    int row0, int K, int tid)
{
    const int row   = tid >> 1;
    const int half  = tid & 1;
    const int kbase = kt * 32 + half * 16;
    const int grow  = row0 + row;

    uint4 hA0, hA1, lA0, lA1;

    if (MODE_A == A_BF) {
        const uint32_t* Xp = (const uint32_t*)Av + (size_t)grow * 128;
        int k2 = kbase >> 1;
        hA0 = *(const uint4*)(Xp + k2);
        hA1 = *(const uint4*)(Xp + k2 + 4);
        lA0 = *(const uint4*)(Xp + 64 + k2);
        lA1 = *(const uint4*)(Xp + 64 + k2 + 4);
    } else {
        float x[16];
        if (kbase < K) {
            const float4* q = (const float4*)((const float*)Av + (size_t)grow * K + kbase);
#pragma unroll
            for (int j = 0; j < 4; ++j) {
                float4 u = q[j];
                x[4 * j] = u.x; x[4 * j + 1] = u.y; x[4 * j + 2] = u.z; x[4 * j + 3] = u.w;
            }
        } else {
#pragma unroll
            for (int j = 0; j < 16; ++j) x[j] = 0.f;
        }
        uint32_t hi[8], lo[8];
#pragma unroll
        for (int j = 0; j < 8; ++j) {
            uint32_t h = packbf(x[2 * j], x[2 * j + 1]);
            hi[j] = h;
            float h0 = __uint_as_float(h << 16);
            float h1 = __uint_as_float(h & 0xFFFF0000u);
            lo[j] = packbf(x[2 * j] - h0, x[2 * j + 1] - h1);
        }
        hA0 = make_uint4(hi[0], hi[1], hi[2], hi[3]);
        hA1 = make_uint4(hi[4], hi[5], hi[6], hi[7]);
        lA0 = make_uint4(lo[0], lo[1], lo[2], lo[3]);
        lA1 = make_uint4(lo[4], lo[5], lo[6], lo[7]);
    }
    {
        uint4* dh = (uint4*)(smem + AHI_OFF(s) + row * 80 + half * 32);
        dh[0] = hA0; dh[1] = hA1;
        uint4* dl = (uint4*)(smem + ALO_OFF(s) + row * 80 + half * 32);
        dl[0] = lA0; dl[1] = lA1;
    }
    {
        const int k2 = tid >> 4;
        const int nn = (tid & 15) * 8;
        const size_t gi = (size_t)(kt * 16 + k2) * 128 + nn;
        uint4 h0 = *(const uint4*)(Whp + gi);
        uint4 h1 = *(const uint4*)(Whp + gi + 4);
        uint4 l0 = *(const uint4*)(Wlp + gi);
        uint4 l1 = *(const uint4*)(Wlp + gi + 4);
        char* wb = smem + WHI_OFF(s) + k2 * 544 + nn * 4;
        ((uint4*)wb)[0] = h0; ((uint4*)wb)[1] = h1;
        char* lb = smem + WLO_OFF(s) + k2 * 544 + nn * 4;
        ((uint4*)lb)[0] = l0; ((uint4*)lb)[1] = l1;
    }
}

template<int MODE_A, int MODE_EPI>
__global__ __launch_bounds__(256, 2)
void mma_gemm(const void* __restrict__ Av,
              const uint32_t* __restrict__ Whp, const uint32_t* __restrict__ Wlp,
              const float* __restrict__ bias, void* __restrict__ Cv,
              const float* __restrict__ base,
              uint32_t* __restrict__ C2,
              int K, int nchunk, int wstride, long long cstrideB)
{
    extern __shared__ char smem[];
    const int tid  = threadIdx.x;
    const int wid  = tid >> 5;
    const int lane = tid & 31;
    const int row0 = blockIdx.x * 128;
    const int wm = wid & 1;
    const int wn = wid >> 1;

    Whp += (size_t)blockIdx.y * wstride;
    Wlp += (size_t)blockIdx.y * wstride;
    char* Cb = (char*)Cv + (size_t)blockIdx.y * cstrideB;

    float* bias_s = (float*)(smem + SM_BIAS);
    if (tid < 128) bias_s[tid] = bias ? bias[tid] : 0.f;
    __syncthreads();

    float acc[4][4][4];
#pragma unroll
    for (int f = 0; f < 4; ++f)
#pragma unroll
        for (int nf = 0; nf < 4; ++nf)
#pragma unroll
            for (int j = 0; j < 4; ++j) acc[f][nf][j] = 0.f;

    fill_tile<MODE_A>(smem, 0, 0, Av, Whp, Wlp, row0, K, tid);
    __syncthreads();

    for (int kt = 0; kt < nchunk; ++kt) {
        const int s = kt & 1;
        if (kt + 1 < nchunk)
            fill_tile<MODE_A>(smem, s ^ 1, kt + 1, Av, Whp, Wlp, row0, K, tid);

        const uint32_t* AH = (const uint32_t*)(smem + AHI_OFF(s));
        const uint32_t* AL = (const uint32_t*)(smem + ALO_OFF(s));
        const uint32_t* WH = (const uint32_t*)(smem + WHI_OFF(s));
        const uint32_t* WL = (const uint32_t*)(smem + WLO_OFF(s));

#pragma unroll
        for (int step = 0; step < 2; ++step) {
            uint32_t ah[4][4], al[4][4];
#pragma unroll
            for (int f = 0; f < 4; ++f) {
                int r = wm * 64 + f * 16 + (lane >> 2);
                int i0 = r * 20 + (lane & 3) + step * 8;
                ah[f][0] = AH[i0];       ah[f][1] = AH[i0 + 160];
                ah[f][2] = AH[i0 + 4];   ah[f][3] = AH[i0 + 164];
                al[f][0] = AL[i0];       al[f][1] = AL[i0 + 160];
                al[f][2] = AL[i0 + 4];   al[f][3] = AL[i0 + 164];
            }
#pragma unroll
            for (int nf = 0; nf < 4; ++nf) {
                int bi = (step * 8 + (lane & 3)) * 136 + wn * 32 + nf * 8 + (lane >> 2);
                uint32_t bh0 = WH[bi], bh1 = WH[bi + 544];
                uint32_t bl0 = WL[bi], bl1 = WL[bi + 544];
#pragma unroll
                for (int f = 0; f < 4; ++f) {
                    mma16816(acc[f][nf], ah[f], bh0, bh1);
                    mma16816(acc[f][nf], ah[f], bl0, bl1);
                    mma16816(acc[f][nf], al[f], bh0, bh1);
                }
            }
        }
        __syncthreads();
    }

    float bc0[4], bc1[4];
#pragma unroll
    for (int nf = 0; nf < 4; ++nf) {
        int c = wn * 32 + nf * 8 + (lane & 3) * 2;
        bc0[nf] = bias_s[c];
        bc1[nf] = bias_s[c + 1];
    }
#pragma unroll
    for (int f = 0; f < 4; ++f) {
        int rl0 = wm * 64 + f * 16 + (lane >> 2);
        int rl1 = rl0 + 8;
        int r0 = row0 + rl0;
        int r1 = row0 + rl1;
#pragma unroll
        for (int nf = 0; nf < 4; ++nf) {
            int c = wn * 32 + nf * 8 + (lane & 3) * 2;
            float v0 = acc[f][nf][0] + bc0[nf];
            float v1 = acc[f][nf][1] + bc1[nf];
            float v2 = acc[f][nf][2] + bc0[nf];
            float v3 = acc[f][nf][3] + bc1[nf];
            if (MODE_EPI == E_RELU_F32) {
                float* CF = (float*)Cb;
                *(float2*)(&CF[(size_t)r0 * NF + c]) = make_float2(fmaxf(v0, 0.f), fmaxf(v1, 0.f));
                *(float2*)(&CF[(size_t)r1 * NF + c]) = make_float2(fmaxf(v2, 0.f), fmaxf(v3, 0.f));
            } else if (MODE_EPI == E_BASE) {
                float* CF = (float*)Cb;
                *(float2*)(&CF[(size_t)r0 * NF + c]) = make_float2(v0, v1);
                *(float2*)(&CF[(size_t)r1 * NF + c]) = make_float2(v2, v3);
            } else { // E_RESID / E_RESID0
                float* CF = (float*)Cb;
                float2 b0 = *(const float2*)(&base[(size_t)r0 * NF + c]);
                float2 b1 = *(const float2*)(&base[(size_t)r1 * NF + c]);
                float2 p0 = make_float2(0.f, 0.f), p1 = make_float2(0.f, 0.f);
                if (MODE_EPI == E_RESID) {
                    p0 = *(const float2*)(&CF[(size_t)r0 * NF + c]);
                    p1 = *(const float2*)(&CF[(size_t)r1 * NF + c]);
                }
                float a0 = fmaxf(v0 + b0.x + p0.x, 0.f);
                float a1 = fmaxf(v1 + b0.y + p0.y, 0.f);
                float a2 = fmaxf(v2 + b1.x + p1.x, 0.f);
                float a3 = fmaxf(v3 + b1.y + p1.y, 0.f);
                *(float2*)(&CF[(size_t)r0 * NF + c]) = make_float2(a0, a1);
                *(float2*)(&CF[(size_t)r1 * NF + c]) = make_float2(a2, a3);
                uint32_t h0 = packbf(a0, a1);
                uint32_t h1 = packbf(a2, a3);
                C2[(size_t)r0 * 128 + (c >> 1)] = h0;
                C2[(size_t)r1 * 128 + (c >> 1)] = h1;
                C2[(size_t)r0 * 128 + 64 + (c >> 1)] =
                    packbf(a0 - __uint_as_float(h0 << 16), a1 - __uint_as_float(h0 & 0xFFFF0000u));
                C2[(size_t)r1 * 128 + 64 + (c >> 1)] =
                    packbf(a2 - __uint_as_float(h1 << 16), a3 - __uint_as_float(h1 & 0xFFFF0000u));
            }
        }
    }
}

// ---------------- final predictor layer --------------------------------------
__global__ void pred_final_kernel(const float* __restrict__ X, const float* __restrict__ W,
                                  const float* __restrict__ bias, float* __restrict__ out)
{
    __shared__ float Ws[NF * DOUT];
    __shared__ float bs[DOUT];
    int tid = threadIdx.x;
    for (int i = tid; i < NF * DOUT; i += blockDim.x) Ws[i] = W[i];
    if (tid < DOUT) bs[tid] = bias[tid];
    __syncthreads();
    int p = blockIdx.x * blockDim.x + tid;
    float a0 = bs[0], a1 = bs[1], a2 = bs[2];
    const float4* xp = (const float4*)(X + (size_t)p * NF);
#pragma unroll
    for (int k4 = 0; k4 < NF / 4; ++k4) {
        float4 x = xp[k4];
        int k = k4 * 4;
        a0 += x.x * Ws[k * 3 + 0] + x.y * Ws[(k + 1) * 3 + 0] +
              x.z * Ws[(k + 2) * 3 + 0] + x.w * Ws[(k + 3) * 3 + 0];
        a1 += x.x * Ws[k * 3 + 1] + x.y * Ws[(k + 1) * 3 + 1] +
              x.z * Ws[(k + 2) * 3 + 1] + x.w * Ws[(k + 3) * 3 + 1];
        a2 += x.x * Ws[k * 3 + 2] + x.y * Ws[(k + 1) * 3 + 2] +
              x.z * Ws[(k + 2) * 3 + 2] + x.w * Ws[(k + 3) * 3 + 2];
    }
    out[p * 3 + 0] = a0;
    out[p * 3 + 1] = a1;
    out[p * 3 + 2] = a2;
}

// ---------------- host orchestration ----------------------------------------
extern "C" void kernel_launch(void* const* d_in, const int* in_sizes, int n_in,
                              void* d_out, int out_size)
{
    const float* state = (const float*)d_in[0];
    const float* Rr    = (const float*)d_in[1];
    const float* Rs    = (const float*)d_in[2];
    const float* Ra    = (const float*)d_in[3];
    const float* pe_w0 = (const float*)d_in[5],  *pe_b0 = (const float*)d_in[6];
    const float* pe_w1 = (const float*)d_in[7],  *pe_b1 = (const float*)d_in[8];
    const float* re_w0 = (const float*)d_in[9],  *re_b0 = (const float*)d_in[10];
    const float* re_w1 = (const float*)d_in[11], *re_b1 = (const float*)d_in[12];
    const float* re_w2 = (const float*)d_in[13], *re_b2 = (const float*)d_in[14];
    const float* rp_w  = (const float*)d_in[15], *rp_b  = (const float*)d_in[16];
    const float* pp_w  = (const float*)d_in[17], *pp_b  = (const float*)d_in[18];
    const float* pr_w0 = (const float*)d_in[19], *pr_b0 = (const float*)d_in[20];
    const float* pr_w1 = (const float*)d_in[21], *pr_b1 = (const float*)d_in[22];
    float* out = (float*)d_out;

    uint32_t *ptmpP, *peffP, *wh, *wl;
    float *relbase, *peffect, *pbase, *eagg, *pair;
    int *recv, *send, *cnt, *off, *pos, *list;
    cudaGetSymbolAddress((void**)&relbase, g_relbase);
    cudaGetSymbolAddress((void**)&ptmpP,   g_ptmpP);
    cudaGetSymbolAddress((void**)&peffP,   g_peffP);
    cudaGetSymbolAddress((void**)&peffect, g_peffect);
    cudaGetSymbolAddress((void**)&pbase,   g_pbase);
    cudaGetSymbolAddress((void**)&eagg,    g_eagg);
    cudaGetSymbolAddress((void**)&pair,    g_pair);
    cudaGetSymbolAddress((void**)&recv,    g_recv);
    cudaGetSymbolAddress((void**)&send,    g_send);
    cudaGetSymbolAddress((void**)&cnt,     g_cnt);
    cudaGetSymbolAddress((void**)&off,     g_off);
    cudaGetSymbolAddress((void**)&pos,     g_pos);
    cudaGetSymbolAddress((void**)&list,    g_list);
    cudaGetSymbolAddress((void**)&wh,      g_wh);
    cudaGetSymbolAddress((void**)&wl,      g_wl);

    cudaFuncSetAttribute(mma_gemm<A_BF,  E_BASE>,    cudaFuncAttributeMaxDynamicSharedMemorySize, SMEM_TOTAL_B);
    cudaFuncSetAttribute(mma_gemm<A_F32, E_RESID>,   cudaFuncAttributeMaxDynamicSharedMemorySize, SMEM_TOTAL_B);
    cudaFuncSetAttribute(mma_gemm<A_F32, E_RESID0>,  cudaFuncAttributeMaxDynamicSharedMemorySize, SMEM_TOTAL_B);
    cudaFuncSetAttribute(mma_gemm<A_BF,  E_RELU_F32>,cudaFuncAttributeMaxDynamicSharedMemorySize, SMEM_TOTAL_B);
    cudaFuncSetAttribute(relchain_kernel,  cudaFuncAttributeMaxDynamicSharedMemorySize, CH_TOTAL);
    cudaFuncSetAttribute(partall_kernel,   cudaFuncAttributeMaxDynamicSharedMemorySize, CH_TOTAL);

    float* P1 = pair;
    float* P2 = pair + (size_t)MPART * NF;
    const int WO_PPBOT = WO_PP + 8192;

    // 1) weights + cnt zero
    split_all_kernel<<<(WT_U32 + MPART + 255) / 256, 256>>>(
        pe_w0, pe_w1, re_w0, re_w1, re_w2, rp_w, pp_w, pr_w0, wh, wl, cnt);
    // 2) one-hot -> indices + CSR count (high-MLP scan)
    extract_idx_kernel<<<2048, 256>>>((const uint4*)Rr, (const uint4*)Rs, recv, send, cnt);
    // 3) CSR scan + fill
    csr_scan_kernel<<<1, 1024>>>(cnt, off, pos);
    csr_fill_kernel<<<MREL / 256, 256>>>(recv, pos, list);
    // 4) particle prep: Sr, Ss, pencode chain -> pbase
    partall_kernel<<<MPART / 128, 256, CH_TOTAL>>>(state, pe_b0, pe_b1, pp_b, wh, wl,
                                                   P1, P2, pbase);
    // 5) relation chain -> relbase
    relchain_kernel<<<MREL / 128, 256, CH_TOTAL>>>(
        P1, P2, Ra, re_w0 + 64 * 128, re_b0, re_b1, re_b2, rp_b, recv, send, wh, wl, relbase);
    // 6) propagation (first step uses E_RESID0 — no stale peffect read)
    agg_kernel<true><<<MPART / 2, 256>>>(relbase, nullptr, nullptr, send, off, list, eagg);
    mma_gemm<A_F32, E_RESID0><<<MPART / 128, 256, SMEM_TOTAL_B>>>(
        eagg, wh + WO_PPBOT, wl + WO_PPBOT, nullptr, peffect, pbase, peffP, 128, 4, 0, 0);
    for (int s = 1; s < PSTEPS; ++s) {
        dim3 g(MPART / 128, 2);
        mma_gemm<A_BF, E_BASE><<<g, 256, SMEM_TOTAL_B>>>(
            peffP, wh + WO_RPM, wl + WO_RPM, nullptr, pair, nullptr, nullptr,
            128, 4, 8192, (long long)MPART * NF * 4);
        agg_kernel<false><<<MPART / 2, 256>>>(relbase, P1, P2, send, off, list, eagg);
        mma_gemm<A_F32, E_RESID><<<MPART / 128, 256, SMEM_TOTAL_B>>>(
            eagg, wh + WO_PPBOT, wl + WO_PPBOT, nullptr, peffect, pbase, peffP, 128, 4, 0, 0);
    }
    // 7) predictor
    mma_gemm<A_BF, E_RELU_F32><<<MPART / 128, 256, SMEM_TOTAL_B>>>(
        peffP, wh + WO_PR0, wl + WO_PR0, pr_b0, ptmpP, nullptr, nullptr, 128, 4, 0, 0);
    pred_final_kernel<<<MPART / 256, 256>>>((const float*)ptmpP, pr_w1, pr_b1, out);
}

// round 16
// speedup vs baseline: 1.1165x; 1.0011x over previous
#include <cuda_runtime.h>
#include <cuda_bf16.h>
#include <cstdint>

#define BB    8
#define NN    1024
#define RR    8192
#define DIN   32
#define NF    128
#define DOUT  3
#define PSTEPS 3
#define MREL  (BB * RR)   // 65536
#define MPART (BB * NN)   // 8192

// ---------------- scratch (device globals) ----------------------------------
__device__ float    g_relbase[MREL * NF]; // 32 MB fp32
__device__ uint32_t g_ptmpP[MPART * NF];
__device__ uint32_t g_peffP[MPART * NF];
__device__ float    g_peffect[MPART * NF];
__device__ float    g_pbase[MPART * NF];
__device__ float    g_eagg[MPART * NF];
__device__ float    g_pair[2 * MPART * NF]; // Sr/Ss, later P1/P2
__device__ int      g_recv[MREL];
__device__ int      g_send[MREL];
__device__ int      g_cnt[MPART];
__device__ int      g_off[MPART + 1];
__device__ int      g_pos[MPART];
__device__ int      g_list[MREL];
// packed weights: [Kpad/2][128] u32 (bf16x2 of k,k+1 per col n), hi & lo planes
#define WT_U32 79872
__device__ uint32_t g_wh[WT_U32];
__device__ uint32_t g_wl[WT_U32];
#define WO_PE0  0       // Kpad 32
#define WO_PE1  2048    // 128
#define WO_RE1  10240   // 128
#define WO_RE2  18432   // 128
#define WO_RPT  26624   // 128 (rp_w rows 0-127)
#define WO_RPM  34816   // 128 (rows 128-255)
#define WO_RPB  43008   // 128 (rows 256-383)
#define WO_PP   51200   // 256 (top: k2 0-63, bot: +8192)
#define WO_PR0  67584   // 128
#define WO_REWR 75776   // 32 (re_w0 rows 0-31)
#define WO_REWS 77824   // 32 (re_w0 rows 32-63)

// ---------------- helpers ----------------------------------------------------
__device__ __forceinline__ uint32_t packbf(float vlo, float vhi) {
    uint32_t r;
    asm("cvt.rn.bf16x2.f32 %0, %1, %2;" : "=r"(r) : "f"(vhi), "f"(vlo));
    return r;
}
__device__ __forceinline__ void mma16816(float* d, const uint32_t* a, uint32_t b0, uint32_t b1) {
    asm volatile("mma.sync.aligned.m16n8k16.row.col.f32.bf16.bf16.f32 "
                 "{%0,%1,%2,%3}, {%4,%5,%6,%7}, {%8,%9}, {%0,%1,%2,%3};"
                 : "+f"(d[0]), "+f"(d[1]), "+f"(d[2]), "+f"(d[3])
                 : "r"(a[0]), "r"(a[1]), "r"(a[2]), "r"(a[3]), "r"(b0), "r"(b1));
}

// ---------------- index extraction + inline CSR count (high-MLP) -------------
__device__ __forceinline__ void proc_quad(uint4 v, long long idx,
                                          int* __restrict__ dst,
                                          int* __restrict__ cnt, bool do_cnt)
{
    if (v.x | v.y | v.z | v.w) {
        long long e = idx * 4;
        int b = (int)(e >> 23);
        int n = (int)((e >> 13) & (NN - 1));
        int r = (int)(e & (RR - 1));
        int* o = dst + b * RR + r;
        int nz = 0;
        if (v.x) { o[0] = n; ++nz; }
        if (v.y) { o[1] = n; ++nz; }
        if (v.z) { o[2] = n; ++nz; }
        if (v.w) { o[3] = n; ++nz; }
        if (do_cnt) atomicAdd(&cnt[(b << 10) + n], nz);
    }
}

__global__ void extract_idx_kernel(const uint4* __restrict__ Rr,
                                   const uint4* __restrict__ Rs,
                                   int* __restrict__ recv, int* __restrict__ send,
                                   int* __restrict__ cnt)
{
    const long long total  = (long long)BB * NN * RR / 4;          // 16M uint4
    const long long stride = (long long)gridDim.x * blockDim.x * 4;
    const int bd = blockDim.x;
    for (long long base = (long long)blockIdx.x * bd * 4 + threadIdx.x;
         base < total; base += stride) {
        uint4 a0 = __ldcs(Rr + base);
        uint4 a1 = __ldcs(Rr + base + bd);
        uint4 a2 = __ldcs(Rr + base + 2 * bd);
        uint4 a3 = __ldcs(Rr + base + 3 * bd);
        uint4 b0 = __ldcs(Rs + base);
        uint4 b1 = __ldcs(Rs + base + bd);
        uint4 b2 = __ldcs(Rs + base + 2 * bd);
        uint4 b3 = __ldcs(Rs + base + 3 * bd);
        proc_quad(a0, base,          recv, cnt, true);
        proc_quad(a1, base + bd,     recv, cnt, true);
        proc_quad(a2, base + 2 * bd, recv, cnt, true);
        proc_quad(a3, base + 3 * bd, recv, cnt, true);
        proc_quad(b0, base,          send, nullptr, false);
        proc_quad(b1, base + bd,     send, nullptr, false);
        proc_quad(b2, base + 2 * bd, send, nullptr, false);
        proc_quad(b3, base + 3 * bd, send, nullptr, false);
    }
}

// ---------------- CSR scan + fill --------------------------------------------
__global__ void csr_scan_kernel(const int* __restrict__ cnt,
                                int* __restrict__ off, int* __restrict__ pos) {
    __shared__ int part[1024];
    const int tid = threadIdx.x;
    int local[8];
    int s = 0;
#pragma unroll
    for (int j = 0; j < 8; ++j) { local[j] = s; s += cnt[tid * 8 + j]; }
    part[tid] = s;
    __syncthreads();
    for (int d = 1; d < 1024; d <<= 1) {
        int v = part[tid];
        if (tid >= d) v += part[tid - d];
        __syncthreads();
        part[tid] = v;
        __syncthreads();
    }
    int base = (tid == 0) ? 0 : part[tid - 1];
#pragma unroll
    for (int j = 0; j < 8; ++j) {
        int o = base + local[j];
        off[tid * 8 + j] = o;
        pos[tid * 8 + j] = o;
    }
    if (tid == 1023) off[MPART] = part[1023];
}
__global__ void csr_fill_kernel(const int* __restrict__ recv,
                                int* __restrict__ pos, int* __restrict__ list) {
    int r = blockIdx.x * blockDim.x + threadIdx.x;
    int p = ((r >> 13) << 10) + recv[r];
    int idx = atomicAdd(&pos[p], 1);
    list[idx] = r;
}

// ---------------- weights: transpose + split + pack (+ cnt zero) ------------
__global__ void split_all_kernel(const float* __restrict__ pe_w0, const float* __restrict__ pe_w1,
                                 const float* __restrict__ re_w0, const float* __restrict__ re_w1,
                                 const float* __restrict__ re_w2, const float* __restrict__ rp_w,
                                 const float* __restrict__ pp_w, const float* __restrict__ pr_w0,
                                 uint32_t* __restrict__ hi, uint32_t* __restrict__ lo,
                                 int* __restrict__ cnt)
{
    int idx = blockIdx.x * blockDim.x + threadIdx.x;
    if (idx >= WT_U32) {
        int z = idx - WT_U32;
        if (z < MPART) cnt[z] = 0;
        return;
    }
    const float* w; int K, local;
    if      (idx < 2048)  { w = pe_w0;              K = 32;  local = idx; }
    else if (idx < 10240) { w = pe_w1;              K = 128; local = idx - 2048; }
    else if (idx < 18432) { w = re_w1;              K = 128; local = idx - 10240; }
    else if (idx < 26624) { w = re_w2;              K = 128; local = idx - 18432; }
    else if (idx < 34816) { w = rp_w;               K = 128; local = idx - 26624; }
    else if (idx < 43008) { w = rp_w + 128 * 128;   K = 128; local = idx - 34816; }
    else if (idx < 51200) { w = rp_w + 256 * 128;   K = 128; local = idx - 43008; }
    else if (idx < 67584) { w = pp_w;               K = 256; local = idx - 51200; }
    else if (idx < 75776) { w = pr_w0;              K = 128; local = idx - 67584; }
    else if (idx < 77824) { w = re_w0;              K = 32;  local = idx - 75776; }
    else                  { w = re_w0 + 32 * 128;   K = 32;  local = idx - 77824; }
    int k2 = local >> 7, n = local & 127;
    int k0 = 2 * k2;
    float v0 = (k0 < K)     ? w[(size_t)k0 * 128 + n]       : 0.f;
    float v1 = (k0 + 1 < K) ? w[(size_t)(k0 + 1) * 128 + n] : 0.f;
    uint32_t h = packbf(v0, v1);
    float h0 = __uint_as_float(h << 16);
    float h1 = __uint_as_float(h & 0xFFFF0000u);
    hi[idx] = h;
    lo[idx] = packbf(v0 - h0, v1 - h1);
}

// -------- CSR gather-reduce aggregation (atomic-free, 4-way unrolled) --------
template<bool FIRST>
__global__ __launch_bounds__(256, 8)
void agg_kernel(const float* __restrict__ relbase,
                const float* __restrict__ P1, const float* __restrict__ P2,
                const int* __restrict__ send,
                const int* __restrict__ off, const int* __restrict__ list,
                float* __restrict__ eagg)
{
    const int p = blockIdx.x * 2 + (threadIdx.x >> 7);
    const int c = threadIdx.x & 127;
    const int beg = off[p], end = off[p + 1];
    float p1c = FIRST ? 0.f : P1[(size_t)p * NF + c];
    float acc = 0.f;
    int i = beg;
    for (; i + 4 <= end; i += 4) {
        int r0 = list[i];
        int r1 = list[i + 1];
        int r2 = list[i + 2];
        int r3 = list[i + 3];
        float v0 = relbase[(size_t)r0 * NF + c];
        float v1 = relbase[(size_t)r1 * NF + c];
        float v2 = relbase[(size_t)r2 * NF + c];
        float v3 = relbase[(size_t)r3 * NF + c];
        if (!FIRST) {
            int gs0 = ((r0 >> 13) << 10) + send[r0];
            int gs1 = ((r1 >> 13) << 10) + send[r1];
            int gs2 = ((r2 >> 13) << 10) + send[r2];
            int gs3 = ((r3 >> 13) << 10) + send[r3];
            v0 += P2[(size_t)gs0 * NF + c];
            v1 += P2[(size_t)gs1 * NF + c];
            v2 += P2[(size_t)gs2 * NF + c];
            v3 += P2[(size_t)gs3 * NF + c];
        }
        acc += fmaxf(v0 + p1c, 0.f);
        acc += fmaxf(v1 + p1c, 0.f);
        acc += fmaxf(v2 + p1c, 0.f);
        acc += fmaxf(v3 + p1c, 0.f);
    }
    for (; i + 2 <= end; i += 2) {
        int r0 = list[i];
        int r1 = list[i + 1];
        float v0 = relbase[(size_t)r0 * NF + c];
        float v1 = relbase[(size_t)r1 * NF + c];
        if (!FIRST) {
            int gs0 = ((r0 >> 13) << 10) + send[r0];
            int gs1 = ((r1 >> 13) << 10) + send[r1];
            v0 += P2[(size_t)gs0 * NF + c];
            v1 += P2[(size_t)gs1 * NF + c];
        }
        acc += fmaxf(v0 + p1c, 0.f);
        acc += fmaxf(v1 + p1c, 0.f);
    }
    if (i < end) {
        int r = list[i];
        float v = relbase[(size_t)r * NF + c] + p1c;
        if (!FIRST) {
            int gs = ((r >> 13) << 10) + send[r];
            v += P2[(size_t)gs * NF + c];
        }
        acc += fmaxf(v, 0.f);
    }
    eagg[(size_t)p * NF + c] = acc;
}

// ================== chained multi-layer GEMM machinery (R12-validated) =======
#define CH_WA   0
#define CH_B0   512
#define CH_BA   1024
#define CH_BB   1536
#define CH_BC   2048
#define CH_AHI  2560                        // chained A hi plane: 128 rows x 68 u32
#define CH_ALO  (CH_AHI + 34816)            // 37376
#define CH_WBASE (CH_ALO + 34816)           // 72192
#define CH_WHI(s) (CH_WBASE + (s) * 8704)
#define CH_WLO(s) (CH_WBASE + 17408 + (s) * 8704)
#define CH_TOTAL (CH_WBASE + 34816)         // 107008

__device__ __forceinline__ void ch_fill_w(char* smem, int s, int kt,
    const uint32_t* __restrict__ Whp, const uint32_t* __restrict__ Wlp, int tid)
{
    const int k2 = tid >> 4;
    const int nn = (tid & 15) * 8;
    const size_t gi = (size_t)(kt * 16 + k2) * 128 + nn;
    uint4 h0 = *(const uint4*)(Whp + gi);
    uint4 h1 = *(const uint4*)(Whp + gi + 4);
    uint4 l0 = *(const uint4*)(Wlp + gi);
    uint4 l1 = *(const uint4*)(Wlp + gi + 4);
    char* wb = smem + CH_WHI(s) + k2 * 544 + nn * 4;
    ((uint4*)wb)[0] = h0; ((uint4*)wb)[1] = h1;
    char* lb = smem + CH_WLO(s) + k2 * 544 + nn * 4;
    ((uint4*)lb)[0] = l0; ((uint4*)lb)[1] = l1;
}

__device__ __forceinline__ void ch_compute(char* smem, int kt, int s,
    int wm, int wn, int lane, float (&acc)[4][4][4])
{
    const uint32_t* AH = (const uint32_t*)(smem + CH_AHI);
    const uint32_t* AL = (const uint32_t*)(smem + CH_ALO);
    const uint32_t* WH = (const uint32_t*)(smem + CH_WHI(s));
    const uint32_t* WL = (const uint32_t*)(smem + CH_WLO(s));
#pragma unroll
    for (int step = 0; step < 2; ++step) {
        uint32_t ah[4][4], al[4][4];
#pragma unroll
        for (int f = 0; f < 4; ++f) {
            int r = wm * 64 + f * 16 + (lane >> 2);
            int i0 = r * 68 + kt * 16 + (lane & 3) + step * 8;
            ah[f][0] = AH[i0];       ah[f][1] = AH[i0 + 544];
            ah[f][2] = AH[i0 + 4];   ah[f][3] = AH[i0 + 548];
            al[f][0] = AL[i0];       al[f][1] = AL[i0 + 544];
            al[f][2] = AL[i0 + 4];   al[f][3] = AL[i0 + 548];
        }
#pragma unroll
        for (int nf = 0; nf < 4; ++nf) {
            int bi = (step * 8 + (lane & 3)) * 136 + wn * 32 + nf * 8 + (lane >> 2);
            uint32_t bh0 = WH[bi], bh1 = WH[bi + 544];
            uint32_t bl0 = WL[bi], bl1 = WL[bi + 544];
#pragma unroll
            for (int f = 0; f < 4; ++f) {
                mma16816(acc[f][nf], ah[f], bh0, bh1);
                mma16816(acc[f][nf], ah[f], bl0, bl1);
                mma16816(acc[f][nf], al[f], bh0, bh1);
            }
        }
    }
}

__device__ __forceinline__ void ch_gemm_layer(char* smem,
    const uint32_t* __restrict__ Whp, const uint32_t* __restrict__ Wlp, int nchunk,
    int wm, int wn, int lane, int tid, float (&acc)[4][4][4])
{
#pragma unroll
    for (int f = 0; f < 4; ++f)
#pragma unroll
        for (int nf = 0; nf < 4; ++nf)
#pragma unroll
            for (int j = 0; j < 4; ++j) acc[f][nf][j] = 0.f;
    ch_fill_w(smem, 0, 0, Whp, Wlp, tid);
    __syncthreads();
    for (int kt = 0; kt < nchunk; ++kt) {
        int s = kt & 1;
        if (kt + 1 < nchunk) ch_fill_w(smem, s ^ 1, kt + 1, Whp, Wlp, tid);
        ch_compute(smem, kt, s, wm, wn, lane, acc);
        __syncthreads();
    }
}

__device__ __forceinline__ void ch_epi_planes(char* smem, const float* bias_s,
    int wm, int wn, int lane, float (&acc)[4][4][4])
{
    uint32_t* AH = (uint32_t*)(smem + CH_AHI);
    uint32_t* AL = (uint32_t*)(smem + CH_ALO);
#pragma unroll
    for (int f = 0; f < 4; ++f) {
        int r0 = wm * 64 + f * 16 + (lane >> 2);
        int r1 = r0 + 8;
#pragma unroll
        for (int nf = 0; nf < 4; ++nf) {
            int c = wn * 32 + nf * 8 + (lane & 3) * 2;
            int c2 = c >> 1;
            float a0 = fmaxf(acc[f][nf][0] + bias_s[c], 0.f);
            float a1 = fmaxf(acc[f][nf][1] + bias_s[c + 1], 0.f);
            float a2 = fmaxf(acc[f][nf][2] + bias_s[c], 0.f);
            float a3 = fmaxf(acc[f][nf][3] + bias_s[c + 1], 0.f);
            uint32_t h0 = packbf(a0, a1), h1 = packbf(a2, a3);
            AH[r0 * 68 + c2] = h0;
            AH[r1 * 68 + c2] = h1;
            AL[r0 * 68 + c2] = packbf(a0 - __uint_as_float(h0 << 16), a1 - __uint_as_float(h0 & 0xFFFF0000u));
            AL[r1 * 68 + c2] = packbf(a2 - __uint_as_float(h1 << 16), a3 - __uint_as_float(h1 & 0xFFFF0000u));
        }
    }
}

__device__ __forceinline__ void ch_write_f32(float* dst, int row0, const float* bias_s,
    int wm, int wn, int lane, float (&acc)[4][4][4])
{
#pragma unroll
    for (int f = 0; f < 4; ++f) {
        int r0 = wm * 64 + f * 16 + (lane >> 2), r1 = r0 + 8;
#pragma unroll
        for (int nf = 0; nf < 4; ++nf) {
            int c = wn * 32 + nf * 8 + (lane & 3) * 2;
            float b0 = bias_s ? bias_s[c] : 0.f;
            float b1 = bias_s ? bias_s[c + 1] : 0.f;
            *(float2*)(dst + (size_t)(row0 + r0) * 128 + c) =
                make_float2(acc[f][nf][0] + b0, acc[f][nf][1] + b1);
            *(float2*)(dst + (size_t)(row0 + r1) * 128 + c) =
                make_float2(acc[f][nf][2] + b0, acc[f][nf][3] + b1);
        }
    }
}

// ---- fused relation chain: gather-combine -> re1 -> re2 -> relbase ----------
__global__ __launch_bounds__(256, 2)
void relchain_kernel(const float* __restrict__ Sr, const float* __restrict__ Ss,
                     const float* __restrict__ Ra,
                     const float* __restrict__ wa, const float* __restrict__ b0,
                     const float* __restrict__ b1, const float* __restrict__ b2,
                     const float* __restrict__ brp,
                     const int* __restrict__ recv, const int* __restrict__ send,
                     const uint32_t* __restrict__ wh, const uint32_t* __restrict__ wl,
                     float* __restrict__ relbase)
{
    extern __shared__ char smem[];
    const int tid = threadIdx.x, lane = tid & 31, wid = tid >> 5;
    const int wm = wid & 1, wn = wid >> 1;
    const int row0 = blockIdx.x * 128;
    float* wa_s = (float*)(smem + CH_WA);
    float* b0_s = (float*)(smem + CH_B0);
    float* bA_s = (float*)(smem + CH_BA);
    float* bB_s = (float*)(smem + CH_BB);
    float* bC_s = (float*)(smem + CH_BC);
    if (tid < 128) {
        wa_s[tid] = wa[tid]; b0_s[tid] = b0[tid];
        bA_s[tid] = b1[tid]; bB_s[tid] = b2[tid]; bC_s[tid] = brp[tid];
    }
    const int row = tid >> 1, half = tid & 1, grow = row0 + row, bb = grow >> 13;
    const float ra = Ra[grow];
    const int rv = (bb << 10) + recv[grow];
    const int sd = (bb << 10) + send[grow];
    const float4* pr = (const float4*)(Sr + (size_t)rv * 128 + half * 64);
    const float4* ps = (const float4*)(Ss + (size_t)sd * 128 + half * 64);
    __syncthreads();
    {
        uint32_t* AH = (uint32_t*)(smem + CH_AHI) + row * 68 + half * 32;
        uint32_t* AL = (uint32_t*)(smem + CH_ALO) + row * 68 + half * 32;
#pragma unroll
        for (int j = 0; j < 16; ++j) {
            float4 u = pr[j], v = ps[j];
            int c = half * 64 + j * 4;
            float a0 = fmaxf(u.x + v.x + ra * wa_s[c]     + b0_s[c],     0.f);
            float a1 = fmaxf(u.y + v.y + ra * wa_s[c + 1] + b0_s[c + 1], 0.f);
            float a2 = fmaxf(u.z + v.z + ra * wa_s[c + 2] + b0_s[c + 2], 0.f);
            float a3 = fmaxf(u.w + v.w + ra * wa_s[c + 3] + b0_s[c + 3], 0.f);
            uint32_t h0 = packbf(a0, a1), h1 = packbf(a2, a3);
            AH[2 * j] = h0; AH[2 * j + 1] = h1;
            AL[2 * j] = packbf(a0 - __uint_as_float(h0 << 16), a1 - __uint_as_float(h0 & 0xFFFF0000u));
            AL[2 * j + 1] = packbf(a2 - __uint_as_float(h1 << 16), a3 - __uint_as_float(h1 & 0xFFFF0000u));
        }
    }
    float acc[4][4][4];
    ch_gemm_layer(smem, wh + WO_RE1, wl + WO_RE1, 4, wm, wn, lane, tid, acc);
    ch_epi_planes(smem, bA_s, wm, wn, lane, acc);
    ch_gemm_layer(smem, wh + WO_RE2, wl + WO_RE2, 4, wm, wn, lane, tid, acc);
    ch_epi_planes(smem, bB_s, wm, wn, lane, acc);
    ch_gemm_layer(smem, wh + WO_RPT, wl + WO_RPT, 4, wm, wn, lane, tid, acc);
    ch_write_f32(relbase, row0, bC_s, wm, wn, lane, acc);
}

// ---- fused particle prep: Sr, Ss, pe0 -> pe1 -> pbase -----------------------
__global__ __launch_bounds__(256, 2)
void partall_kernel(const float* __restrict__ state,
                    const float* __restrict__ pe_b0, const float* __restrict__ pe_b1,
                    const float* __restrict__ pp_b,
                    const uint32_t* __restrict__ wh, const uint32_t* __restrict__ wl,
                    float* __restrict__ Sr, float* __restrict__ Ss,
                    float* __restrict__ pbase)
{
    extern __shared__ char smem[];
    const int tid = threadIdx.x, lane = tid & 31, wid = tid >> 5;
    const int wm = wid & 1, wn = wid >> 1;
    const int row0 = blockIdx.x * 128;
    float* bA_s = (float*)(smem + CH_BA);
    float* bB_s = (float*)(smem + CH_BB);
    float* bC_s = (float*)(smem + CH_BC);
    if (tid < 128) { bA_s[tid] = pe_b0[tid]; bB_s[tid] = pe_b1[tid]; bC_s[tid] = pp_b[tid]; }
    {
        const int row = tid >> 1, half = tid & 1, grow = row0 + row;
        const float4* q = (const float4*)(state + (size_t)grow * 32 + half * 16);
        float x[16];
#pragma unroll
        for (int j = 0; j < 4; ++j) {
            float4 u = q[j];
            x[4 * j] = u.x; x[4 * j + 1] = u.y; x[4 * j + 2] = u.z; x[4 * j + 3] = u.w;
        }
        uint32_t* AH = (uint32_t*)(smem + CH_AHI) + row * 68 + half * 8;
        uint32_t* AL = (uint32_t*)(smem + CH_ALO) + row * 68 + half * 8;
#pragma unroll
        for (int j = 0; j < 8; ++j) {
            uint32_t h = packbf(x[2 * j], x[2 * j + 1]);
            AH[j] = h;
            AL[j] = packbf(x[2 * j] - __uint_as_float(h << 16),
                           x[2 * j + 1] - __uint_as_float(h & 0xFFFF0000u));
        }
    }
    float acc[4][4][4];
    ch_gemm_layer(smem, wh + WO_REWR, wl + WO_REWR, 1, wm, wn, lane, tid, acc);
    ch_write_f32(Sr, row0, nullptr, wm, wn, lane, acc);
    ch_gemm_layer(smem, wh + WO_REWS, wl + WO_REWS, 1, wm, wn, lane, tid, acc);
    ch_write_f32(Ss, row0, nullptr, wm, wn, lane, acc);
    ch_gemm_layer(smem, wh + WO_PE0, wl + WO_PE0, 1, wm, wn, lane, tid, acc);
    ch_epi_planes(smem, bA_s, wm, wn, lane, acc);
    ch_gemm_layer(smem, wh + WO_PE1, wl + WO_PE1, 4, wm, wn, lane, tid, acc);
    ch_epi_planes(smem, bB_s, wm, wn, lane, acc);
    ch_gemm_layer(smem, wh + WO_PP, wl + WO_PP, 4, wm, wn, lane, tid, acc);
    ch_write_f32(pbase, row0, bC_s, wm, wn, lane, acc);
}

// ---------------- generic fused mma.sync GEMM (R12-validated) ----------------
enum { A_F32 = 0, A_BF = 1 };
enum { E_RELU_F32 = 0, E_BASE = 2, E_RESID = 3, E_RESID0 = 4 };

#define SM_BIAS 0
#define SM_A    1536
#define AHI_OFF(s) (SM_A + (s) * 10240)
#define ALO_OFF(s) (SM_A + 20480 + (s) * 10240)
#define SM_W    (SM_A + 40960)
#define WHI_OFF(s) (SM_W + (s) * 8704)
#define WLO_OFF(s) (SM_W + 17408 + (s) * 8704)
#define SMEM_TOTAL_B (SM_W + 34816)   // 77312 bytes

template<int MODE_A>
__device__ __forceinline__ void fill_tile(
    char* smem, int s, int kt,
    const void* __restrict__ Av,
    const uint32_t* __restrict__ Whp, const uint32_t* __restrict__ Wlp,
    int row0, int K, int tid)
{
    const int row   = tid >> 1;
    const int half  = tid & 1;
    const int kbase = kt * 32 + half * 16;
    const int grow  = row0 + row;

    uint4 hA0, hA1, lA0, lA1;

    if (MODE_A == A_BF) {
        const uint32_t* Xp = (const uint32_t*)Av + (size_t)grow * 128;
        int k2 = kbase >> 1;
        hA0 = *(const uint4*)(Xp + k2);
        hA1 = *(const uint4*)(Xp + k2 + 4);
        lA0 = *(const uint4*)(Xp + 64 + k2);
        lA1 = *(const uint4*)(Xp + 64 + k2 + 4);
    } else {
        float x[16];
        if (kbase < K) {
            const float4* q = (const float4*)((const float*)Av + (size_t)grow * K + kbase);
#pragma unroll
            for (int j = 0; j < 4; ++j) {
                float4 u = q[j];
                x[4 * j] = u.x; x[4 * j + 1] = u.y; x[4 * j + 2] = u.z; x[4 * j + 3] = u.w;
            }
        } else {
#pragma unroll
            for (int j = 0; j < 16; ++j) x[j] = 0.f;
        }
        uint32_t hi[8], lo[8];
#pragma unroll
        for (int j = 0; j < 8; ++j) {
            uint32_t h = packbf(x[2 * j], x[2 * j + 1]);
            hi[j] = h;
            float h0 = __uint_as_float(h << 16);
            float h1 = __uint_as_float(h & 0xFFFF0000u);
            lo[j] = packbf(x[2 * j] - h0, x[2 * j + 1] - h1);
        }
        hA0 = make_uint4(hi[0], hi[1], hi[2], hi[3]);
        hA1 = make_uint4(hi[4], hi[5], hi[6], hi[7]);
        lA0 = make_uint4(lo[0], lo[1], lo[2], lo[3]);
        lA1 = make_uint4(lo[4], lo[5], lo[6], lo[7]);
    }
    {
        uint4* dh = (uint4*)(smem + AHI_OFF(s) + row * 80 + half * 32);
        dh[0] = hA0; dh[1] = hA1;
        uint4* dl = (uint4*)(smem + ALO_OFF(s) + row * 80 + half * 32);
        dl[0] = lA0; dl[1] = lA1;
    }
    {
        const int k2 = tid >> 4;
        const int nn = (tid & 15) * 8;
        const size_t gi = (size_t)(kt * 16 + k2) * 128 + nn;
        uint4 h0 = *(const uint4*)(Whp + gi);
        uint4 h1 = *(const uint4*)(Whp + gi + 4);
        uint4 l0 = *(const uint4*)(Wlp + gi);
        uint4 l1 = *(const uint4*)(Wlp + gi + 4);
        char* wb = smem + WHI_OFF(s) + k2 * 544 + nn * 4;
        ((uint4*)wb)[0] = h0; ((uint4*)wb)[1] = h1;
        char* lb = smem + WLO_OFF(s) + k2 * 544 + nn * 4;
        ((uint4*)lb)[0] = l0; ((uint4*)lb)[1] = l1;
    }
}

template<int MODE_A, int MODE_EPI>
__global__ __launch_bounds__(256, 2)
void mma_gemm(const void* __restrict__ Av,
              const uint32_t* __restrict__ Whp, const uint32_t* __restrict__ Wlp,
              const float* __restrict__ bias, void* __restrict__ Cv,
              const float* __restrict__ base,
              uint32_t* __restrict__ C2,
              int K, int nchunk, int wstride, long long cstrideB)
{
    extern __shared__ char smem[];
    const int tid  = threadIdx.x;
    const int wid  = tid >> 5;
    const int lane = tid & 31;
    const int row0 = blockIdx.x * 128;
    const int wm = wid & 1;
    const int wn = wid >> 1;

    Whp += (size_t)blockIdx.y * wstride;
    Wlp += (size_t)blockIdx.y * wstride;
    char* Cb = (char*)Cv + (size_t)blockIdx.y * cstrideB;

    float* bias_s = (float*)(smem + SM_BIAS);
    if (tid < 128) bias_s[tid] = bias ? bias[tid] : 0.f;
    __syncthreads();

    float acc[4][4][4];
#pragma unroll
    for (int f = 0; f < 4; ++f)
#pragma unroll
        for (int nf = 0; nf < 4; ++nf)
#pragma unroll
            for (int j = 0; j < 4; ++j) acc[f][nf][j] = 0.f;

    fill_tile<MODE_A>(smem, 0, 0, Av, Whp, Wlp, row0, K, tid);
    __syncthreads();

    for (int kt = 0; kt < nchunk; ++kt) {
        const int s = kt & 1;
        if (kt + 1 < nchunk)
            fill_tile<MODE_A>(smem, s ^ 1, kt + 1, Av, Whp, Wlp, row0, K, tid);

        const uint32_t* AH = (const uint32_t*)(smem + AHI_OFF(s));
        const uint32_t* AL = (const uint32_t*)(smem + ALO_OFF(s));
        const uint32_t* WH = (const uint32_t*)(smem + WHI_OFF(s));
        const uint32_t* WL = (const uint32_t*)(smem + WLO_OFF(s));

#pragma unroll
        for (int step = 0; step < 2; ++step) {
            uint32_t ah[4][4], al[4][4];
#pragma unroll
            for (int f = 0; f < 4; ++f) {
                int r = wm * 64 + f * 16 + (lane >> 2);
                int i0 = r * 20 + (lane & 3) + step * 8;
                ah[f][0] = AH[i0];       ah[f][1] = AH[i0 + 160];
                ah[f][2] = AH[i0 + 4];   ah[f][3] = AH[i0 + 164];
                al[f][0] = AL[i0];       al[f][1] = AL[i0 + 160];
                al[f][2] = AL[i0 + 4];   al[f][3] = AL[i0 + 164];
            }
#pragma unroll
            for (int nf = 0; nf < 4; ++nf) {
                int bi = (step * 8 + (lane & 3)) * 136 + wn * 32 + nf * 8 + (lane >> 2);
                uint32_t bh0 = WH[bi], bh1 = WH[bi + 544];
                uint32_t bl0 = WL[bi], bl1 = WL[bi + 544];
#pragma unroll
                for (int f = 0; f < 4; ++f) {
                    mma16816(acc[f][nf], ah[f], bh0, bh1);
                    mma16816(acc[f][nf], ah[f], bl0, bl1);
                    mma16816(acc[f][nf], al[f], bh0, bh1);
                }
            }
        }
        __syncthreads();
    }

    float bc0[4], bc1[4];
#pragma unroll
    for (int nf = 0; nf < 4; ++nf) {
        int c = wn * 32 + nf * 8 + (lane & 3) * 2;
        bc0[nf] = bias_s[c];
        bc1[nf] = bias_s[c + 1];
    }
#pragma unroll
    for (int f = 0; f < 4; ++f) {
        int rl0 = wm * 64 + f * 16 + (lane >> 2);
        int rl1 = rl0 + 8;
        int r0 = row0 + rl0;
        int r1 = row0 + rl1;
#pragma unroll
        for (int nf = 0; nf < 4; ++nf) {
            int c = wn * 32 + nf * 8 + (lane & 3) * 2;
            float v0 = acc[f][nf][0] + bc0[nf];
            float v1 = acc[f][nf][1] + bc1[nf];
            float v2 = acc[f][nf][2] + bc0[nf];
            float v3 = acc[f][nf][3] + bc1[nf];
            if (MODE_EPI == E_RELU_F32) {
                float* CF = (float*)Cb;
                *(float2*)(&CF[(size_t)r0 * NF + c]) = make_float2(fmaxf(v0, 0.f), fmaxf(v1, 0.f));
                *(float2*)(&CF[(size_t)r1 * NF + c]) = make_float2(fmaxf(v2, 0.f), fmaxf(v3, 0.f));
            } else if (MODE_EPI == E_BASE) {
                float* CF = (float*)Cb;
                *(float2*)(&CF[(size_t)r0 * NF + c]) = make_float2(v0, v1);
                *(float2*)(&CF[(size_t)r1 * NF + c]) = make_float2(v2, v3);
            } else { // E_RESID / E_RESID0
                float* CF = (float*)Cb;
                float2 b0 = *(const float2*)(&base[(size_t)r0 * NF + c]);
                float2 b1 = *(const float2*)(&base[(size_t)r1 * NF + c]);
                float2 p0 = make_float2(0.f, 0.f), p1 = make_float2(0.f, 0.f);
                if (MODE_EPI == E_RESID) {
                    p0 = *(const float2*)(&CF[(size_t)r0 * NF + c]);
                    p1 = *(const float2*)(&CF[(size_t)r1 * NF + c]);
                }
                float a0 = fmaxf(v0 + b0.x + p0.x, 0.f);
                float a1 = fmaxf(v1 + b0.y + p0.y, 0.f);
                float a2 = fmaxf(v2 + b1.x + p1.x, 0.f);
                float a3 = fmaxf(v3 + b1.y + p1.y, 0.f);
                *(float2*)(&CF[(size_t)r0 * NF + c]) = make_float2(a0, a1);
                *(float2*)(&CF[(size_t)r1 * NF + c]) = make_float2(a2, a3);
                uint32_t h0 = packbf(a0, a1);
                uint32_t h1 = packbf(a2, a3);
                C2[(size_t)r0 * 128 + (c >> 1)] = h0;
                C2[(size_t)r1 * 128 + (c >> 1)] = h1;
                C2[(size_t)r0 * 128 + 64 + (c >> 1)] =
                    packbf(a0 - __uint_as_float(h0 << 16), a1 - __uint_as_float(h0 & 0xFFFF0000u));
                C2[(size_t)r1 * 128 + 64 + (c >> 1)] =
                    packbf(a2 - __uint_as_float(h1 << 16), a3 - __uint_as_float(h1 & 0xFFFF0000u));
            }
        }
    }
}

// ---------------- final predictor layer --------------------------------------
__global__ void pred_final_kernel(const float* __restrict__ X, const float* __restrict__ W,
                                  const float* __restrict__ bias, float* __restrict__ out)
{
    __shared__ float Ws[NF * DOUT];
    __shared__ float bs[DOUT];
    int tid = threadIdx.x;
    for (int i = tid; i < NF * DOUT; i += blockDim.x) Ws[i] = W[i];
    if (tid < DOUT) bs[tid] = bias[tid];
    __syncthreads();
    int p = blockIdx.x * blockDim.x + tid;
    float a0 = bs[0], a1 = bs[1], a2 = bs[2];
    const float4* xp = (const float4*)(X + (size_t)p * NF);
#pragma unroll
    for (int k4 = 0; k4 < NF / 4; ++k4) {
        float4 x = xp[k4];
        int k = k4 * 4;
        a0 += x.x * Ws[k * 3 + 0] + x.y * Ws[(k + 1) * 3 + 0] +
              x.z * Ws[(k + 2) * 3 + 0] + x.w * Ws[(k + 3) * 3 + 0];
        a1 += x.x * Ws[k * 3 + 1] + x.y * Ws[(k + 1) * 3 + 1] +
              x.z * Ws[(k + 2) * 3 + 1] + x.w * Ws[(k + 3) * 3 + 1];
        a2 += x.x * Ws[k * 3 + 2] + x.y * Ws[(k + 1) * 3 + 2] +
              x.z * Ws[(k + 2) * 3 + 2] + x.w * Ws[(k + 3) * 3 + 2];
    }
    out[p * 3 + 0] = a0;
    out[p * 3 + 1] = a1;
    out[p * 3 + 2] = a2;
}

// ---------------- host orchestration ----------------------------------------
extern "C" void kernel_launch(void* const* d_in, const int* in_sizes, int n_in,
                              void* d_out, int out_size)
{
    const float* state = (const float*)d_in[0];
    const float* Rr    = (const float*)d_in[1];
    const float* Rs    = (const float*)d_in[2];
    const float* Ra    = (const float*)d_in[3];
    const float* pe_w0 = (const float*)d_in[5],  *pe_b0 = (const float*)d_in[6];
    const float* pe_w1 = (const float*)d_in[7],  *pe_b1 = (const float*)d_in[8];
    const float* re_w0 = (const float*)d_in[9],  *re_b0 = (const float*)d_in[10];
    const float* re_w1 = (const float*)d_in[11], *re_b1 = (const float*)d_in[12];
    const float* re_w2 = (const float*)d_in[13], *re_b2 = (const float*)d_in[14];
    const float* rp_w  = (const float*)d_in[15], *rp_b  = (const float*)d_in[16];
    const float* pp_w  = (const float*)d_in[17], *pp_b  = (const float*)d_in[18];
    const float* pr_w0 = (const float*)d_in[19], *pr_b0 = (const float*)d_in[20];
    const float* pr_w1 = (const float*)d_in[21], *pr_b1 = (const float*)d_in[22];
    float* out = (float*)d_out;

    uint32_t *ptmpP, *peffP, *wh, *wl;
    float *relbase, *peffect, *pbase, *eagg, *pair;
    int *recv, *send, *cnt, *off, *pos, *list;
    cudaGetSymbolAddress((void**)&relbase, g_relbase);
    cudaGetSymbolAddress((void**)&ptmpP,   g_ptmpP);
    cudaGetSymbolAddress((void**)&peffP,   g_peffP);
    cudaGetSymbolAddress((void**)&peffect, g_peffect);
    cudaGetSymbolAddress((void**)&pbase,   g_pbase);
    cudaGetSymbolAddress((void**)&eagg,    g_eagg);
    cudaGetSymbolAddress((void**)&pair,    g_pair);
    cudaGetSymbolAddress((void**)&recv,    g_recv);
    cudaGetSymbolAddress((void**)&send,    g_send);
    cudaGetSymbolAddress((void**)&cnt,     g_cnt);
    cudaGetSymbolAddress((void**)&off,     g_off);
    cudaGetSymbolAddress((void**)&pos,     g_pos);
    cudaGetSymbolAddress((void**)&list,    g_list);
    cudaGetSymbolAddress((void**)&wh,      g_wh);
    cudaGetSymbolAddress((void**)&wl,      g_wl);

    cudaFuncSetAttribute(mma_gemm<A_BF,  E_BASE>,    cudaFuncAttributeMaxDynamicSharedMemorySize, SMEM_TOTAL_B);
    cudaFuncSetAttribute(mma_gemm<A_F32, E_RESID>,   cudaFuncAttributeMaxDynamicSharedMemorySize, SMEM_TOTAL_B);
    cudaFuncSetAttribute(mma_gemm<A_F32, E_RESID0>,  cudaFuncAttributeMaxDynamicSharedMemorySize, SMEM_TOTAL_B);
    cudaFuncSetAttribute(mma_gemm<A_BF,  E_RELU_F32>,cudaFuncAttributeMaxDynamicSharedMemorySize, SMEM_TOTAL_B);
    cudaFuncSetAttribute(relchain_kernel,  cudaFuncAttributeMaxDynamicSharedMemorySize, CH_TOTAL);
    cudaFuncSetAttribute(partall_kernel,   cudaFuncAttributeMaxDynamicSharedMemorySize, CH_TOTAL);

    float* P1 = pair;
    float* P2 = pair + (size_t)MPART * NF;
    const int WO_PPBOT = WO_PP + 8192;

    // 1) weights + cnt zero
    split_all_kernel<<<(WT_U32 + MPART + 255) / 256, 256>>>(
        pe_w0, pe_w1, re_w0, re_w1, re_w2, rp_w, pp_w, pr_w0, wh, wl, cnt);
    // 2) one-hot -> indices + CSR count (high-MLP scan)
    extract_idx_kernel<<<2048, 256>>>((const uint4*)Rr, (const uint4*)Rs, recv, send, cnt);
    // 3) CSR scan + fill
    csr_scan_kernel<<<1, 1024>>>(cnt, off, pos);
    csr_fill_kernel<<<MREL / 256, 256>>>(recv, pos, list);
    // 4) particle prep: Sr, Ss, pencode chain -> pbase
    partall_kernel<<<MPART / 128, 256, CH_TOTAL>>>(state, pe_b0, pe_b1, pp_b, wh, wl,
                                                   P1, P2, pbase);
    // 5) relation chain -> relbase
    relchain_kernel<<<MREL / 128, 256, CH_TOTAL>>>(
        P1, P2, Ra, re_w0 + 64 * 128, re_b0, re_b1, re_b2, rp_b, recv, send, wh, wl, relbase);
    // 6) propagation (first step uses E_RESID0 — no stale peffect read)
    agg_kernel<true><<<MPART / 2, 256>>>(relbase, nullptr, nullptr, send, off, list, eagg);
    mma_gemm<A_F32, E_RESID0><<<MPART / 128, 256, SMEM_TOTAL_B>>>(
        eagg, wh + WO_PPBOT, wl + WO_PPBOT, nullptr, peffect, pbase, peffP, 128, 4, 0, 0);
    for (int s = 1; s < PSTEPS; ++s) {
        dim3 g(MPART / 128, 2);
        mma_gemm<A_BF, E_BASE><<<g, 256, SMEM_TOTAL_B>>>(
            peffP, wh + WO_RPM, wl + WO_RPM, nullptr, pair, nullptr, nullptr,
            128, 4, 8192, (long long)MPART * NF * 4);
        agg_kernel<false><<<MPART / 2, 256>>>(relbase, P1, P2, send, off, list, eagg);
        mma_gemm<A_F32, E_RESID><<<MPART / 128, 256, SMEM_TOTAL_B>>>(
            eagg, wh + WO_PPBOT, wl + WO_PPBOT, nullptr, peffect, pbase, peffP, 128, 4, 0, 0);
    }
    // 7) predictor
    mma_gemm<A_BF, E_RELU_F32><<<MPART / 128, 256, SMEM_TOTAL_B>>>(
        peffP, wh + WO_PR0, wl + WO_PR0, pr_b0, ptmpP, nullptr, nullptr, 128, 4, 0, 0);
    pred_final_kernel<<<MPART / 256, 256>>>((const float*)ptmpP, pr_w1, pr_b1, out);
}

// round 17
// speedup vs baseline: 1.1291x; 1.0112x over previous
#include <cuda_runtime.h>
#include <cuda_bf16.h>
#include <cstdint>

#define BB    8
#define NN    1024
#define RR    8192
#define DIN   32
#define NF    128
#define DOUT  3
#define PSTEPS 3
#define MREL  (BB * RR)   // 65536
#define MPART (BB * NN)   // 8192

// ---------------- scratch (device globals) ----------------------------------
__device__ float    g_relbase[MREL * NF]; // 32 MB fp32
__device__ uint32_t g_ptmpP[MPART * NF];
__device__ uint32_t g_peffP[MPART * NF];
__device__ float    g_peffect[MPART * NF];
__device__ float    g_pbase[MPART * NF];
__device__ float    g_eagg[MPART * NF];
__device__ float    g_pair[2 * MPART * NF]; // Sr/Ss, later P1/P2
__device__ int      g_recv[MREL];
__device__ int      g_send[MREL];
__device__ int      g_cnt[MPART];
__device__ int      g_off[MPART + 1];
__device__ int      g_pos[MPART];
__device__ int      g_list[MREL];
__device__ int      g_slist[MREL];   // precomputed global send row per CSR slot
// packed weights: [Kpad/2][128] u32 (bf16x2 of k,k+1 per col n), hi & lo planes
#define WT_U32 79872
__device__ uint32_t g_wh[WT_U32];
__device__ uint32_t g_wl[WT_U32];
#define WO_PE0  0       // Kpad 32
#define WO_PE1  2048    // 128
#define WO_RE1  10240   // 128
#define WO_RE2  18432   // 128
#define WO_RPT  26624   // 128 (rp_w rows 0-127)
#define WO_RPM  34816   // 128 (rows 128-255)
#define WO_RPB  43008   // 128 (rows 256-383)
#define WO_PP   51200   // 256 (top: k2 0-63, bot: +8192)
#define WO_PR0  67584   // 128
#define WO_REWR 75776   // 32 (re_w0 rows 0-31)
#define WO_REWS 77824   // 32 (re_w0 rows 32-63)

// ---------------- helpers ----------------------------------------------------
__device__ __forceinline__ uint32_t packbf(float vlo, float vhi) {
    uint32_t r;
    asm("cvt.rn.bf16x2.f32 %0, %1, %2;" : "=r"(r) : "f"(vhi), "f"(vlo));
    return r;
}
__device__ __forceinline__ void mma16816(float* d, const uint32_t* a, uint32_t b0, uint32_t b1) {
    asm volatile("mma.sync.aligned.m16n8k16.row.col.f32.bf16.bf16.f32 "
                 "{%0,%1,%2,%3}, {%4,%5,%6,%7}, {%8,%9}, {%0,%1,%2,%3};"
                 : "+f"(d[0]), "+f"(d[1]), "+f"(d[2]), "+f"(d[3])
                 : "r"(a[0]), "r"(a[1]), "r"(a[2]), "r"(a[3]), "r"(b0), "r"(b1));
}

// ---------------- index extraction + inline CSR count (high-MLP) -------------
__device__ __forceinline__ void proc_quad(uint4 v, long long idx,
                                          int* __restrict__ dst,
                                          int* __restrict__ cnt, bool do_cnt)
{
    if (v.x | v.y | v.z | v.w) {
        long long e = idx * 4;
        int b = (int)(e >> 23);
        int n = (int)((e >> 13) & (NN - 1));
        int r = (int)(e & (RR - 1));
        int* o = dst + b * RR + r;
        int nz = 0;
        if (v.x) { o[0] = n; ++nz; }
        if (v.y) { o[1] = n; ++nz; }
        if (v.z) { o[2] = n; ++nz; }
        if (v.w) { o[3] = n; ++nz; }
        if (do_cnt) atomicAdd(&cnt[(b << 10) + n], nz);
    }
}

__global__ void extract_idx_kernel(const uint4* __restrict__ Rr,
                                   const uint4* __restrict__ Rs,
                                   int* __restrict__ recv, int* __restrict__ send,
                                   int* __restrict__ cnt)
{
    const long long total  = (long long)BB * NN * RR / 4;          // 16M uint4
    const long long stride = (long long)gridDim.x * blockDim.x * 4;
    const int bd = blockDim.x;
    for (long long base = (long long)blockIdx.x * bd * 4 + threadIdx.x;
         base < total; base += stride) {
        uint4 a0 = __ldcs(Rr + base);
        uint4 a1 = __ldcs(Rr + base + bd);
        uint4 a2 = __ldcs(Rr + base + 2 * bd);
        uint4 a3 = __ldcs(Rr + base + 3 * bd);
        uint4 b0 = __ldcs(Rs + base);
        uint4 b1 = __ldcs(Rs + base + bd);
        uint4 b2 = __ldcs(Rs + base + 2 * bd);
        uint4 b3 = __ldcs(Rs + base + 3 * bd);
        proc_quad(a0, base,          recv, cnt, true);
        proc_quad(a1, base + bd,     recv, cnt, true);
        proc_quad(a2, base + 2 * bd, recv, cnt, true);
        proc_quad(a3, base + 3 * bd, recv, cnt, true);
        proc_quad(b0, base,          send, nullptr, false);
        proc_quad(b1, base + bd,     send, nullptr, false);
        proc_quad(b2, base + 2 * bd, send, nullptr, false);
        proc_quad(b3, base + 3 * bd, send, nullptr, false);
    }
}

// ---------------- CSR scan + fill --------------------------------------------
__global__ void csr_scan_kernel(const int* __restrict__ cnt,
                                int* __restrict__ off, int* __restrict__ pos) {
    __shared__ int part[1024];
    const int tid = threadIdx.x;
    int local[8];
    int s = 0;
#pragma unroll
    for (int j = 0; j < 8; ++j) { local[j] = s; s += cnt[tid * 8 + j]; }
    part[tid] = s;
    __syncthreads();
    for (int d = 1; d < 1024; d <<= 1) {
        int v = part[tid];
        if (tid >= d) v += part[tid - d];
        __syncthreads();
        part[tid] = v;
        __syncthreads();
    }
    int base = (tid == 0) ? 0 : part[tid - 1];
#pragma unroll
    for (int j = 0; j < 8; ++j) {
        int o = base + local[j];
        off[tid * 8 + j] = o;
        pos[tid * 8 + j] = o;
    }
    if (tid == 1023) off[MPART] = part[1023];
}
// fill also precomputes the global send row (removes one indirection level in agg)
__global__ void csr_fill_kernel(const int* __restrict__ recv, const int* __restrict__ send,
                                int* __restrict__ pos, int* __restrict__ list,
                                int* __restrict__ slist) {
    int r = blockIdx.x * blockDim.x + threadIdx.x;
    int hi = (r >> 13) << 10;
    int p = hi + recv[r];
    int gs = hi + send[r];
    int idx = atomicAdd(&pos[p], 1);
    list[idx] = r;
    slist[idx] = gs;
}

// ---------------- weights: transpose + split + pack (+ cnt zero) ------------
__global__ void split_all_kernel(const float* __restrict__ pe_w0, const float* __restrict__ pe_w1,
                                 const float* __restrict__ re_w0, const float* __restrict__ re_w1,
                                 const float* __restrict__ re_w2, const float* __restrict__ rp_w,
                                 const float* __restrict__ pp_w, const float* __restrict__ pr_w0,
                                 uint32_t* __restrict__ hi, uint32_t* __restrict__ lo,
                                 int* __restrict__ cnt)
{
    int idx = blockIdx.x * blockDim.x + threadIdx.x;
    if (idx >= WT_U32) {
        int z = idx - WT_U32;
        if (z < MPART) cnt[z] = 0;
        return;
    }
    const float* w; int K, local;
    if      (idx < 2048)  { w = pe_w0;              K = 32;  local = idx; }
    else if (idx < 10240) { w = pe_w1;              K = 128; local = idx - 2048; }
    else if (idx < 18432) { w = re_w1;              K = 128; local = idx - 10240; }
    else if (idx < 26624) { w = re_w2;              K = 128; local = idx - 18432; }
    else if (idx < 34816) { w = rp_w;               K = 128; local = idx - 26624; }
    else if (idx < 43008) { w = rp_w + 128 * 128;   K = 128; local = idx - 34816; }
    else if (idx < 51200) { w = rp_w + 256 * 128;   K = 128; local = idx - 43008; }
    else if (idx < 67584) { w = pp_w;               K = 256; local = idx - 51200; }
    else if (idx < 75776) { w = pr_w0;              K = 128; local = idx - 67584; }
    else if (idx < 77824) { w = re_w0;              K = 32;  local = idx - 75776; }
    else                  { w = re_w0 + 32 * 128;   K = 32;  local = idx - 77824; }
    int k2 = local >> 7, n = local & 127;
    int k0 = 2 * k2;
    float v0 = (k0 < K)     ? w[(size_t)k0 * 128 + n]       : 0.f;
    float v1 = (k0 + 1 < K) ? w[(size_t)(k0 + 1) * 128 + n] : 0.f;
    uint32_t h = packbf(v0, v1);
    float h0 = __uint_as_float(h << 16);
    float h1 = __uint_as_float(h & 0xFFFF0000u);
    hi[idx] = h;
    lo[idx] = packbf(v0 - h0, v1 - h1);
}

// -------- CSR gather-reduce aggregation (atomic-free, 4-way, flat indices) ---
template<bool FIRST>
__global__ __launch_bounds__(256, 8)
void agg_kernel(const float* __restrict__ relbase,
                const float* __restrict__ P1, const float* __restrict__ P2,
                const int* __restrict__ slist,
                const int* __restrict__ off, const int* __restrict__ list,
                float* __restrict__ eagg)
{
    const int p = blockIdx.x * 2 + (threadIdx.x >> 7);
    const int c = threadIdx.x & 127;
    const int beg = off[p], end = off[p + 1];
    float p1c = FIRST ? 0.f : P1[(size_t)p * NF + c];
    float acc = 0.f;
    int i = beg;
    for (; i + 4 <= end; i += 4) {
        int r0 = list[i];
        int r1 = list[i + 1];
        int r2 = list[i + 2];
        int r3 = list[i + 3];
        float v0 = relbase[(size_t)r0 * NF + c];
        float v1 = relbase[(size_t)r1 * NF + c];
        float v2 = relbase[(size_t)r2 * NF + c];
        float v3 = relbase[(size_t)r3 * NF + c];
        if (!FIRST) {
            int gs0 = slist[i];
            int gs1 = slist[i + 1];
            int gs2 = slist[i + 2];
            int gs3 = slist[i + 3];
            v0 += P2[(size_t)gs0 * NF + c];
            v1 += P2[(size_t)gs1 * NF + c];
            v2 += P2[(size_t)gs2 * NF + c];
            v3 += P2[(size_t)gs3 * NF + c];
        }
        acc += fmaxf(v0 + p1c, 0.f);
        acc += fmaxf(v1 + p1c, 0.f);
        acc += fmaxf(v2 + p1c, 0.f);
        acc += fmaxf(v3 + p1c, 0.f);
    }
    for (; i + 2 <= end; i += 2) {
        int r0 = list[i];
        int r1 = list[i + 1];
        float v0 = relbase[(size_t)r0 * NF + c];
        float v1 = relbase[(size_t)r1 * NF + c];
        if (!FIRST) {
            v0 += P2[(size_t)slist[i] * NF + c];
            v1 += P2[(size_t)slist[i + 1] * NF + c];
        }
        acc += fmaxf(v0 + p1c, 0.f);
        acc += fmaxf(v1 + p1c, 0.f);
    }
    if (i < end) {
        int r = list[i];
        float v = relbase[(size_t)r * NF + c] + p1c;
        if (!FIRST) {
            v += P2[(size_t)slist[i] * NF + c];
        }
        acc += fmaxf(v, 0.f);
    }
    eagg[(size_t)p * NF + c] = acc;
}

// ================== chained multi-layer GEMM machinery (R12-validated) =======
#define CH_WA   0
#define CH_B0   512
#define CH_BA   1024
#define CH_BB   1536
#define CH_BC   2048
#define CH_AHI  2560                        // chained A hi plane: 128 rows x 68 u32
#define CH_ALO  (CH_AHI + 34816)            // 37376
#define CH_WBASE (CH_ALO + 34816)           // 72192
#define CH_WHI(s) (CH_WBASE + (s) * 8704)
#define CH_WLO(s) (CH_WBASE + 17408 + (s) * 8704)
#define CH_TOTAL (CH_WBASE + 34816)         // 107008

__device__ __forceinline__ void ch_fill_w(char* smem, int s, int kt,
    const uint32_t* __restrict__ Whp, const uint32_t* __restrict__ Wlp, int tid)
{
    const int k2 = tid >> 4;
    const int nn = (tid & 15) * 8;
    const size_t gi = (size_t)(kt * 16 + k2) * 128 + nn;
    uint4 h0 = *(const uint4*)(Whp + gi);
    uint4 h1 = *(const uint4*)(Whp + gi + 4);
    uint4 l0 = *(const uint4*)(Wlp + gi);
    uint4 l1 = *(const uint4*)(Wlp + gi + 4);
    char* wb = smem + CH_WHI(s) + k2 * 544 + nn * 4;
    ((uint4*)wb)[0] = h0; ((uint4*)wb)[1] = h1;
    char* lb = smem + CH_WLO(s) + k2 * 544 + nn * 4;
    ((uint4*)lb)[0] = l0; ((uint4*)lb)[1] = l1;
}

__device__ __forceinline__ void ch_compute(char* smem, int kt, int s,
    int wm, int wn, int lane, float (&acc)[4][4][4])
{
    const uint32_t* AH = (const uint32_t*)(smem + CH_AHI);
    const uint32_t* AL = (const uint32_t*)(smem + CH_ALO);
    const uint32_t* WH = (const uint32_t*)(smem + CH_WHI(s));
    const uint32_t* WL = (const uint32_t*)(smem + CH_WLO(s));
#pragma unroll
    for (int step = 0; step < 2; ++step) {
        uint32_t ah[4][4], al[4][4];
#pragma unroll
        for (int f = 0; f < 4; ++f) {
            int r = wm * 64 + f * 16 + (lane >> 2);
            int i0 = r * 68 + kt * 16 + (lane & 3) + step * 8;
            ah[f][0] = AH[i0];       ah[f][1] = AH[i0 + 544];
            ah[f][2] = AH[i0 + 4];   ah[f][3] = AH[i0 + 548];
            al[f][0] = AL[i0];       al[f][1] = AL[i0 + 544];
            al[f][2] = AL[i0 + 4];   al[f][3] = AL[i0 + 548];
        }
#pragma unroll
        for (int nf = 0; nf < 4; ++nf) {
            int bi = (step * 8 + (lane & 3)) * 136 + wn * 32 + nf * 8 + (lane >> 2);
            uint32_t bh0 = WH[bi], bh1 = WH[bi + 544];
            uint32_t bl0 = WL[bi], bl1 = WL[bi + 544];
#pragma unroll
            for (int f = 0; f < 4; ++f) {
                mma16816(acc[f][nf], ah[f], bh0, bh1);
                mma16816(acc[f][nf], ah[f], bl0, bl1);
                mma16816(acc[f][nf], al[f], bh0, bh1);
            }
        }
    }
}

__device__ __forceinline__ void ch_gemm_layer(char* smem,
    const uint32_t* __restrict__ Whp, const uint32_t* __restrict__ Wlp, int nchunk,
    int wm, int wn, int lane, int tid, float (&acc)[4][4][4])
{
#pragma unroll
    for (int f = 0; f < 4; ++f)
#pragma unroll
        for (int nf = 0; nf < 4; ++nf)
#pragma unroll
            for (int j = 0; j < 4; ++j) acc[f][nf][j] = 0.f;
    ch_fill_w(smem, 0, 0, Whp, Wlp, tid);
    __syncthreads();
    for (int kt = 0; kt < nchunk; ++kt) {
        int s = kt & 1;
        if (kt + 1 < nchunk) ch_fill_w(smem, s ^ 1, kt + 1, Whp, Wlp, tid);
        ch_compute(smem, kt, s, wm, wn, lane, acc);
        __syncthreads();
    }
}

__device__ __forceinline__ void ch_epi_planes(char* smem, const float* bias_s,
    int wm, int wn, int lane, float (&acc)[4][4][4])
{
    uint32_t* AH = (uint32_t*)(smem + CH_AHI);
    uint32_t* AL = (uint32_t*)(smem + CH_ALO);
#pragma unroll
    for (int f = 0; f < 4; ++f) {
        int r0 = wm * 64 + f * 16 + (lane >> 2);
        int r1 = r0 + 8;
#pragma unroll
        for (int nf = 0; nf < 4; ++nf) {
            int c = wn * 32 + nf * 8 + (lane & 3) * 2;
            int c2 = c >> 1;
            float a0 = fmaxf(acc[f][nf][0] + bias_s[c], 0.f);
            float a1 = fmaxf(acc[f][nf][1] + bias_s[c + 1], 0.f);
            float a2 = fmaxf(acc[f][nf][2] + bias_s[c], 0.f);
            float a3 = fmaxf(acc[f][nf][3] + bias_s[c + 1], 0.f);
            uint32_t h0 = packbf(a0, a1), h1 = packbf(a2, a3);
            AH[r0 * 68 + c2] = h0;
            AH[r1 * 68 + c2] = h1;
            AL[r0 * 68 + c2] = packbf(a0 - __uint_as_float(h0 << 16), a1 - __uint_as_float(h0 & 0xFFFF0000u));
            AL[r1 * 68 + c2] = packbf(a2 - __uint_as_float(h1 << 16), a3 - __uint_as_float(h1 & 0xFFFF0000u));
        }
    }
}

__device__ __forceinline__ void ch_write_f32(float* dst, int row0, const float* bias_s,
    int wm, int wn, int lane, float (&acc)[4][4][4])
{
#pragma unroll
    for (int f = 0; f < 4; ++f) {
        int r0 = wm * 64 + f * 16 + (lane >> 2), r1 = r0 + 8;
#pragma unroll
        for (int nf = 0; nf < 4; ++nf) {
            int c = wn * 32 + nf * 8 + (lane & 3) * 2;
            float b0 = bias_s ? bias_s[c] : 0.f;
            float b1 = bias_s ? bias_s[c + 1] : 0.f;
            *(float2*)(dst + (size_t)(row0 + r0) * 128 + c) =
                make_float2(acc[f][nf][0] + b0, acc[f][nf][1] + b1);
            *(float2*)(dst + (size_t)(row0 + r1) * 128 + c) =
                make_float2(acc[f][nf][2] + b0, acc[f][nf][3] + b1);
        }
    }
}

// ---- fused relation chain: gather-combine -> re1 -> re2 -> relbase ----------
__global__ __launch_bounds__(256, 2)
void relchain_kernel(const float* __restrict__ Sr, const float* __restrict__ Ss,
                     const float* __restrict__ Ra,
                     const float* __restrict__ wa, const float* __restrict__ b0,
                     const float* __restrict__ b1, const float* __restrict__ b2,
                     const float* __restrict__ brp,
                     const int* __restrict__ recv, const int* __restrict__ send,
                     const uint32_t* __restrict__ wh, const uint32_t* __restrict__ wl,
                     float* __restrict__ relbase)
{
    extern __shared__ char smem[];
    const int tid = threadIdx.x, lane = tid & 31, wid = tid >> 5;
    const int wm = wid & 1, wn = wid >> 1;
    const int row0 = blockIdx.x * 128;
    float* wa_s = (float*)(smem + CH_WA);
    float* b0_s = (float*)(smem + CH_B0);
    float* bA_s = (float*)(smem + CH_BA);
    float* bB_s = (float*)(smem + CH_BB);
    float* bC_s = (float*)(smem + CH_BC);
    if (tid < 128) {
        wa_s[tid] = wa[tid]; b0_s[tid] = b0[tid];
        bA_s[tid] = b1[tid]; bB_s[tid] = b2[tid]; bC_s[tid] = brp[tid];
    }
    const int row = tid >> 1, half = tid & 1, grow = row0 + row, bb = grow >> 13;
    const float ra = Ra[grow];
    const int rv = (bb << 10) + recv[grow];
    const int sd = (bb << 10) + send[grow];
    const float4* pr = (const float4*)(Sr + (size_t)rv * 128 + half * 64);
    const float4* ps = (const float4*)(Ss + (size_t)sd * 128 + half * 64);
    __syncthreads();
    {
        uint32_t* AH = (uint32_t*)(smem + CH_AHI) + row * 68 + half * 32;
        uint32_t* AL = (uint32_t*)(smem + CH_ALO) + row * 68 + half * 32;
#pragma unroll
        for (int j = 0; j < 16; ++j) {
            float4 u = pr[j], v = ps[j];
            int c = half * 64 + j * 4;
            float a0 = fmaxf(u.x + v.x + ra * wa_s[c]     + b0_s[c],     0.f);
            float a1 = fmaxf(u.y + v.y + ra * wa_s[c + 1] + b0_s[c + 1], 0.f);
            float a2 = fmaxf(u.z + v.z + ra * wa_s[c + 2] + b0_s[c + 2], 0.f);
            float a3 = fmaxf(u.w + v.w + ra * wa_s[c + 3] + b0_s[c + 3], 0.f);
            uint32_t h0 = packbf(a0, a1), h1 = packbf(a2, a3);
            AH[2 * j] = h0; AH[2 * j + 1] = h1;
            AL[2 * j] = packbf(a0 - __uint_as_float(h0 << 16), a1 - __uint_as_float(h0 & 0xFFFF0000u));
            AL[2 * j + 1] = packbf(a2 - __uint_as_float(h1 << 16), a3 - __uint_as_float(h1 & 0xFFFF0000u));
        }
    }
    float acc[4][4][4];
    ch_gemm_layer(smem, wh + WO_RE1, wl + WO_RE1, 4, wm, wn, lane, tid, acc);
    ch_epi_planes(smem, bA_s, wm, wn, lane, acc);
    ch_gemm_layer(smem, wh + WO_RE2, wl + WO_RE2, 4, wm, wn, lane, tid, acc);
    ch_epi_planes(smem, bB_s, wm, wn, lane, acc);
    ch_gemm_layer(smem, wh + WO_RPT, wl + WO_RPT, 4, wm, wn, lane, tid, acc);
    ch_write_f32(relbase, row0, bC_s, wm, wn, lane, acc);
}

// ---- fused particle prep: Sr, Ss, pe0 -> pe1 -> pbase -----------------------
__global__ __launch_bounds__(256, 2)
void partall_kernel(const float* __restrict__ state,
                    const float* __restrict__ pe_b0, const float* __restrict__ pe_b1,
                    const float* __restrict__ pp_b,
                    const uint32_t* __restrict__ wh, const uint32_t* __restrict__ wl,
                    float* __restrict__ Sr, float* __restrict__ Ss,
                    float* __restrict__ pbase)
{
    extern __shared__ char smem[];
    const int tid = threadIdx.x, lane = tid & 31, wid = tid >> 5;
    const int wm = wid & 1, wn = wid >> 1;
    const int row0 = blockIdx.x * 128;
    float* bA_s = (float*)(smem + CH_BA);
    float* bB_s = (float*)(smem + CH_BB);
    float* bC_s = (float*)(smem + CH_BC);
    if (tid < 128) { bA_s[tid] = pe_b0[tid]; bB_s[tid] = pe_b1[tid]; bC_s[tid] = pp_b[tid]; }
    {
        const int row = tid >> 1, half = tid & 1, grow = row0 + row;
        const float4* q = (const float4*)(state + (size_t)grow * 32 + half * 16);
        float x[16];
#pragma unroll
        for (int j = 0; j < 4; ++j) {
            float4 u = q[j];
            x[4 * j] = u.x; x[4 * j + 1] = u.y; x[4 * j + 2] = u.z; x[4 * j + 3] = u.w;
        }
        uint32_t* AH = (uint32_t*)(smem + CH_AHI) + row * 68 + half * 8;
        uint32_t* AL = (uint32_t*)(smem + CH_ALO) + row * 68 + half * 8;
#pragma unroll
        for (int j = 0; j < 8; ++j) {
            uint32_t h = packbf(x[2 * j], x[2 * j + 1]);
            AH[j] = h;
            AL[j] = packbf(x[2 * j] - __uint_as_float(h << 16),
                           x[2 * j + 1] - __uint_as_float(h & 0xFFFF0000u));
        }
    }
    float acc[4][4][4];
    ch_gemm_layer(smem, wh + WO_REWR, wl + WO_REWR, 1, wm, wn, lane, tid, acc);
    ch_write_f32(Sr, row0, nullptr, wm, wn, lane, acc);
    ch_gemm_layer(smem, wh + WO_REWS, wl + WO_REWS, 1, wm, wn, lane, tid, acc);
    ch_write_f32(Ss, row0, nullptr, wm, wn, lane, acc);
    ch_gemm_layer(smem, wh + WO_PE0, wl + WO_PE0, 1, wm, wn, lane, tid, acc);
    ch_epi_planes(smem, bA_s, wm, wn, lane, acc);
    ch_gemm_layer(smem, wh + WO_PE1, wl + WO_PE1, 4, wm, wn, lane, tid, acc);
    ch_epi_planes(smem, bB_s, wm, wn, lane, acc);
    ch_gemm_layer(smem, wh + WO_PP, wl + WO_PP, 4, wm, wn, lane, tid, acc);
    ch_write_f32(pbase, row0, bC_s, wm, wn, lane, acc);
}

// ---------------- generic fused mma.sync GEMM (R12-validated) ----------------
enum { A_F32 = 0, A_BF = 1 };
enum { E_RELU_F32 = 0, E_BASE = 2, E_RESID = 3, E_RESID0 = 4 };

#define SM_BIAS 0
#define SM_A    1536
#define AHI_OFF(s) (SM_A + (s) * 10240)
#define ALO_OFF(s) (SM_A + 20480 + (s) * 10240)
#define SM_W    (SM_A + 40960)
#define WHI_OFF(s) (SM_W + (s) * 8704)
#define WLO_OFF(s) (SM_W + 17408 + (s) * 8704)
#define SMEM_TOTAL_B (SM_W + 34816)   // 77312 bytes

template<int MODE_A>
__device__ __forceinline__ void fill_tile(
    char* smem, int s, int kt,
    const void* __restrict__ Av,
    const uint32_t* __restrict__ Whp, const uint32_t* __restrict__ Wlp,
    int row0, int K, int tid)
{
    const int row   = tid >> 1;
    const int half  = tid & 1;
    const int kbase = kt * 32 + half * 16;
    const int grow  = row0 + row;

    uint4 hA0, hA1, lA0, lA1;

    if (MODE_A == A_BF) {
        const uint32_t* Xp = (const uint32_t*)Av + (size_t)grow * 128;
        int k2 = kbase >> 1;
        hA0 = *(const uint4*)(Xp + k2);
        hA1 = *(const uint4*)(Xp + k2 + 4);
        lA0 = *(const uint4*)(Xp + 64 + k2);
        lA1 = *(const uint4*)(Xp + 64 + k2 + 4);
    } else {
        float x[16];
        if (kbase < K) {
            const float4* q = (const float4*)((const float*)Av + (size_t)grow * K + kbase);
#pragma unroll
            for (int j = 0; j < 4; ++j) {
                float4 u = q[j];
                x[4 * j] = u.x; x[4 * j + 1] = u.y; x[4 * j + 2] = u.z; x[4 * j + 3] = u.w;
            }
        } else {
#pragma unroll
            for (int j = 0; j < 16; ++j) x[j] = 0.f;
        }
        uint32_t hi[8], lo[8];
#pragma unroll
        for (int j = 0; j < 8; ++j) {
            uint32_t h = packbf(x[2 * j], x[2 * j + 1]);
            hi[j] = h;
            float h0 = __uint_as_float(h << 16);
            float h1 = __uint_as_float(h & 0xFFFF0000u);
            lo[j] = packbf(x[2 * j] - h0, x[2 * j + 1] - h1);
        }
        hA0 = make_uint4(hi[0], hi[1], hi[2], hi[3]);
        hA1 = make_uint4(hi[4], hi[5], hi[6], hi[7]);
        lA0 = make_uint4(lo[0], lo[1], lo[2], lo[3]);
        lA1 = make_uint4(lo[4], lo[5], lo[6], lo[7]);
    }
    {
        uint4* dh = (uint4*)(smem + AHI_OFF(s) + row * 80 + half * 32);
        dh[0] = hA0; dh[1] = hA1;
        uint4* dl = (uint4*)(smem + ALO_OFF(s) + row * 80 + half * 32);
        dl[0] = lA0; dl[1] = lA1;
    }
    {
        const int k2 = tid >> 4;
        const int nn = (tid & 15) * 8;
        const size_t gi = (size_t)(kt * 16 + k2) * 128 + nn;
        uint4 h0 = *(const uint4*)(Whp + gi);
        uint4 h1 = *(const uint4*)(Whp + gi + 4);
        uint4 l0 = *(const uint4*)(Wlp + gi);
        uint4 l1 = *(const uint4*)(Wlp + gi + 4);
        char* wb = smem + WHI_OFF(s) + k2 * 544 + nn * 4;
        ((uint4*)wb)[0] = h0; ((uint4*)wb)[1] = h1;
        char* lb = smem + WLO_OFF(s) + k2 * 544 + nn * 4;
        ((uint4*)lb)[0] = l0; ((uint4*)lb)[1] = l1;
    }
}

template<int MODE_A, int MODE_EPI>
__global__ __launch_bounds__(256, 2)
void mma_gemm(const void* __restrict__ Av,
              const uint32_t* __restrict__ Whp, const uint32_t* __restrict__ Wlp,
              const float* __restrict__ bias, void* __restrict__ Cv,
              const float* __restrict__ base,
              uint32_t* __restrict__ C2,
              int K, int nchunk, int wstride, long long cstrideB)
{
    extern __shared__ char smem[];
    const int tid  = threadIdx.x;
    const int wid  = tid >> 5;
    const int lane = tid & 31;
    const int row0 = blockIdx.x * 128;
    const int wm = wid & 1;
    const int wn = wid >> 1;

    Whp += (size_t)blockIdx.y * wstride;
    Wlp += (size_t)blockIdx.y * wstride;
    char* Cb = (char*)Cv + (size_t)blockIdx.y * cstrideB;

    float* bias_s = (float*)(smem + SM_BIAS);
    if (tid < 128) bias_s[tid] = bias ? bias[tid] : 0.f;
    __syncthreads();

    float acc[4][4][4];
#pragma unroll
    for (int f = 0; f < 4; ++f)
#pragma unroll
        for (int nf = 0; nf < 4; ++nf)
#pragma unroll
            for (int j = 0; j < 4; ++j) acc[f][nf][j] = 0.f;

    fill_tile<MODE_A>(smem, 0, 0, Av, Whp, Wlp, row0, K, tid);
    __syncthreads();

    for (int kt = 0; kt < nchunk; ++kt) {
        const int s = kt & 1;
        if (kt + 1 < nchunk)
            fill_tile<MODE_A>(smem, s ^ 1, kt + 1, Av, Whp, Wlp, row0, K, tid);

        const uint32_t* AH = (const uint32_t*)(smem + AHI_OFF(s));
        const uint32_t* AL = (const uint32_t*)(smem + ALO_OFF(s));
        const uint32_t* WH = (const uint32_t*)(smem + WHI_OFF(s));
        const uint32_t* WL = (const uint32_t*)(smem + WLO_OFF(s));

#pragma unroll
        for (int step = 0; step < 2; ++step) {
            uint32_t ah[4][4], al[4][4];
#pragma unroll
            for (int f = 0; f < 4; ++f) {
                int r = wm * 64 + f * 16 + (lane >> 2);
                int i0 = r * 20 + (lane & 3) + step * 8;
                ah[f][0] = AH[i0];       ah[f][1] = AH[i0 + 160];
                ah[f][2] = AH[i0 + 4];   ah[f][3] = AH[i0 + 164];
                al[f][0] = AL[i0];       al[f][1] = AL[i0 + 160];
                al[f][2] = AL[i0 + 4];   al[f][3] = AL[i0 + 164];
            }
#pragma unroll
            for (int nf = 0; nf < 4; ++nf) {
                int bi = (step * 8 + (lane & 3)) * 136 + wn * 32 + nf * 8 + (lane >> 2);
                uint32_t bh0 = WH[bi], bh1 = WH[bi + 544];
                uint32_t bl0 = WL[bi], bl1 = WL[bi + 544];
#pragma unroll
                for (int f = 0; f < 4; ++f) {
                    mma16816(acc[f][nf], ah[f], bh0, bh1);
                    mma16816(acc[f][nf], ah[f], bl0, bl1);
                    mma16816(acc[f][nf], al[f], bh0, bh1);
                }
            }
        }
        __syncthreads();
    }

    float bc0[4], bc1[4];
#pragma unroll
    for (int nf = 0; nf < 4; ++nf) {
        int c = wn * 32 + nf * 8 + (lane & 3) * 2;
        bc0[nf] = bias_s[c];
        bc1[nf] = bias_s[c + 1];
    }
#pragma unroll
    for (int f = 0; f < 4; ++f) {
        int rl0 = wm * 64 + f * 16 + (lane >> 2);
        int rl1 = rl0 + 8;
        int r0 = row0 + rl0;
        int r1 = row0 + rl1;
#pragma unroll
        for (int nf = 0; nf < 4; ++nf) {
            int c = wn * 32 + nf * 8 + (lane & 3) * 2;
            float v0 = acc[f][nf][0] + bc0[nf];
            float v1 = acc[f][nf][1] + bc1[nf];
            float v2 = acc[f][nf][2] + bc0[nf];
            float v3 = acc[f][nf][3] + bc1[nf];
            if (MODE_EPI == E_RELU_F32) {
                float* CF = (float*)Cb;
                *(float2*)(&CF[(size_t)r0 * NF + c]) = make_float2(fmaxf(v0, 0.f), fmaxf(v1, 0.f));
                *(float2*)(&CF[(size_t)r1 * NF + c]) = make_float2(fmaxf(v2, 0.f), fmaxf(v3, 0.f));
            } else if (MODE_EPI == E_BASE) {
                float* CF = (float*)Cb;
                *(float2*)(&CF[(size_t)r0 * NF + c]) = make_float2(v0, v1);
                *(float2*)(&CF[(size_t)r1 * NF + c]) = make_float2(v2, v3);
            } else { // E_RESID / E_RESID0
                float* CF = (float*)Cb;
                float2 b0 = *(const float2*)(&base[(size_t)r0 * NF + c]);
                float2 b1 = *(const float2*)(&base[(size_t)r1 * NF + c]);
                float2 p0 = make_float2(0.f, 0.f), p1 = make_float2(0.f, 0.f);
                if (MODE_EPI == E_RESID) {
                    p0 = *(const float2*)(&CF[(size_t)r0 * NF + c]);
                    p1 = *(const float2*)(&CF[(size_t)r1 * NF + c]);
                }
                float a0 = fmaxf(v0 + b0.x + p0.x, 0.f);
                float a1 = fmaxf(v1 + b0.y + p0.y, 0.f);
                float a2 = fmaxf(v2 + b1.x + p1.x, 0.f);
                float a3 = fmaxf(v3 + b1.y + p1.y, 0.f);
                *(float2*)(&CF[(size_t)r0 * NF + c]) = make_float2(a0, a1);
                *(float2*)(&CF[(size_t)r1 * NF + c]) = make_float2(a2, a3);
                uint32_t h0 = packbf(a0, a1);
                uint32_t h1 = packbf(a2, a3);
                C2[(size_t)r0 * 128 + (c >> 1)] = h0;
                C2[(size_t)r1 * 128 + (c >> 1)] = h1;
                C2[(size_t)r0 * 128 + 64 + (c >> 1)] =
                    packbf(a0 - __uint_as_float(h0 << 16), a1 - __uint_as_float(h0 & 0xFFFF0000u));
                C2[(size_t)r1 * 128 + 64 + (c >> 1)] =
                    packbf(a2 - __uint_as_float(h1 << 16), a3 - __uint_as_float(h1 & 0xFFFF0000u));
            }
        }
    }
}

// ---------------- final predictor layer --------------------------------------
__global__ void pred_final_kernel(const float* __restrict__ X, const float* __restrict__ W,
                                  const float* __restrict__ bias, float* __restrict__ out)
{
    __shared__ float Ws[NF * DOUT];
    __shared__ float bs[DOUT];
    int tid = threadIdx.x;
    for (int i = tid; i < NF * DOUT; i += blockDim.x) Ws[i] = W[i];
    if (tid < DOUT) bs[tid] = bias[tid];
    __syncthreads();
    int p = blockIdx.x * blockDim.x + tid;
    float a0 = bs[0], a1 = bs[1], a2 = bs[2];
    const float4* xp = (const float4*)(X + (size_t)p * NF);
#pragma unroll
    for (int k4 = 0; k4 < NF / 4; ++k4) {
        float4 x = xp[k4];
        int k = k4 * 4;
        a0 += x.x * Ws[k * 3 + 0] + x.y * Ws[(k + 1) * 3 + 0] +
              x.z * Ws[(k + 2) * 3 + 0] + x.w * Ws[(k + 3) * 3 + 0];
        a1 += x.x * Ws[k * 3 + 1] + x.y * Ws[(k + 1) * 3 + 1] +
              x.z * Ws[(k + 2) * 3 + 1] + x.w * Ws[(k + 3) * 3 + 1];
        a2 += x.x * Ws[k * 3 + 2] + x.y * Ws[(k + 1) * 3 + 2] +
              x.z * Ws[(k + 2) * 3 + 2] + x.w * Ws[(k + 3) * 3 + 2];
    }
    out[p * 3 + 0] = a0;
    out[p * 3 + 1] = a1;
    out[p * 3 + 2] = a2;
}

// ---------------- host orchestration ----------------------------------------
extern "C" void kernel_launch(void* const* d_in, const int* in_sizes, int n_in,
                              void* d_out, int out_size)
{
    const float* state = (const float*)d_in[0];
    const float* Rr    = (const float*)d_in[1];
    const float* Rs    = (const float*)d_in[2];
    const float* Ra    = (const float*)d_in[3];
    const float* pe_w0 = (const float*)d_in[5],  *pe_b0 = (const float*)d_in[6];
    const float* pe_w1 = (const float*)d_in[7],  *pe_b1 = (const float*)d_in[8];
    const float* re_w0 = (const float*)d_in[9],  *re_b0 = (const float*)d_in[10];
    const float* re_w1 = (const float*)d_in[11], *re_b1 = (const float*)d_in[12];
    const float* re_w2 = (const float*)d_in[13], *re_b2 = (const float*)d_in[14];
    const float* rp_w  = (const float*)d_in[15], *rp_b  = (const float*)d_in[16];
    const float* pp_w  = (const float*)d_in[17], *pp_b  = (const float*)d_in[18];
    const float* pr_w0 = (const float*)d_in[19], *pr_b0 = (const float*)d_in[20];
    const float* pr_w1 = (const float*)d_in[21], *pr_b1 = (const float*)d_in[22];
    float* out = (float*)d_out;

    uint32_t *ptmpP, *peffP, *wh, *wl;
    float *relbase, *peffect, *pbase, *eagg, *pair;
    int *recv, *send, *cnt, *off, *pos, *list, *slist;
    cudaGetSymbolAddress((void**)&relbase, g_relbase);
    cudaGetSymbolAddress((void**)&ptmpP,   g_ptmpP);
    cudaGetSymbolAddress((void**)&peffP,   g_peffP);
    cudaGetSymbolAddress((void**)&peffect, g_peffect);
    cudaGetSymbolAddress((void**)&pbase,   g_pbase);
    cudaGetSymbolAddress((void**)&eagg,    g_eagg);
    cudaGetSymbolAddress((void**)&pair,    g_pair);
    cudaGetSymbolAddress((void**)&recv,    g_recv);
    cudaGetSymbolAddress((void**)&send,    g_send);
    cudaGetSymbolAddress((void**)&cnt,     g_cnt);
    cudaGetSymbolAddress((void**)&off,     g_off);
    cudaGetSymbolAddress((void**)&pos,     g_pos);
    cudaGetSymbolAddress((void**)&list,    g_list);
    cudaGetSymbolAddress((void**)&slist,   g_slist);
    cudaGetSymbolAddress((void**)&wh,      g_wh);
    cudaGetSymbolAddress((void**)&wl,      g_wl);

    cudaFuncSetAttribute(mma_gemm<A_BF,  E_BASE>,    cudaFuncAttributeMaxDynamicSharedMemorySize, SMEM_TOTAL_B);
    cudaFuncSetAttribute(mma_gemm<A_F32, E_RESID>,   cudaFuncAttributeMaxDynamicSharedMemorySize, SMEM_TOTAL_B);
    cudaFuncSetAttribute(mma_gemm<A_F32, E_RESID0>,  cudaFuncAttributeMaxDynamicSharedMemorySize, SMEM_TOTAL_B);
    cudaFuncSetAttribute(mma_gemm<A_BF,  E_RELU_F32>,cudaFuncAttributeMaxDynamicSharedMemorySize, SMEM_TOTAL_B);
    cudaFuncSetAttribute(relchain_kernel,  cudaFuncAttributeMaxDynamicSharedMemorySize, CH_TOTAL);
    cudaFuncSetAttribute(partall_kernel,   cudaFuncAttributeMaxDynamicSharedMemorySize, CH_TOTAL);

    float* P1 = pair;
    float* P2 = pair + (size_t)MPART * NF;
    const int WO_PPBOT = WO_PP + 8192;

    // 1) weights + cnt zero
    split_all_kernel<<<(WT_U32 + MPART + 255) / 256, 256>>>(
        pe_w0, pe_w1, re_w0, re_w1, re_w2, rp_w, pp_w, pr_w0, wh, wl, cnt);
    // 2) one-hot -> indices + CSR count (high-MLP scan)
    extract_idx_kernel<<<2048, 256>>>((const uint4*)Rr, (const uint4*)Rs, recv, send, cnt);
    // 3) CSR scan + fill (fill also precomputes global send rows)
    csr_scan_kernel<<<1, 1024>>>(cnt, off, pos);
    csr_fill_kernel<<<MREL / 256, 256>>>(recv, send, pos, list, slist);
    // 4) particle prep: Sr, Ss, pencode chain -> pbase
    partall_kernel<<<MPART / 128, 256, CH_TOTAL>>>(state, pe_b0, pe_b1, pp_b, wh, wl,
                                                   P1, P2, pbase);
    // 5) relation chain -> relbase
    relchain_kernel<<<MREL / 128, 256, CH_TOTAL>>>(
        P1, P2, Ra, re_w0 + 64 * 128, re_b0, re_b1, re_b2, rp_b, recv, send, wh, wl, relbase);
    // 6) propagation (first step uses E_RESID0 — no stale peffect read)
    agg_kernel<true><<<MPART / 2, 256>>>(relbase, nullptr, nullptr, slist, off, list, eagg);
    mma_gemm<A_F32, E_RESID0><<<MPART / 128, 256, SMEM_TOTAL_B>>>(
        eagg, wh + WO_PPBOT, wl + WO_PPBOT, nullptr, peffect, pbase, peffP, 128, 4, 0, 0);
    for (int s = 1; s < PSTEPS; ++s) {
        dim3 g(MPART / 128, 2);
        mma_gemm<A_BF, E_BASE><<<g, 256, SMEM_TOTAL_B>>>(
            peffP, wh + WO_RPM, wl + WO_RPM, nullptr, pair, nullptr, nullptr,
            128, 4, 8192, (long long)MPART * NF * 4);
        agg_kernel<false><<<MPART / 2, 256>>>(relbase, P1, P2, slist, off, list, eagg);
        mma_gemm<A_F32, E_RESID><<<MPART / 128, 256, SMEM_TOTAL_B>>>(
            eagg, wh + WO_PPBOT, wl + WO_PPBOT, nullptr, peffect, pbase, peffP, 128, 4, 0, 0);
    }
    // 7) predictor
    mma_gemm<A_BF, E_RELU_F32><<<MPART / 128, 256, SMEM_TOTAL_B>>>(
        peffP, wh + WO_PR0, wl + WO_PR0, pr_b0, ptmpP, nullptr, nullptr, 128, 4, 0, 0);
    pred_final_kernel<<<MPART / 256, 256>>>((const float*)ptmpP, pr_w1, pr_b1, out);
}